// round 1
// baseline (speedup 1.0000x reference)
#include <cuda_runtime.h>
#include <math.h>
#include <stdint.h>

#define NE   8
#define HD   1024
#define DD   512
#define DS   1024
#define TMAX 8192

// ---------------- scratch (static device globals; no allocations) ------------
__device__ __align__(16) float g_bufA[(size_t)TMAX * HD];          // 33.5 MB
__device__ __align__(16) float g_bufB[(size_t)TMAX * HD];          // 33.5 MB
__device__ __align__(16) float g_routed[(size_t)2 * TMAX * HD];    // 67 MB
__device__ int   g_cnt[NE];
__device__ int   g_base[NE + 1];
__device__ int   g_tok[NE * TMAX];
__device__ int   g_slot[NE * TMAX];
__device__ float g_wt[NE * TMAX];
__device__ float g_psum[NE];

// ---------------- init ------------------------------------------------------
__global__ void k_init() {
    if (threadIdx.x < NE) { g_cnt[threadIdx.x] = 0; g_psum[threadIdx.x] = 0.f; }
}

// ---------------- router: softmax -> top2 -> renorm -> gather lists ---------
__global__ void k_router(const float* __restrict__ x, const float* __restrict__ Wr, int T) {
    __shared__ float s_p[NE];
    if (threadIdx.x < NE) s_p[threadIdx.x] = 0.f;
    __syncthreads();
    int warp = blockIdx.x * (blockDim.x >> 5) + (threadIdx.x >> 5);
    int lane = threadIdx.x & 31;
    if (warp < T) {
        int t = warp;
        const float* xr = x + (size_t)t * HD;
        float acc[NE];
        #pragma unroll
        for (int e = 0; e < NE; e++) acc[e] = 0.f;
        for (int i = lane; i < HD; i += 32) {
            float xv = xr[i];
            const float* w = Wr + (size_t)i * NE;
            #pragma unroll
            for (int e = 0; e < NE; e++) acc[e] += xv * w[e];
        }
        #pragma unroll
        for (int e = 0; e < NE; e++) {
            #pragma unroll
            for (int o = 16; o > 0; o >>= 1)
                acc[e] += __shfl_xor_sync(0xffffffffu, acc[e], o);
        }
        if (lane == 0) {
            float mx = acc[0];
            #pragma unroll
            for (int e = 1; e < NE; e++) mx = fmaxf(mx, acc[e]);
            float p[NE]; float s = 0.f;
            #pragma unroll
            for (int e = 0; e < NE; e++) { p[e] = expf(acc[e] - mx); s += p[e]; }
            float inv = 1.f / s;
            #pragma unroll
            for (int e = 0; e < NE; e++) p[e] *= inv;
            // top-2, ties -> lowest index (matches jax top_k)
            int i0 = 0;
            #pragma unroll
            for (int e = 1; e < NE; e++) if (p[e] > p[i0]) i0 = e;
            int i1 = (i0 == 0) ? 1 : 0;
            #pragma unroll
            for (int e = 0; e < NE; e++) if (e != i0 && p[e] > p[i1]) i1 = e;
            float w0 = p[i0], w1 = p[i1];
            float rn = 1.f / (w0 + w1);
            w0 *= rn; w1 *= rn;
            int pos0 = atomicAdd(&g_cnt[i0], 1);
            g_tok[i0 * TMAX + pos0]  = t;
            g_slot[i0 * TMAX + pos0] = t;         // slot k=0
            g_wt[i0 * TMAX + pos0]   = w0;
            int pos1 = atomicAdd(&g_cnt[i1], 1);
            g_tok[i1 * TMAX + pos1]  = t;
            g_slot[i1 * TMAX + pos1] = T + t;     // slot k=1
            g_wt[i1 * TMAX + pos1]   = w1;
            #pragma unroll
            for (int e = 0; e < NE; e++) atomicAdd(&s_p[e], p[e]);
        }
    }
    __syncthreads();
    if (threadIdx.x < NE) atomicAdd(&g_psum[threadIdx.x], s_p[threadIdx.x]);
}

// ---------------- scan + aux loss -------------------------------------------
__global__ void k_scan(float* __restrict__ out, int T, int out_size) {
    if (threadIdx.x == 0 && blockIdx.x == 0) {
        int s = 0;
        for (int e = 0; e < NE; e++) { g_base[e] = s; s += g_cnt[e]; }
        g_base[NE] = s;
        float a = 0.f;
        for (int e = 0; e < NE; e++) { float m = g_psum[e] / (float)T; a += m * m; }
        a *= (float)NE;
        for (size_t i = (size_t)T * HD; i < (size_t)out_size; i++) out[i] = a;
    }
}

// ---------------- plain SGEMM: C[M,N] = A[M,K] @ B[K,N] (tiles divide dims) --
__global__ __launch_bounds__(256, 2)
void k_sgemm(const float* __restrict__ A, const float* __restrict__ B,
             float* __restrict__ C, int M, int N, int K) {
    __shared__ float As[8][128];
    __shared__ float Bs[8][128];
    const int tid  = threadIdx.x;
    const int row0 = blockIdx.y * 128;
    const int col0 = blockIdx.x * 128;
    const int aRow = tid >> 1;
    const int aCol = (tid & 1) * 4;
    const int bRow = tid >> 5;
    const int bCol = (tid & 31) * 4;
    const int ty = tid >> 4, tx = tid & 15;
    float acc[8][8];
    #pragma unroll
    for (int i = 0; i < 8; i++)
        #pragma unroll
        for (int j = 0; j < 8; j++) acc[i][j] = 0.f;
    const float* Aptr = A + (size_t)(row0 + aRow) * K + aCol;
    const float* Bptr = B + (size_t)bRow * N + col0 + bCol;
    for (int k0 = 0; k0 < K; k0 += 8) {
        float4 av = *(const float4*)(Aptr + k0);
        float4 bv = *(const float4*)(Bptr + (size_t)k0 * N);
        As[aCol + 0][aRow] = av.x; As[aCol + 1][aRow] = av.y;
        As[aCol + 2][aRow] = av.z; As[aCol + 3][aRow] = av.w;
        *(float4*)(&Bs[bRow][bCol]) = bv;
        __syncthreads();
        #pragma unroll
        for (int kk = 0; kk < 8; kk++) {
            float ra[8], rb[8];
            *(float4*)(ra)     = *(const float4*)(&As[kk][ty * 8]);
            *(float4*)(ra + 4) = *(const float4*)(&As[kk][ty * 8 + 4]);
            *(float4*)(rb)     = *(const float4*)(&Bs[kk][tx * 8]);
            *(float4*)(rb + 4) = *(const float4*)(&Bs[kk][tx * 8 + 4]);
            #pragma unroll
            for (int i = 0; i < 8; i++)
                #pragma unroll
                for (int j = 0; j < 8; j++)
                    acc[i][j] = fmaf(ra[i], rb[j], acc[i][j]);
        }
        __syncthreads();
    }
    #pragma unroll
    for (int i = 0; i < 8; i++) {
        float* cp = C + (size_t)(row0 + ty * 8 + i) * N + col0 + tx * 8;
        *(float4*)(cp)     = make_float4(acc[i][0], acc[i][1], acc[i][2], acc[i][3]);
        *(float4*)(cp + 4) = make_float4(acc[i][4], acc[i][5], acc[i][6], acc[i][7]);
    }
}

// -------- gathered GEMM for routed gate/up: rows gathered from x via lists ---
__global__ __launch_bounds__(256, 2)
void k_gateup(const float* __restrict__ x, const float* __restrict__ W,
              float* __restrict__ Cbuf) {
    const int e = blockIdx.z;
    const int M = g_cnt[e];
    const int row0 = blockIdx.y * 128;
    if (row0 >= M) return;
    const int* tok = g_tok + e * TMAX;
    const float* B = W + (size_t)e * HD * DD;     // [K=HD, N=DD] row-major
    float* C = Cbuf + (size_t)g_base[e] * DD;
    const int N = DD, K = HD;
    const int col0 = blockIdx.x * 128;
    __shared__ float As[8][128];
    __shared__ float Bs[8][128];
    const int tid  = threadIdx.x;
    const int aRow = tid >> 1;
    const int aCol = (tid & 1) * 4;
    const int bRow = tid >> 5;
    const int bCol = (tid & 31) * 4;
    const int ty = tid >> 4, tx = tid & 15;
    float acc[8][8];
    #pragma unroll
    for (int i = 0; i < 8; i++)
        #pragma unroll
        for (int j = 0; j < 8; j++) acc[i][j] = 0.f;
    const int gr = row0 + aRow;
    const bool avalid = gr < M;
    const float* Aptr = x;
    if (avalid) Aptr = x + (size_t)tok[gr] * HD + aCol;
    const float* Bptr = B + (size_t)bRow * N + col0 + bCol;
    for (int k0 = 0; k0 < K; k0 += 8) {
        float4 av = make_float4(0.f, 0.f, 0.f, 0.f);
        if (avalid) av = *(const float4*)(Aptr + k0);
        float4 bv = *(const float4*)(Bptr + (size_t)k0 * N);
        As[aCol + 0][aRow] = av.x; As[aCol + 1][aRow] = av.y;
        As[aCol + 2][aRow] = av.z; As[aCol + 3][aRow] = av.w;
        *(float4*)(&Bs[bRow][bCol]) = bv;
        __syncthreads();
        #pragma unroll
        for (int kk = 0; kk < 8; kk++) {
            float ra[8], rb[8];
            *(float4*)(ra)     = *(const float4*)(&As[kk][ty * 8]);
            *(float4*)(ra + 4) = *(const float4*)(&As[kk][ty * 8 + 4]);
            *(float4*)(rb)     = *(const float4*)(&Bs[kk][tx * 8]);
            *(float4*)(rb + 4) = *(const float4*)(&Bs[kk][tx * 8 + 4]);
            #pragma unroll
            for (int i = 0; i < 8; i++)
                #pragma unroll
                for (int j = 0; j < 8; j++)
                    acc[i][j] = fmaf(ra[i], rb[j], acc[i][j]);
        }
        __syncthreads();
    }
    #pragma unroll
    for (int i = 0; i < 8; i++) {
        int r = row0 + ty * 8 + i;
        if (r < M) {
            float* cp = C + (size_t)r * N + col0 + tx * 8;
            *(float4*)(cp)     = make_float4(acc[i][0], acc[i][1], acc[i][2], acc[i][3]);
            *(float4*)(cp + 4) = make_float4(acc[i][4], acc[i][5], acc[i][6], acc[i][7]);
        }
    }
}

// -------- routed down GEMM: H[M,DD] @ Wd[e] -> scatter rows into slot buffer -
__global__ __launch_bounds__(256, 2)
void k_down(const float* __restrict__ Wd) {
    const int e = blockIdx.z;
    const int M = g_cnt[e];
    const int row0 = blockIdx.y * 128;
    if (row0 >= M) return;
    const float* A = g_bufA + (size_t)g_base[e] * DD;  // [M, K=DD]
    const float* B = Wd + (size_t)e * DD * HD;         // [K=DD, N=HD]
    const int N = HD, K = DD;
    const int col0 = blockIdx.x * 128;
    __shared__ float As[8][128];
    __shared__ float Bs[8][128];
    const int tid  = threadIdx.x;
    const int aRow = tid >> 1;
    const int aCol = (tid & 1) * 4;
    const int bRow = tid >> 5;
    const int bCol = (tid & 31) * 4;
    const int ty = tid >> 4, tx = tid & 15;
    float acc[8][8];
    #pragma unroll
    for (int i = 0; i < 8; i++)
        #pragma unroll
        for (int j = 0; j < 8; j++) acc[i][j] = 0.f;
    const int gr = row0 + aRow;
    const bool avalid = gr < M;
    const float* Aptr = A + (size_t)(avalid ? gr : 0) * K + aCol;
    const float* Bptr = B + (size_t)bRow * N + col0 + bCol;
    for (int k0 = 0; k0 < K; k0 += 8) {
        float4 av = make_float4(0.f, 0.f, 0.f, 0.f);
        if (avalid) av = *(const float4*)(Aptr + k0);
        float4 bv = *(const float4*)(Bptr + (size_t)k0 * N);
        As[aCol + 0][aRow] = av.x; As[aCol + 1][aRow] = av.y;
        As[aCol + 2][aRow] = av.z; As[aCol + 3][aRow] = av.w;
        *(float4*)(&Bs[bRow][bCol]) = bv;
        __syncthreads();
        #pragma unroll
        for (int kk = 0; kk < 8; kk++) {
            float ra[8], rb[8];
            *(float4*)(ra)     = *(const float4*)(&As[kk][ty * 8]);
            *(float4*)(ra + 4) = *(const float4*)(&As[kk][ty * 8 + 4]);
            *(float4*)(rb)     = *(const float4*)(&Bs[kk][tx * 8]);
            *(float4*)(rb + 4) = *(const float4*)(&Bs[kk][tx * 8 + 4]);
            #pragma unroll
            for (int i = 0; i < 8; i++)
                #pragma unroll
                for (int j = 0; j < 8; j++)
                    acc[i][j] = fmaf(ra[i], rb[j], acc[i][j]);
        }
        __syncthreads();
    }
    #pragma unroll
    for (int i = 0; i < 8; i++) {
        int r = row0 + ty * 8 + i;
        if (r < M) {
            int slot = g_slot[e * TMAX + r];
            float* cp = g_routed + (size_t)slot * HD + col0 + tx * 8;
            *(float4*)(cp)     = make_float4(acc[i][0], acc[i][1], acc[i][2], acc[i][3]);
            *(float4*)(cp + 4) = make_float4(acc[i][4], acc[i][5], acc[i][6], acc[i][7]);
        }
    }
}

// ---------------- elementwise SwiGLU (shared expert): bufA = silu(bufA)*bufB -
__global__ void k_swiglu_shared(int n4) {
    float4* A = (float4*)g_bufA;
    const float4* Bv = (const float4*)g_bufB;
    int i = blockIdx.x * blockDim.x + threadIdx.x;
    int stride = gridDim.x * blockDim.x;
    for (; i < n4; i += stride) {
        float4 g = A[i], u = Bv[i];
        g.x = (g.x / (1.f + expf(-g.x))) * u.x;
        g.y = (g.y / (1.f + expf(-g.y))) * u.y;
        g.z = (g.z / (1.f + expf(-g.z))) * u.z;
        g.w = (g.w / (1.f + expf(-g.w))) * u.w;
        A[i] = g;
    }
}

// ---------------- weighted SwiGLU (routed): bufA = w * silu(bufA)*bufB -------
__global__ void k_swiglu_routed() {
    const int e = blockIdx.z;
    const int M = g_cnt[e];
    const int base = g_base[e];
    for (int p = blockIdx.y; p < M; p += gridDim.y) {
        float w = g_wt[e * TMAX + p];
        float4* g4 = (float4*)(g_bufA + (size_t)(base + p) * DD);
        const float4* u4 = (const float4*)(g_bufB + (size_t)(base + p) * DD);
        int d = threadIdx.x;             // 128 threads == DD/4 float4s
        float4 g = g4[d]; float4 u = u4[d];
        g.x = w * (g.x / (1.f + expf(-g.x))) * u.x;
        g.y = w * (g.y / (1.f + expf(-g.y))) * u.y;
        g.z = w * (g.z / (1.f + expf(-g.z))) * u.z;
        g.w = w * (g.w / (1.f + expf(-g.w))) * u.w;
        g4[d] = g;
    }
}

// ---------------- final: out += routed_slot0 + routed_slot1 ------------------
__global__ void k_final(float* __restrict__ out, int n4) {
    const float4* r = (const float4*)g_routed;
    float4* o4 = (float4*)out;
    int i = blockIdx.x * blockDim.x + threadIdx.x;
    int stride = gridDim.x * blockDim.x;
    for (; i < n4; i += stride) {
        float4 a = o4[i], b = r[i], c = r[i + n4];
        a.x += b.x + c.x;
        a.y += b.y + c.y;
        a.z += b.z + c.z;
        a.w += b.w + c.w;
        o4[i] = a;
    }
}

// ---------------- launch -----------------------------------------------------
extern "C" void kernel_launch(void* const* d_in, const int* in_sizes, int n_in,
                              void* d_out, int out_size) {
    const float* x   = (const float*)d_in[0];
    const float* Wr  = (const float*)d_in[1];
    const float* Wg  = (const float*)d_in[2];
    const float* Wu  = (const float*)d_in[3];
    const float* Wd  = (const float*)d_in[4];
    const float* Wsg = (const float*)d_in[5];
    const float* Wsu = (const float*)d_in[6];
    const float* Wsd = (const float*)d_in[7];
    float* out = (float*)d_out;
    const int T = in_sizes[0] / HD;     // 8192

    float *bufA, *bufB;
    cudaGetSymbolAddress((void**)&bufA, g_bufA);
    cudaGetSymbolAddress((void**)&bufB, g_bufB);

    // routing
    k_init<<<1, 32>>>();
    k_router<<<T / 8, 256>>>(x, Wr, T);
    k_scan<<<1, 1>>>(out, T, out_size);

    // shared expert: out = (silu(x@Wsg) * (x@Wsu)) @ Wsd
    dim3 gs(DS / 128, T / 128);
    k_sgemm<<<gs, 256>>>(x, Wsg, bufA, T, DS, HD);
    k_sgemm<<<gs, 256>>>(x, Wsu, bufB, T, DS, HD);
    k_swiglu_shared<<<1024, 256>>>(T * DS / 4);
    dim3 gd(HD / 128, T / 128);
    k_sgemm<<<gd, 256>>>(bufA, Wsd, out, T, HD, DS);

    // routed experts (gathered)
    dim3 gg(DD / 128, T / 128, NE);
    k_gateup<<<gg, 256>>>(x, Wg, bufA);
    k_gateup<<<gg, 256>>>(x, Wu, bufB);
    k_swiglu_routed<<<dim3(1, 64, NE), 128>>>();
    k_down<<<dim3(HD / 128, T / 128, NE), 256>>>(Wd);

    // combine
    k_final<<<2048, 256>>>(out, (T * HD) / 4);
}

// round 3
// speedup vs baseline: 2.2809x; 2.2809x over previous
#include <cuda_runtime.h>
#include <cuda_bf16.h>
#include <math.h>
#include <stdint.h>

#define NE   8
#define HD   1024
#define DD   512
#define DS   1024
#define TMAX 8192

#define BM 128
#define BN 128
#define BK 32
#define SA 40   // smem row stride (bf16 elems): BK + 8 pad -> conflict-free frags

// ---------------- scratch (static device globals; no allocations) ------------
__device__ __align__(16) float g_bufA[(size_t)TMAX * DS];
__device__ __align__(16) float g_bufB[(size_t)TMAX * DS];
__device__ __align__(16) float g_routed[(size_t)2 * TMAX * HD];
__device__ __align__(16) float g_WsgT[(size_t)DS * HD];
__device__ __align__(16) float g_WsuT[(size_t)DS * HD];
__device__ __align__(16) float g_WsdT[(size_t)HD * DS];
__device__ __align__(16) float g_WgT[(size_t)NE * DD * HD];
__device__ __align__(16) float g_WuT[(size_t)NE * DD * HD];
__device__ __align__(16) float g_WdT[(size_t)NE * HD * DD];
__device__ int   g_cnt[NE];
__device__ int   g_base[NE + 1];
__device__ int   g_tok[NE * TMAX];
__device__ int   g_slot[NE * TMAX];
__device__ float g_wt[NE * TMAX];
__device__ float g_psum[NE];

// ---------------- init ------------------------------------------------------
__global__ void k_init() {
    if (threadIdx.x < NE) { g_cnt[threadIdx.x] = 0; g_psum[threadIdx.x] = 0.f; }
}

// ---------------- router: softmax -> top2 -> renorm -> gather lists ---------
__global__ void k_router(const float* __restrict__ x, const float* __restrict__ Wr, int T) {
    __shared__ float s_p[NE];
    if (threadIdx.x < NE) s_p[threadIdx.x] = 0.f;
    __syncthreads();
    int warp = blockIdx.x * (blockDim.x >> 5) + (threadIdx.x >> 5);
    int lane = threadIdx.x & 31;
    if (warp < T) {
        int t = warp;
        const float* xr = x + (size_t)t * HD;
        float acc[NE];
        #pragma unroll
        for (int e = 0; e < NE; e++) acc[e] = 0.f;
        for (int i = lane; i < HD; i += 32) {
            float xv = xr[i];
            const float* w = Wr + (size_t)i * NE;
            #pragma unroll
            for (int e = 0; e < NE; e++) acc[e] += xv * w[e];
        }
        #pragma unroll
        for (int e = 0; e < NE; e++) {
            #pragma unroll
            for (int o = 16; o > 0; o >>= 1)
                acc[e] += __shfl_xor_sync(0xffffffffu, acc[e], o);
        }
        if (lane == 0) {
            float mx = acc[0];
            #pragma unroll
            for (int e = 1; e < NE; e++) mx = fmaxf(mx, acc[e]);
            float p[NE]; float s = 0.f;
            #pragma unroll
            for (int e = 0; e < NE; e++) { p[e] = expf(acc[e] - mx); s += p[e]; }
            float inv = 1.f / s;
            #pragma unroll
            for (int e = 0; e < NE; e++) p[e] *= inv;
            int i0 = 0;
            #pragma unroll
            for (int e = 1; e < NE; e++) if (p[e] > p[i0]) i0 = e;
            int i1 = (i0 == 0) ? 1 : 0;
            #pragma unroll
            for (int e = 0; e < NE; e++) if (e != i0 && p[e] > p[i1]) i1 = e;
            float w0 = p[i0], w1 = p[i1];
            float rn = 1.f / (w0 + w1);
            w0 *= rn; w1 *= rn;
            int pos0 = atomicAdd(&g_cnt[i0], 1);
            g_tok[i0 * TMAX + pos0]  = t;
            g_slot[i0 * TMAX + pos0] = t;
            g_wt[i0 * TMAX + pos0]   = w0;
            int pos1 = atomicAdd(&g_cnt[i1], 1);
            g_tok[i1 * TMAX + pos1]  = t;
            g_slot[i1 * TMAX + pos1] = T + t;
            g_wt[i1 * TMAX + pos1]   = w1;
            #pragma unroll
            for (int e = 0; e < NE; e++) atomicAdd(&s_p[e], p[e]);
        }
    }
    __syncthreads();
    if (threadIdx.x < NE) atomicAdd(&g_psum[threadIdx.x], s_p[threadIdx.x]);
}

// ---------------- scan + aux loss -------------------------------------------
__global__ void k_scan(float* __restrict__ out, int T, int out_size) {
    if (threadIdx.x == 0 && blockIdx.x == 0) {
        int s = 0;
        for (int e = 0; e < NE; e++) { g_base[e] = s; s += g_cnt[e]; }
        g_base[NE] = s;
        float a = 0.f;
        for (int e = 0; e < NE; e++) { float m = g_psum[e] / (float)T; a += m * m; }
        a *= (float)NE;
        for (size_t i = (size_t)T * HD; i < (size_t)out_size; i++) out[i] = a;
    }
}

// ---------------- transpose: in[R,C] -> out[C,R], per-z matrix ---------------
__global__ void k_transpose(const float* __restrict__ in, float* __restrict__ out,
                            int R, int C) {
    __shared__ float t[32][33];
    const size_t mat = (size_t)R * C;
    in  += (size_t)blockIdx.z * mat;
    out += (size_t)blockIdx.z * mat;
    int c0 = blockIdx.x * 32, r0 = blockIdx.y * 32;
    int tx = threadIdx.x, ty = threadIdx.y;
    #pragma unroll
    for (int j = 0; j < 32; j += 8)
        t[ty + j][tx] = in[(size_t)(r0 + ty + j) * C + c0 + tx];
    __syncthreads();
    #pragma unroll
    for (int j = 0; j < 32; j += 8)
        out[(size_t)(c0 + ty + j) * R + r0 + tx] = t[tx][ty + j];
}

// ---------------- bf16 mma helper --------------------------------------------
__device__ __forceinline__ void mma_bf16(float* c, const uint32_t* a, const uint32_t* b) {
    asm volatile(
        "mma.sync.aligned.m16n8k16.row.col.f32.bf16.bf16.f32 "
        "{%0,%1,%2,%3}, {%4,%5,%6,%7}, {%8,%9}, {%0,%1,%2,%3};\n"
        : "+f"(c[0]), "+f"(c[1]), "+f"(c[2]), "+f"(c[3])
        : "r"(a[0]), "r"(a[1]), "r"(a[2]), "r"(a[3]), "r"(b[0]), "r"(b[1]));
}

__device__ __forceinline__ void store_split(__nv_bfloat16* hi, __nv_bfloat16* lo,
                                            int r, int c4, float4 v) {
    int off = r * SA + c4 * 4;
    __nv_bfloat162 h01 = __floats2bfloat162_rn(v.x, v.y);
    __nv_bfloat162 h23 = __floats2bfloat162_rn(v.z, v.w);
    float lx = v.x - __bfloat162float(h01.x);
    float ly = v.y - __bfloat162float(h01.y);
    float lz = v.z - __bfloat162float(h23.x);
    float lw = v.w - __bfloat162float(h23.y);
    __nv_bfloat162 l01 = __floats2bfloat162_rn(lx, ly);
    __nv_bfloat162 l23 = __floats2bfloat162_rn(lz, lw);
    uint2 hv = make_uint2(*(uint32_t*)&h01, *(uint32_t*)&h23);
    uint2 lv = make_uint2(*(uint32_t*)&l01, *(uint32_t*)&l23);
    *(uint2*)(hi + off) = hv;
    *(uint2*)(lo + off) = lv;
}

// ---------------- tensor-core GEMM via mma.sync + 3xBF16 ---------------------
// C[M,N] = A[M,K] @ Wt[N,K]^T  (Wt is K-major per output column)
// GATHER_A: A rows via g_tok[e]; C rows position-dense (base g_base[e]), ldc=N
// SCATTER_C: A rows position-dense from base g_base[e]; C rows -> g_routed slots
template<int GATHER_A, int SCATTER_C>
__global__ __launch_bounds__(256, 1)
void k_mma(const float* __restrict__ A, const float* __restrict__ Wt,
           float* __restrict__ C, int Mtot, int N, int K,
           size_t wstride, int ldc)
{
    const int e = blockIdx.z;
    const int M = (GATHER_A || SCATTER_C) ? g_cnt[e] : Mtot;
    const int row0 = blockIdx.y * BM;
    if (row0 >= M) return;
    const int col0 = blockIdx.x * BN;
    const float* W = Wt + (size_t)e * wstride;

    __shared__ __nv_bfloat16 sAh[BM * SA];
    __shared__ __nv_bfloat16 sAl[BM * SA];
    __shared__ __nv_bfloat16 sBh[BN * SA];
    __shared__ __nv_bfloat16 sBl[BN * SA];

    const int tid = threadIdx.x;
    const int wid = tid >> 5, lane = tid & 31;
    const int wm = wid & 1, wn = wid >> 1;
    const int g = lane >> 2, t4 = lane & 3;

    // global-load assignment: 4 float4 for A, 4 for B per thread
    const float* aptr[4];
    const float* bptr[4];
    int lr[4], lc4[4];
    #pragma unroll
    for (int i = 0; i < 4; i++) {
        int f = i * 256 + tid;
        int r = f >> 3, c4 = f & 7;
        lr[i] = r; lc4[i] = c4;
        int gr = row0 + r;
        int grc = (gr < M) ? gr : (M - 1);
        if (GATHER_A)       aptr[i] = A + (size_t)g_tok[e * TMAX + grc] * K + c4 * 4;
        else if (SCATTER_C) aptr[i] = A + ((size_t)g_base[e] + grc) * K + c4 * 4;
        else                aptr[i] = A + (size_t)gr * K + c4 * 4;
        bptr[i] = W + (size_t)(col0 + r) * K + c4 * 4;
    }

    float acc[4][4][4];
    #pragma unroll
    for (int mi = 0; mi < 4; mi++)
        #pragma unroll
        for (int ni = 0; ni < 4; ni++)
            #pragma unroll
            for (int q = 0; q < 4; q++) acc[mi][ni][q] = 0.f;

    float4 ra[4], rb[4];
    #pragma unroll
    for (int i = 0; i < 4; i++) { ra[i] = *(const float4*)aptr[i]; rb[i] = *(const float4*)bptr[i]; }

    const int NC = K / BK;
    for (int cidx = 0; cidx < NC; cidx++) {
        __syncthreads();
        #pragma unroll
        for (int i = 0; i < 4; i++) {
            store_split(sAh, sAl, lr[i], lc4[i], ra[i]);
            store_split(sBh, sBl, lr[i], lc4[i], rb[i]);
        }
        __syncthreads();
        if (cidx + 1 < NC) {
            int off = (cidx + 1) * BK;
            #pragma unroll
            for (int i = 0; i < 4; i++) {
                ra[i] = *(const float4*)(aptr[i] + off);
                rb[i] = *(const float4*)(bptr[i] + off);
            }
        }
        #pragma unroll
        for (int ks = 0; ks < 2; ks++) {
            uint32_t fAh[4][4], fAl[4][4], fBh[4][2], fBl[4][2];
            const int cb = ks * 16 + t4 * 2;
            #pragma unroll
            for (int mi = 0; mi < 4; mi++) {
                int r = wm * 64 + mi * 16;
                fAh[mi][0] = *(const uint32_t*)&sAh[(r + g    ) * SA + cb    ];
                fAh[mi][1] = *(const uint32_t*)&sAh[(r + g + 8) * SA + cb    ];
                fAh[mi][2] = *(const uint32_t*)&sAh[(r + g    ) * SA + cb + 8];
                fAh[mi][3] = *(const uint32_t*)&sAh[(r + g + 8) * SA + cb + 8];
                fAl[mi][0] = *(const uint32_t*)&sAl[(r + g    ) * SA + cb    ];
                fAl[mi][1] = *(const uint32_t*)&sAl[(r + g + 8) * SA + cb    ];
                fAl[mi][2] = *(const uint32_t*)&sAl[(r + g    ) * SA + cb + 8];
                fAl[mi][3] = *(const uint32_t*)&sAl[(r + g + 8) * SA + cb + 8];
            }
            #pragma unroll
            for (int ni = 0; ni < 4; ni++) {
                int n = wn * 32 + ni * 8 + g;
                fBh[ni][0] = *(const uint32_t*)&sBh[n * SA + cb    ];
                fBh[ni][1] = *(const uint32_t*)&sBh[n * SA + cb + 8];
                fBl[ni][0] = *(const uint32_t*)&sBl[n * SA + cb    ];
                fBl[ni][1] = *(const uint32_t*)&sBl[n * SA + cb + 8];
            }
            // pass 1: Ah*Bh (16 independent chains), pass 2: Al*Bh, pass 3: Ah*Bl
            #pragma unroll
            for (int mi = 0; mi < 4; mi++)
                #pragma unroll
                for (int ni = 0; ni < 4; ni++) mma_bf16(acc[mi][ni], fAh[mi], fBh[ni]);
            #pragma unroll
            for (int mi = 0; mi < 4; mi++)
                #pragma unroll
                for (int ni = 0; ni < 4; ni++) mma_bf16(acc[mi][ni], fAl[mi], fBh[ni]);
            #pragma unroll
            for (int mi = 0; mi < 4; mi++)
                #pragma unroll
                for (int ni = 0; ni < 4; ni++) mma_bf16(acc[mi][ni], fAh[mi], fBl[ni]);
        }
    }

    // epilogue: rows p (position in tile list) / global rows; cols col0 + ...
    #pragma unroll
    for (int mi = 0; mi < 4; mi++) {
        int p0 = row0 + wm * 64 + mi * 16 + g;
        int p1 = p0 + 8;
        float* c0 = nullptr; float* c1 = nullptr;
        if (SCATTER_C) {
            if (p0 < M) c0 = g_routed + (size_t)g_slot[e * TMAX + p0] * HD;
            if (p1 < M) c1 = g_routed + (size_t)g_slot[e * TMAX + p1] * HD;
        } else if (GATHER_A) {
            if (p0 < M) c0 = C + ((size_t)g_base[e] + p0) * ldc;
            if (p1 < M) c1 = C + ((size_t)g_base[e] + p1) * ldc;
        } else {
            c0 = C + (size_t)p0 * ldc;
            c1 = C + (size_t)p1 * ldc;
        }
        #pragma unroll
        for (int ni = 0; ni < 4; ni++) {
            int col = col0 + wn * 32 + ni * 8 + 2 * t4;
            if (c0) *(float2*)(c0 + col) = make_float2(acc[mi][ni][0], acc[mi][ni][1]);
            if (c1) *(float2*)(c1 + col) = make_float2(acc[mi][ni][2], acc[mi][ni][3]);
        }
    }
}

// ---------------- elementwise SwiGLU (shared expert): bufA = silu(bufA)*bufB -
__global__ void k_swiglu_shared(int n4) {
    float4* A = (float4*)g_bufA;
    const float4* Bv = (const float4*)g_bufB;
    int i = blockIdx.x * blockDim.x + threadIdx.x;
    int stride = gridDim.x * blockDim.x;
    for (; i < n4; i += stride) {
        float4 g = A[i], u = Bv[i];
        g.x = (g.x / (1.f + expf(-g.x))) * u.x;
        g.y = (g.y / (1.f + expf(-g.y))) * u.y;
        g.z = (g.z / (1.f + expf(-g.z))) * u.z;
        g.w = (g.w / (1.f + expf(-g.w))) * u.w;
        A[i] = g;
    }
}

// ---------------- weighted SwiGLU (routed): bufA = w * silu(bufA)*bufB -------
__global__ void k_swiglu_routed() {
    const int e = blockIdx.z;
    const int M = g_cnt[e];
    const int base = g_base[e];
    for (int p = blockIdx.y; p < M; p += gridDim.y) {
        float w = g_wt[e * TMAX + p];
        float4* g4 = (float4*)(g_bufA + (size_t)(base + p) * DD);
        const float4* u4 = (const float4*)(g_bufB + (size_t)(base + p) * DD);
        int d = threadIdx.x;
        float4 g = g4[d]; float4 u = u4[d];
        g.x = w * (g.x / (1.f + expf(-g.x))) * u.x;
        g.y = w * (g.y / (1.f + expf(-g.y))) * u.y;
        g.z = w * (g.z / (1.f + expf(-g.z))) * u.z;
        g.w = w * (g.w / (1.f + expf(-g.w))) * u.w;
        g4[d] = g;
    }
}

// ---------------- final: out += routed_slot0 + routed_slot1 ------------------
__global__ void k_final(float* __restrict__ out, int n4) {
    const float4* r = (const float4*)g_routed;
    float4* o4 = (float4*)out;
    int i = blockIdx.x * blockDim.x + threadIdx.x;
    int stride = gridDim.x * blockDim.x;
    for (; i < n4; i += stride) {
        float4 a = o4[i], b = r[i], c = r[i + n4];
        a.x += b.x + c.x;
        a.y += b.y + c.y;
        a.z += b.z + c.z;
        a.w += b.w + c.w;
        o4[i] = a;
    }
}

// ---------------- launch -----------------------------------------------------
extern "C" void kernel_launch(void* const* d_in, const int* in_sizes, int n_in,
                              void* d_out, int out_size) {
    const float* x   = (const float*)d_in[0];
    const float* Wr  = (const float*)d_in[1];
    const float* Wg  = (const float*)d_in[2];
    const float* Wu  = (const float*)d_in[3];
    const float* Wd  = (const float*)d_in[4];
    const float* Wsg = (const float*)d_in[5];
    const float* Wsu = (const float*)d_in[6];
    const float* Wsd = (const float*)d_in[7];
    float* out = (float*)d_out;
    const int T = in_sizes[0] / HD;   // 8192

    float *bufA, *bufB, *WsgT, *WsuT, *WsdT, *WgT, *WuT, *WdT;
    cudaGetSymbolAddress((void**)&bufA, g_bufA);
    cudaGetSymbolAddress((void**)&bufB, g_bufB);
    cudaGetSymbolAddress((void**)&WsgT, g_WsgT);
    cudaGetSymbolAddress((void**)&WsuT, g_WsuT);
    cudaGetSymbolAddress((void**)&WsdT, g_WsdT);
    cudaGetSymbolAddress((void**)&WgT,  g_WgT);
    cudaGetSymbolAddress((void**)&WuT,  g_WuT);
    cudaGetSymbolAddress((void**)&WdT,  g_WdT);

    // routing
    k_init<<<1, 32>>>();
    k_router<<<T / 8, 256>>>(x, Wr, T);
    k_scan<<<1, 1>>>(out, T, out_size);

    // weight transposes into K-major [N][K] form
    dim3 tb(32, 8);
    k_transpose<<<dim3(DS / 32, HD / 32, 1),  tb>>>(Wsg, WsgT, HD, DS);
    k_transpose<<<dim3(DS / 32, HD / 32, 1),  tb>>>(Wsu, WsuT, HD, DS);
    k_transpose<<<dim3(HD / 32, DS / 32, 1),  tb>>>(Wsd, WsdT, DS, HD);
    k_transpose<<<dim3(DD / 32, HD / 32, NE), tb>>>(Wg,  WgT,  HD, DD);
    k_transpose<<<dim3(DD / 32, HD / 32, NE), tb>>>(Wu,  WuT,  HD, DD);
    k_transpose<<<dim3(HD / 32, DD / 32, NE), tb>>>(Wd,  WdT,  DD, HD);

    // shared expert
    dim3 gs(DS / BN, T / BM);
    k_mma<0, 0><<<gs, 256>>>(x, WsgT, bufA, T, DS, HD, 0, DS);
    k_mma<0, 0><<<gs, 256>>>(x, WsuT, bufB, T, DS, HD, 0, DS);
    k_swiglu_shared<<<1024, 256>>>(T * DS / 4);
    dim3 gd(HD / BN, T / BM);
    k_mma<0, 0><<<gd, 256>>>(bufA, WsdT, out, T, HD, DS, 0, HD);

    // routed experts
    dim3 gg(DD / BN, T / BM, NE);
    k_mma<1, 0><<<gg, 256>>>(x, WgT, bufA, 0, DD, HD, (size_t)DD * HD, DD);
    k_mma<1, 0><<<gg, 256>>>(x, WuT, bufB, 0, DD, HD, (size_t)DD * HD, DD);
    k_swiglu_routed<<<dim3(1, 64, NE), 128>>>();
    k_mma<0, 1><<<dim3(HD / BN, T / BM, NE), 256>>>(bufA, WdT, nullptr, 0, HD, DD,
                                                    (size_t)HD * DD, HD);

    // combine
    k_final<<<2048, 256>>>(out, (T * HD) / 4);
}

// round 4
// speedup vs baseline: 2.4608x; 1.0789x over previous
#include <cuda_runtime.h>
#include <cuda_bf16.h>
#include <math.h>
#include <stdint.h>

#define NE   8
#define HD   1024
#define DD   512
#define DS   1024
#define TMAX 8192

#define BM 128
#define BN 128
#define BK 32
#define SA 40                 // bf16 elems per smem row (32 + 8 pad)
#define TILE_B (128 * SA * 2) // 10240 bytes per 128x32 bf16 tile
#define STG_GU (6 * TILE_B)   // Ah,Al,Bgh,Bgl,Buh,Bul
#define STG_DN (4 * TILE_B)
#define SMEM_GU (2 * STG_GU)
#define SMEM_DN (2 * STG_DN)

// ---------------- scratch (static device globals; no allocations) ------------
__device__ __align__(16) __nv_bfloat16 g_xh[(size_t)TMAX * HD];
__device__ __align__(16) __nv_bfloat16 g_xl[(size_t)TMAX * HD];
__device__ __align__(16) __nv_bfloat16 g_bufH[(size_t)TMAX * DS];
__device__ __align__(16) __nv_bfloat16 g_bufL[(size_t)TMAX * DS];
__device__ __align__(16) float g_routed[(size_t)2 * TMAX * HD];
__device__ __align__(16) __nv_bfloat16 g_WsgTh[(size_t)DS * HD];
__device__ __align__(16) __nv_bfloat16 g_WsgTl[(size_t)DS * HD];
__device__ __align__(16) __nv_bfloat16 g_WsuTh[(size_t)DS * HD];
__device__ __align__(16) __nv_bfloat16 g_WsuTl[(size_t)DS * HD];
__device__ __align__(16) __nv_bfloat16 g_WsdTh[(size_t)HD * DS];
__device__ __align__(16) __nv_bfloat16 g_WsdTl[(size_t)HD * DS];
__device__ __align__(16) __nv_bfloat16 g_WgTh[(size_t)NE * DD * HD];
__device__ __align__(16) __nv_bfloat16 g_WgTl[(size_t)NE * DD * HD];
__device__ __align__(16) __nv_bfloat16 g_WuTh[(size_t)NE * DD * HD];
__device__ __align__(16) __nv_bfloat16 g_WuTl[(size_t)NE * DD * HD];
__device__ __align__(16) __nv_bfloat16 g_WdTh[(size_t)NE * HD * DD];
__device__ __align__(16) __nv_bfloat16 g_WdTl[(size_t)NE * HD * DD];
__device__ int   g_cnt[NE];
__device__ int   g_base[NE + 1];
__device__ int   g_tok[NE * TMAX];
__device__ int   g_slot[NE * TMAX];
__device__ float g_wt[NE * TMAX];
__device__ float g_psum[NE];

// ---------------- asm helpers ------------------------------------------------
__device__ __forceinline__ uint32_t smem_u32(const void* p) {
    uint32_t a;
    asm("{ .reg .u64 t; cvta.to.shared.u64 t, %1; cvt.u32.u64 %0, t; }" : "=r"(a) : "l"(p));
    return a;
}
#define CP16(dst, src) \
    asm volatile("cp.async.cg.shared.global [%0], [%1], 16;" :: "r"(dst), "l"(src) : "memory")
#define CPCOMMIT() asm volatile("cp.async.commit_group;" ::: "memory")
#define CPWAIT0()  asm volatile("cp.async.wait_group 0;" ::: "memory")
#define CPWAIT1()  asm volatile("cp.async.wait_group 1;" ::: "memory")

__device__ __forceinline__ void ldsm4(uint32_t* r, uint32_t addr) {
    asm volatile("ldmatrix.sync.aligned.m8n8.x4.shared.b16 {%0,%1,%2,%3}, [%4];"
        : "=r"(r[0]), "=r"(r[1]), "=r"(r[2]), "=r"(r[3]) : "r"(addr));
}
__device__ __forceinline__ void mma_bf16(float* c, const uint32_t* a, const uint32_t* b) {
    asm volatile(
        "mma.sync.aligned.m16n8k16.row.col.f32.bf16.bf16.f32 "
        "{%0,%1,%2,%3}, {%4,%5,%6,%7}, {%8,%9}, {%0,%1,%2,%3};\n"
        : "+f"(c[0]), "+f"(c[1]), "+f"(c[2]), "+f"(c[3])
        : "r"(a[0]), "r"(a[1]), "r"(a[2]), "r"(a[3]), "r"(b[0]), "r"(b[1]));
}

// ---------------- init ------------------------------------------------------
__global__ void k_init() {
    if (threadIdx.x < NE) { g_cnt[threadIdx.x] = 0; g_psum[threadIdx.x] = 0.f; }
}

// ---------------- router ----------------------------------------------------
__global__ void k_router(const float* __restrict__ x, const float* __restrict__ Wr, int T) {
    __shared__ float s_p[NE];
    if (threadIdx.x < NE) s_p[threadIdx.x] = 0.f;
    __syncthreads();
    int warp = blockIdx.x * (blockDim.x >> 5) + (threadIdx.x >> 5);
    int lane = threadIdx.x & 31;
    if (warp < T) {
        int t = warp;
        const float* xr = x + (size_t)t * HD;
        float acc[NE];
        #pragma unroll
        for (int e = 0; e < NE; e++) acc[e] = 0.f;
        for (int i = lane; i < HD; i += 32) {
            float xv = xr[i];
            const float* w = Wr + (size_t)i * NE;
            #pragma unroll
            for (int e = 0; e < NE; e++) acc[e] += xv * w[e];
        }
        #pragma unroll
        for (int e = 0; e < NE; e++) {
            #pragma unroll
            for (int o = 16; o > 0; o >>= 1)
                acc[e] += __shfl_xor_sync(0xffffffffu, acc[e], o);
        }
        if (lane == 0) {
            float mx = acc[0];
            #pragma unroll
            for (int e = 1; e < NE; e++) mx = fmaxf(mx, acc[e]);
            float p[NE]; float s = 0.f;
            #pragma unroll
            for (int e = 0; e < NE; e++) { p[e] = expf(acc[e] - mx); s += p[e]; }
            float inv = 1.f / s;
            #pragma unroll
            for (int e = 0; e < NE; e++) p[e] *= inv;
            int i0 = 0;
            #pragma unroll
            for (int e = 1; e < NE; e++) if (p[e] > p[i0]) i0 = e;
            int i1 = (i0 == 0) ? 1 : 0;
            #pragma unroll
            for (int e = 0; e < NE; e++) if (e != i0 && p[e] > p[i1]) i1 = e;
            float w0 = p[i0], w1 = p[i1];
            float rn = 1.f / (w0 + w1);
            w0 *= rn; w1 *= rn;
            int pos0 = atomicAdd(&g_cnt[i0], 1);
            g_tok[i0 * TMAX + pos0]  = t;
            g_slot[i0 * TMAX + pos0] = t;
            g_wt[i0 * TMAX + pos0]   = w0;
            int pos1 = atomicAdd(&g_cnt[i1], 1);
            g_tok[i1 * TMAX + pos1]  = t;
            g_slot[i1 * TMAX + pos1] = T + t;
            g_wt[i1 * TMAX + pos1]   = w1;
            #pragma unroll
            for (int e = 0; e < NE; e++) atomicAdd(&s_p[e], p[e]);
        }
    }
    __syncthreads();
    if (threadIdx.x < NE) atomicAdd(&g_psum[threadIdx.x], s_p[threadIdx.x]);
}

// ---------------- scan + aux loss -------------------------------------------
__global__ void k_scan(float* __restrict__ out, int T, int out_size) {
    if (threadIdx.x == 0 && blockIdx.x == 0) {
        int s = 0;
        for (int e = 0; e < NE; e++) { g_base[e] = s; s += g_cnt[e]; }
        g_base[NE] = s;
        float a = 0.f;
        for (int e = 0; e < NE; e++) { float m = g_psum[e] / (float)T; a += m * m; }
        a *= (float)NE;
        for (size_t i = (size_t)T * HD; i < (size_t)out_size; i++) out[i] = a;
    }
}

// ---------------- split x: f32 -> bf16 hi/lo ---------------------------------
__global__ void k_split_x(const float* __restrict__ x, int n4) {
    int i = blockIdx.x * blockDim.x + threadIdx.x;
    int stride = gridDim.x * blockDim.x;
    for (; i < n4; i += stride) {
        float4 v = ((const float4*)x)[i];
        __nv_bfloat162 h01 = __floats2bfloat162_rn(v.x, v.y);
        __nv_bfloat162 h23 = __floats2bfloat162_rn(v.z, v.w);
        __nv_bfloat162 l01 = __floats2bfloat162_rn(v.x - __bfloat162float(h01.x),
                                                   v.y - __bfloat162float(h01.y));
        __nv_bfloat162 l23 = __floats2bfloat162_rn(v.z - __bfloat162float(h23.x),
                                                   v.w - __bfloat162float(h23.y));
        ((uint2*)g_xh)[i] = make_uint2(*(uint32_t*)&h01, *(uint32_t*)&h23);
        ((uint2*)g_xl)[i] = make_uint2(*(uint32_t*)&l01, *(uint32_t*)&l23);
    }
}

// -------- transpose + split: in[R,C] f32 -> outH/outL[C,R] bf16 --------------
__global__ void k_tsplit(const float* __restrict__ in, __nv_bfloat16* __restrict__ outH,
                         __nv_bfloat16* __restrict__ outL, int R, int C) {
    __shared__ float t[32][33];
    const size_t mat = (size_t)R * C;
    in   += (size_t)blockIdx.z * mat;
    outH += (size_t)blockIdx.z * mat;
    outL += (size_t)blockIdx.z * mat;
    int c0 = blockIdx.x * 32, r0 = blockIdx.y * 32;
    int tx = threadIdx.x, ty = threadIdx.y;
    #pragma unroll
    for (int j = 0; j < 32; j += 8)
        t[ty + j][tx] = in[(size_t)(r0 + ty + j) * C + c0 + tx];
    __syncthreads();
    #pragma unroll
    for (int j = 0; j < 32; j += 8) {
        float v = t[tx][ty + j];
        __nv_bfloat16 h = __float2bfloat16_rn(v);
        __nv_bfloat16 l = __float2bfloat16_rn(v - __bfloat162float(h));
        outH[(size_t)(c0 + ty + j) * R + r0 + tx] = h;
        outL[(size_t)(c0 + ty + j) * R + r0 + tx] = l;
    }
}

// ---------------- fused gate+up GEMM + SwiGLU, split-bf16 output -------------
// gate = A@Wg^T, up = A@Wu^T; C = (w) * silu(gate) * up  -> bufH/bufL
template<int GATHER>
__global__ __launch_bounds__(256, 1)
void k_gu(const __nv_bfloat16* __restrict__ Ah_g, const __nv_bfloat16* __restrict__ Al_g,
          const __nv_bfloat16* __restrict__ Bgh_g, const __nv_bfloat16* __restrict__ Bgl_g,
          const __nv_bfloat16* __restrict__ Buh_g, const __nv_bfloat16* __restrict__ Bul_g,
          __nv_bfloat16* __restrict__ Ch, __nv_bfloat16* __restrict__ Cl,
          int Mtot, int N, int K, size_t wstride)
{
    const int e = blockIdx.z;
    const int M = GATHER ? g_cnt[e] : Mtot;
    const int row0 = blockIdx.y * BM;
    if (row0 >= M) return;
    const int col0 = blockIdx.x * BN;
    const __nv_bfloat16* Bgh = Bgh_g + (size_t)e * wstride;
    const __nv_bfloat16* Bgl = Bgl_g + (size_t)e * wstride;
    const __nv_bfloat16* Buh = Buh_g + (size_t)e * wstride;
    const __nv_bfloat16* Bul = Bul_g + (size_t)e * wstride;

    extern __shared__ char dsm[];
    const uint32_t sb = smem_u32(dsm);

    const int tid = threadIdx.x;
    const int wid = tid >> 5, lane = tid & 31;
    const int wm = wid & 1, wn = wid >> 1;
    const int g = lane >> 2, t4 = lane & 3;

    // cp.async source offsets (2 chunks/thread/tile)
    size_t aoff[2]; size_t boff[2]; uint32_t adst[2];
    #pragma unroll
    for (int j = 0; j < 2; j++) {
        int q = tid + j * 256;
        int r = q >> 2, c16 = q & 3;
        adst[j] = r * (SA * 2) + c16 * 16;
        int gr = row0 + r;
        int grc = (gr < M) ? gr : (M - 1);
        if (GATHER) aoff[j] = (size_t)g_tok[e * TMAX + grc] * K + c16 * 8;
        else        aoff[j] = (size_t)grc * K + c16 * 8;
        boff[j] = (size_t)(col0 + r) * K + c16 * 8;
    }

    // ldmatrix lane offsets
    const int a_r = (lane & 7) + ((lane >> 3) & 1) * 8;
    const int a_c = ((lane >> 4) & 1) * 8;
    const int b_r = (lane & 7) + ((lane >> 4) & 1) * 8;
    const int b_c = ((lane >> 3) & 1) * 8;
    const uint32_t la = (uint32_t)(a_r * SA + a_c) * 2;
    const uint32_t lb = (uint32_t)(b_r * SA + b_c) * 2;

    float accg[4][4][4], accu[4][4][4];
    #pragma unroll
    for (int mi = 0; mi < 4; mi++)
        #pragma unroll
        for (int ni = 0; ni < 4; ni++)
            #pragma unroll
            for (int q = 0; q < 4; q++) { accg[mi][ni][q] = 0.f; accu[mi][ni][q] = 0.f; }

    const int NC = K / BK;
    // prologue: chunk 0 -> stage 0
    {
        uint32_t st = sb;
        #pragma unroll
        for (int j = 0; j < 2; j++) {
            CP16(st + 0 * TILE_B + adst[j], Ah_g + aoff[j]);
            CP16(st + 1 * TILE_B + adst[j], Al_g + aoff[j]);
            CP16(st + 2 * TILE_B + adst[j], Bgh + boff[j]);
            CP16(st + 3 * TILE_B + adst[j], Bgl + boff[j]);
            CP16(st + 4 * TILE_B + adst[j], Buh + boff[j]);
            CP16(st + 5 * TILE_B + adst[j], Bul + boff[j]);
        }
        CPCOMMIT();
    }

    for (int c = 0; c < NC; c++) {
        if (c + 1 < NC) {
            uint32_t st = sb + ((c + 1) & 1) * STG_GU;
            size_t ko = (size_t)(c + 1) * BK;
            #pragma unroll
            for (int j = 0; j < 2; j++) {
                CP16(st + 0 * TILE_B + adst[j], Ah_g + aoff[j] + ko);
                CP16(st + 1 * TILE_B + adst[j], Al_g + aoff[j] + ko);
                CP16(st + 2 * TILE_B + adst[j], Bgh + boff[j] + ko);
                CP16(st + 3 * TILE_B + adst[j], Bgl + boff[j] + ko);
                CP16(st + 4 * TILE_B + adst[j], Buh + boff[j] + ko);
                CP16(st + 5 * TILE_B + adst[j], Bul + boff[j] + ko);
            }
            CPCOMMIT();
            CPWAIT1();
        } else {
            CPWAIT0();
        }
        __syncthreads();
        const uint32_t st = sb + (c & 1) * STG_GU;
        #pragma unroll
        for (int ks = 0; ks < 2; ks++) {
            uint32_t fAh[4][4], fAl[4][4];
            #pragma unroll
            for (int mi = 0; mi < 4; mi++) {
                uint32_t ro = (uint32_t)((wm * 64 + mi * 16) * SA * 2) + ks * 32;
                ldsm4(fAh[mi], st + 0 * TILE_B + ro + la);
                ldsm4(fAl[mi], st + 1 * TILE_B + ro + la);
            }
            {
                uint32_t fBh[2][4], fBl[2][4];
                #pragma unroll
                for (int nb = 0; nb < 2; nb++) {
                    uint32_t ro = (uint32_t)((wn * 32 + nb * 16) * SA * 2) + ks * 32;
                    ldsm4(fBh[nb], st + 2 * TILE_B + ro + lb);
                    ldsm4(fBl[nb], st + 3 * TILE_B + ro + lb);
                }
                #pragma unroll
                for (int mi = 0; mi < 4; mi++)
                    #pragma unroll
                    for (int ni = 0; ni < 4; ni++)
                        mma_bf16(accg[mi][ni], fAh[mi], &fBh[ni >> 1][(ni & 1) * 2]);
                #pragma unroll
                for (int mi = 0; mi < 4; mi++)
                    #pragma unroll
                    for (int ni = 0; ni < 4; ni++)
                        mma_bf16(accg[mi][ni], fAl[mi], &fBh[ni >> 1][(ni & 1) * 2]);
                #pragma unroll
                for (int mi = 0; mi < 4; mi++)
                    #pragma unroll
                    for (int ni = 0; ni < 4; ni++)
                        mma_bf16(accg[mi][ni], fAh[mi], &fBl[ni >> 1][(ni & 1) * 2]);
            }
            {
                uint32_t fBh[2][4], fBl[2][4];
                #pragma unroll
                for (int nb = 0; nb < 2; nb++) {
                    uint32_t ro = (uint32_t)((wn * 32 + nb * 16) * SA * 2) + ks * 32;
                    ldsm4(fBh[nb], st + 4 * TILE_B + ro + lb);
                    ldsm4(fBl[nb], st + 5 * TILE_B + ro + lb);
                }
                #pragma unroll
                for (int mi = 0; mi < 4; mi++)
                    #pragma unroll
                    for (int ni = 0; ni < 4; ni++)
                        mma_bf16(accu[mi][ni], fAh[mi], &fBh[ni >> 1][(ni & 1) * 2]);
                #pragma unroll
                for (int mi = 0; mi < 4; mi++)
                    #pragma unroll
                    for (int ni = 0; ni < 4; ni++)
                        mma_bf16(accu[mi][ni], fAl[mi], &fBh[ni >> 1][(ni & 1) * 2]);
                #pragma unroll
                for (int mi = 0; mi < 4; mi++)
                    #pragma unroll
                    for (int ni = 0; ni < 4; ni++)
                        mma_bf16(accu[mi][ni], fAh[mi], &fBl[ni >> 1][(ni & 1) * 2]);
            }
        }
        __syncthreads();
    }

    // epilogue: swiglu (weighted if GATHER), split bf16 store
    #pragma unroll
    for (int mi = 0; mi < 4; mi++) {
        int p0 = row0 + wm * 64 + mi * 16 + g;
        int p1 = p0 + 8;
        #pragma unroll
        for (int half = 0; half < 2; half++) {
            int p = half ? p1 : p0;
            if (p >= M) continue;
            float w = GATHER ? g_wt[e * TMAX + p] : 1.f;
            size_t rowo = (GATHER ? (size_t)(g_base[e] + p) : (size_t)p) * N;
            #pragma unroll
            for (int ni = 0; ni < 4; ni++) {
                int col = col0 + wn * 32 + ni * 8 + 2 * t4;
                float gv0 = accg[mi][ni][half * 2 + 0];
                float gv1 = accg[mi][ni][half * 2 + 1];
                float uv0 = accu[mi][ni][half * 2 + 0];
                float uv1 = accu[mi][ni][half * 2 + 1];
                float v0 = w * (gv0 / (1.f + expf(-gv0))) * uv0;
                float v1 = w * (gv1 / (1.f + expf(-gv1))) * uv1;
                __nv_bfloat162 h = __floats2bfloat162_rn(v0, v1);
                __nv_bfloat162 l = __floats2bfloat162_rn(v0 - __bfloat162float(h.x),
                                                         v1 - __bfloat162float(h.y));
                *(__nv_bfloat162*)(Ch + rowo + col) = h;
                *(__nv_bfloat162*)(Cl + rowo + col) = l;
            }
        }
    }
}

// ---------------- down GEMM: split-bf16 A @ W^T -> f32 (dense or scatter) ----
template<int SCATTER>
__global__ __launch_bounds__(256, 1)
void k_dn(const __nv_bfloat16* __restrict__ Ah_g, const __nv_bfloat16* __restrict__ Al_g,
          const __nv_bfloat16* __restrict__ Bh_g, const __nv_bfloat16* __restrict__ Bl_g,
          float* __restrict__ C, int Mtot, int N, int K, size_t wstride, int ldc)
{
    const int e = blockIdx.z;
    const int M = SCATTER ? g_cnt[e] : Mtot;
    const int row0 = blockIdx.y * BM;
    if (row0 >= M) return;
    const int col0 = blockIdx.x * BN;
    const __nv_bfloat16* Bh = Bh_g + (size_t)e * wstride;
    const __nv_bfloat16* Bl = Bl_g + (size_t)e * wstride;

    extern __shared__ char dsm[];
    const uint32_t sb = smem_u32(dsm);

    const int tid = threadIdx.x;
    const int wid = tid >> 5, lane = tid & 31;
    const int wm = wid & 1, wn = wid >> 1;
    const int g = lane >> 2, t4 = lane & 3;

    size_t aoff[2]; size_t boff[2]; uint32_t adst[2];
    #pragma unroll
    for (int j = 0; j < 2; j++) {
        int q = tid + j * 256;
        int r = q >> 2, c16 = q & 3;
        adst[j] = r * (SA * 2) + c16 * 16;
        int gr = row0 + r;
        int grc = (gr < M) ? gr : (M - 1);
        if (SCATTER) aoff[j] = (size_t)(g_base[e] + grc) * K + c16 * 8;
        else         aoff[j] = (size_t)grc * K + c16 * 8;
        boff[j] = (size_t)(col0 + r) * K + c16 * 8;
    }
    const int a_r = (lane & 7) + ((lane >> 3) & 1) * 8;
    const int a_c = ((lane >> 4) & 1) * 8;
    const int b_r = (lane & 7) + ((lane >> 4) & 1) * 8;
    const int b_c = ((lane >> 3) & 1) * 8;
    const uint32_t la = (uint32_t)(a_r * SA + a_c) * 2;
    const uint32_t lb = (uint32_t)(b_r * SA + b_c) * 2;

    float acc[4][4][4];
    #pragma unroll
    for (int mi = 0; mi < 4; mi++)
        #pragma unroll
        for (int ni = 0; ni < 4; ni++)
            #pragma unroll
            for (int q = 0; q < 4; q++) acc[mi][ni][q] = 0.f;

    const int NC = K / BK;
    {
        uint32_t st = sb;
        #pragma unroll
        for (int j = 0; j < 2; j++) {
            CP16(st + 0 * TILE_B + adst[j], Ah_g + aoff[j]);
            CP16(st + 1 * TILE_B + adst[j], Al_g + aoff[j]);
            CP16(st + 2 * TILE_B + adst[j], Bh + boff[j]);
            CP16(st + 3 * TILE_B + adst[j], Bl + boff[j]);
        }
        CPCOMMIT();
    }
    for (int c = 0; c < NC; c++) {
        if (c + 1 < NC) {
            uint32_t st = sb + ((c + 1) & 1) * STG_DN;
            size_t ko = (size_t)(c + 1) * BK;
            #pragma unroll
            for (int j = 0; j < 2; j++) {
                CP16(st + 0 * TILE_B + adst[j], Ah_g + aoff[j] + ko);
                CP16(st + 1 * TILE_B + adst[j], Al_g + aoff[j] + ko);
                CP16(st + 2 * TILE_B + adst[j], Bh + boff[j] + ko);
                CP16(st + 3 * TILE_B + adst[j], Bl + boff[j] + ko);
            }
            CPCOMMIT();
            CPWAIT1();
        } else {
            CPWAIT0();
        }
        __syncthreads();
        const uint32_t st = sb + (c & 1) * STG_DN;
        #pragma unroll
        for (int ks = 0; ks < 2; ks++) {
            uint32_t fAh[4][4], fAl[4][4], fBh[2][4], fBl[2][4];
            #pragma unroll
            for (int mi = 0; mi < 4; mi++) {
                uint32_t ro = (uint32_t)((wm * 64 + mi * 16) * SA * 2) + ks * 32;
                ldsm4(fAh[mi], st + 0 * TILE_B + ro + la);
                ldsm4(fAl[mi], st + 1 * TILE_B + ro + la);
            }
            #pragma unroll
            for (int nb = 0; nb < 2; nb++) {
                uint32_t ro = (uint32_t)((wn * 32 + nb * 16) * SA * 2) + ks * 32;
                ldsm4(fBh[nb], st + 2 * TILE_B + ro + lb);
                ldsm4(fBl[nb], st + 3 * TILE_B + ro + lb);
            }
            #pragma unroll
            for (int mi = 0; mi < 4; mi++)
                #pragma unroll
                for (int ni = 0; ni < 4; ni++)
                    mma_bf16(acc[mi][ni], fAh[mi], &fBh[ni >> 1][(ni & 1) * 2]);
            #pragma unroll
            for (int mi = 0; mi < 4; mi++)
                #pragma unroll
                for (int ni = 0; ni < 4; ni++)
                    mma_bf16(acc[mi][ni], fAl[mi], &fBh[ni >> 1][(ni & 1) * 2]);
            #pragma unroll
            for (int mi = 0; mi < 4; mi++)
                #pragma unroll
                for (int ni = 0; ni < 4; ni++)
                    mma_bf16(acc[mi][ni], fAh[mi], &fBl[ni >> 1][(ni & 1) * 2]);
        }
        __syncthreads();
    }

    #pragma unroll
    for (int mi = 0; mi < 4; mi++) {
        int p0 = row0 + wm * 64 + mi * 16 + g;
        int p1 = p0 + 8;
        float* c0 = nullptr; float* c1 = nullptr;
        if (SCATTER) {
            if (p0 < M) c0 = g_routed + (size_t)g_slot[e * TMAX + p0] * HD;
            if (p1 < M) c1 = g_routed + (size_t)g_slot[e * TMAX + p1] * HD;
        } else {
            c0 = C + (size_t)p0 * ldc;
            c1 = C + (size_t)p1 * ldc;
        }
        #pragma unroll
        for (int ni = 0; ni < 4; ni++) {
            int col = col0 + wn * 32 + ni * 8 + 2 * t4;
            if (c0) *(float2*)(c0 + col) = make_float2(acc[mi][ni][0], acc[mi][ni][1]);
            if (c1) *(float2*)(c1 + col) = make_float2(acc[mi][ni][2], acc[mi][ni][3]);
        }
    }
}

// ---------------- final: out += routed_slot0 + routed_slot1 ------------------
__global__ void k_final(float* __restrict__ out, int n4) {
    const float4* r = (const float4*)g_routed;
    float4* o4 = (float4*)out;
    int i = blockIdx.x * blockDim.x + threadIdx.x;
    int stride = gridDim.x * blockDim.x;
    for (; i < n4; i += stride) {
        float4 a = o4[i], b = r[i], c = r[i + n4];
        a.x += b.x + c.x;
        a.y += b.y + c.y;
        a.z += b.z + c.z;
        a.w += b.w + c.w;
        o4[i] = a;
    }
}

// ---------------- launch -----------------------------------------------------
extern "C" void kernel_launch(void* const* d_in, const int* in_sizes, int n_in,
                              void* d_out, int out_size) {
    const float* x   = (const float*)d_in[0];
    const float* Wr  = (const float*)d_in[1];
    const float* Wg  = (const float*)d_in[2];
    const float* Wu  = (const float*)d_in[3];
    const float* Wd  = (const float*)d_in[4];
    const float* Wsg = (const float*)d_in[5];
    const float* Wsu = (const float*)d_in[6];
    const float* Wsd = (const float*)d_in[7];
    float* out = (float*)d_out;
    const int T = in_sizes[0] / HD;   // 8192

    __nv_bfloat16 *xh, *xl, *bufH, *bufL;
    __nv_bfloat16 *WsgTh, *WsgTl, *WsuTh, *WsuTl, *WsdTh, *WsdTl;
    __nv_bfloat16 *WgTh, *WgTl, *WuTh, *WuTl, *WdTh, *WdTl;
    cudaGetSymbolAddress((void**)&xh, g_xh);
    cudaGetSymbolAddress((void**)&xl, g_xl);
    cudaGetSymbolAddress((void**)&bufH, g_bufH);
    cudaGetSymbolAddress((void**)&bufL, g_bufL);
    cudaGetSymbolAddress((void**)&WsgTh, g_WsgTh);
    cudaGetSymbolAddress((void**)&WsgTl, g_WsgTl);
    cudaGetSymbolAddress((void**)&WsuTh, g_WsuTh);
    cudaGetSymbolAddress((void**)&WsuTl, g_WsuTl);
    cudaGetSymbolAddress((void**)&WsdTh, g_WsdTh);
    cudaGetSymbolAddress((void**)&WsdTl, g_WsdTl);
    cudaGetSymbolAddress((void**)&WgTh, g_WgTh);
    cudaGetSymbolAddress((void**)&WgTl, g_WgTl);
    cudaGetSymbolAddress((void**)&WuTh, g_WuTh);
    cudaGetSymbolAddress((void**)&WuTl, g_WuTl);
    cudaGetSymbolAddress((void**)&WdTh, g_WdTh);
    cudaGetSymbolAddress((void**)&WdTl, g_WdTl);

    cudaFuncSetAttribute(k_gu<0>, cudaFuncAttributeMaxDynamicSharedMemorySize, SMEM_GU);
    cudaFuncSetAttribute(k_gu<1>, cudaFuncAttributeMaxDynamicSharedMemorySize, SMEM_GU);
    cudaFuncSetAttribute(k_dn<0>, cudaFuncAttributeMaxDynamicSharedMemorySize, SMEM_DN);
    cudaFuncSetAttribute(k_dn<1>, cudaFuncAttributeMaxDynamicSharedMemorySize, SMEM_DN);

    // routing
    k_init<<<1, 32>>>();
    k_router<<<T / 8, 256>>>(x, Wr, T);
    k_scan<<<1, 1>>>(out, T, out_size);

    // operand preparation: split x, transpose+split weights
    k_split_x<<<2048, 256>>>(x, T * HD / 4);
    dim3 tb(32, 8);
    k_tsplit<<<dim3(DS / 32, HD / 32, 1),  tb>>>(Wsg, WsgTh, WsgTl, HD, DS);
    k_tsplit<<<dim3(DS / 32, HD / 32, 1),  tb>>>(Wsu, WsuTh, WsuTl, HD, DS);
    k_tsplit<<<dim3(HD / 32, DS / 32, 1),  tb>>>(Wsd, WsdTh, WsdTl, DS, HD);
    k_tsplit<<<dim3(DD / 32, HD / 32, NE), tb>>>(Wg, WgTh, WgTl, HD, DD);
    k_tsplit<<<dim3(DD / 32, HD / 32, NE), tb>>>(Wu, WuTh, WuTl, HD, DD);
    k_tsplit<<<dim3(HD / 32, DD / 32, NE), tb>>>(Wd, WdTh, WdTl, DD, HD);

    // shared expert: fused gate+up+swiglu -> split buf; down -> out
    k_gu<0><<<dim3(DS / BN, T / BM, 1), 256, SMEM_GU>>>(
        xh, xl, WsgTh, WsgTl, WsuTh, WsuTl, bufH, bufL, T, DS, HD, 0);
    k_dn<0><<<dim3(HD / BN, T / BM, 1), 256, SMEM_DN>>>(
        bufH, bufL, WsdTh, WsdTl, out, T, HD, DS, 0, HD);

    // routed experts: gathered fused gate+up+weighted swiglu; down -> slots
    k_gu<1><<<dim3(DD / BN, T / BM, NE), 256, SMEM_GU>>>(
        xh, xl, WgTh, WgTl, WuTh, WuTl, bufH, bufL, 0, DD, HD, (size_t)DD * HD);
    k_dn<1><<<dim3(HD / BN, T / BM, NE), 256, SMEM_DN>>>(
        bufH, bufL, WdTh, WdTl, nullptr, 0, HD, DD, (size_t)HD * DD, HD);

    // combine
    k_final<<<2048, 256>>>(out, (T * HD) / 4);
}

// round 5
// speedup vs baseline: 2.5074x; 1.0189x over previous
#include <cuda_runtime.h>
#include <cuda_bf16.h>
#include <math.h>
#include <stdint.h>

#define NE   8
#define HD   1024
#define DD   512
#define DS   1024
#define TMAX 8192

#define BM 128
#define BN 128
#define BK 32
#define SA 40                 // bf16 elems per smem row (32 + 8 pad)
#define TILE_B (128 * SA * 2) // 10240 bytes per 128x32 bf16 tile
#define STG_GU (6 * TILE_B)   // Ah,Al,Bgh,Bgl,Buh,Bul
#define STG_DN (4 * TILE_B)
#define SMEM_GU (3 * STG_GU)  // 3-stage
#define SMEM_DN (4 * STG_DN)  // 4-stage

// ---------------- scratch (static device globals; no allocations) ------------
__device__ __align__(16) __nv_bfloat16 g_xh[(size_t)TMAX * HD];
__device__ __align__(16) __nv_bfloat16 g_xl[(size_t)TMAX * HD];
__device__ __align__(16) __nv_bfloat16 g_bufH[(size_t)TMAX * DS];
__device__ __align__(16) __nv_bfloat16 g_bufL[(size_t)TMAX * DS];
__device__ __align__(16) float g_routed[(size_t)2 * TMAX * HD];
__device__ __align__(16) __nv_bfloat16 g_WsgTh[(size_t)DS * HD];
__device__ __align__(16) __nv_bfloat16 g_WsgTl[(size_t)DS * HD];
__device__ __align__(16) __nv_bfloat16 g_WsuTh[(size_t)DS * HD];
__device__ __align__(16) __nv_bfloat16 g_WsuTl[(size_t)DS * HD];
__device__ __align__(16) __nv_bfloat16 g_WsdTh[(size_t)HD * DS];
__device__ __align__(16) __nv_bfloat16 g_WsdTl[(size_t)HD * DS];
__device__ __align__(16) __nv_bfloat16 g_WgTh[(size_t)NE * DD * HD];
__device__ __align__(16) __nv_bfloat16 g_WgTl[(size_t)NE * DD * HD];
__device__ __align__(16) __nv_bfloat16 g_WuTh[(size_t)NE * DD * HD];
__device__ __align__(16) __nv_bfloat16 g_WuTl[(size_t)NE * DD * HD];
__device__ __align__(16) __nv_bfloat16 g_WdTh[(size_t)NE * HD * DD];
__device__ __align__(16) __nv_bfloat16 g_WdTl[(size_t)NE * HD * DD];
__device__ int   g_cnt[NE];
__device__ int   g_base[NE + 1];
__device__ int   g_tok[NE * TMAX];
__device__ int   g_slot[NE * TMAX];
__device__ float g_wt[NE * TMAX];
__device__ float g_psum[NE];

// ---------------- asm helpers ------------------------------------------------
__device__ __forceinline__ uint32_t smem_u32(const void* p) {
    uint32_t a;
    asm("{ .reg .u64 t; cvta.to.shared.u64 t, %1; cvt.u32.u64 %0, t; }" : "=r"(a) : "l"(p));
    return a;
}
#define CP16(dst, src) \
    asm volatile("cp.async.cg.shared.global [%0], [%1], 16;" :: "r"(dst), "l"(src) : "memory")
#define CPCOMMIT() asm volatile("cp.async.commit_group;" ::: "memory")
#define CPWAIT1()  asm volatile("cp.async.wait_group 1;" ::: "memory")
#define CPWAIT2()  asm volatile("cp.async.wait_group 2;" ::: "memory")

__device__ __forceinline__ void ldsm4(uint32_t* r, uint32_t addr) {
    asm volatile("ldmatrix.sync.aligned.m8n8.x4.shared.b16 {%0,%1,%2,%3}, [%4];"
        : "=r"(r[0]), "=r"(r[1]), "=r"(r[2]), "=r"(r[3]) : "r"(addr));
}
__device__ __forceinline__ void mma_bf16(float* c, const uint32_t* a, const uint32_t* b) {
    asm volatile(
        "mma.sync.aligned.m16n8k16.row.col.f32.bf16.bf16.f32 "
        "{%0,%1,%2,%3}, {%4,%5,%6,%7}, {%8,%9}, {%0,%1,%2,%3};\n"
        : "+f"(c[0]), "+f"(c[1]), "+f"(c[2]), "+f"(c[3])
        : "r"(a[0]), "r"(a[1]), "r"(a[2]), "r"(a[3]), "r"(b[0]), "r"(b[1]));
}

// ---------------- init ------------------------------------------------------
__global__ void k_init() {
    if (threadIdx.x < NE) { g_cnt[threadIdx.x] = 0; g_psum[threadIdx.x] = 0.f; }
}

// ---------------- router ----------------------------------------------------
__global__ void k_router(const float* __restrict__ x, const float* __restrict__ Wr, int T) {
    __shared__ float s_p[NE];
    if (threadIdx.x < NE) s_p[threadIdx.x] = 0.f;
    __syncthreads();
    int warp = blockIdx.x * (blockDim.x >> 5) + (threadIdx.x >> 5);
    int lane = threadIdx.x & 31;
    if (warp < T) {
        int t = warp;
        const float* xr = x + (size_t)t * HD;
        float acc[NE];
        #pragma unroll
        for (int e = 0; e < NE; e++) acc[e] = 0.f;
        for (int i = lane; i < HD; i += 32) {
            float xv = xr[i];
            const float* w = Wr + (size_t)i * NE;
            #pragma unroll
            for (int e = 0; e < NE; e++) acc[e] += xv * w[e];
        }
        #pragma unroll
        for (int e = 0; e < NE; e++) {
            #pragma unroll
            for (int o = 16; o > 0; o >>= 1)
                acc[e] += __shfl_xor_sync(0xffffffffu, acc[e], o);
        }
        if (lane == 0) {
            float mx = acc[0];
            #pragma unroll
            for (int e = 1; e < NE; e++) mx = fmaxf(mx, acc[e]);
            float p[NE]; float s = 0.f;
            #pragma unroll
            for (int e = 0; e < NE; e++) { p[e] = expf(acc[e] - mx); s += p[e]; }
            float inv = 1.f / s;
            #pragma unroll
            for (int e = 0; e < NE; e++) p[e] *= inv;
            int i0 = 0;
            #pragma unroll
            for (int e = 1; e < NE; e++) if (p[e] > p[i0]) i0 = e;
            int i1 = (i0 == 0) ? 1 : 0;
            #pragma unroll
            for (int e = 0; e < NE; e++) if (e != i0 && p[e] > p[i1]) i1 = e;
            float w0 = p[i0], w1 = p[i1];
            float rn = 1.f / (w0 + w1);
            w0 *= rn; w1 *= rn;
            int pos0 = atomicAdd(&g_cnt[i0], 1);
            g_tok[i0 * TMAX + pos0]  = t;
            g_slot[i0 * TMAX + pos0] = t;
            g_wt[i0 * TMAX + pos0]   = w0;
            int pos1 = atomicAdd(&g_cnt[i1], 1);
            g_tok[i1 * TMAX + pos1]  = t;
            g_slot[i1 * TMAX + pos1] = T + t;
            g_wt[i1 * TMAX + pos1]   = w1;
            #pragma unroll
            for (int e = 0; e < NE; e++) atomicAdd(&s_p[e], p[e]);
        }
    }
    __syncthreads();
    if (threadIdx.x < NE) atomicAdd(&g_psum[threadIdx.x], s_p[threadIdx.x]);
}

// ---------------- scan + aux loss -------------------------------------------
__global__ void k_scan(float* __restrict__ out, int T, int out_size) {
    if (threadIdx.x == 0 && blockIdx.x == 0) {
        int s = 0;
        for (int e = 0; e < NE; e++) { g_base[e] = s; s += g_cnt[e]; }
        g_base[NE] = s;
        float a = 0.f;
        for (int e = 0; e < NE; e++) { float m = g_psum[e] / (float)T; a += m * m; }
        a *= (float)NE;
        for (size_t i = (size_t)T * HD; i < (size_t)out_size; i++) out[i] = a;
    }
}

// ---------------- split x: f32 -> bf16 hi/lo ---------------------------------
__global__ void k_split_x(const float* __restrict__ x, int n4) {
    int i = blockIdx.x * blockDim.x + threadIdx.x;
    int stride = gridDim.x * blockDim.x;
    for (; i < n4; i += stride) {
        float4 v = ((const float4*)x)[i];
        __nv_bfloat162 h01 = __floats2bfloat162_rn(v.x, v.y);
        __nv_bfloat162 h23 = __floats2bfloat162_rn(v.z, v.w);
        __nv_bfloat162 l01 = __floats2bfloat162_rn(v.x - __bfloat162float(h01.x),
                                                   v.y - __bfloat162float(h01.y));
        __nv_bfloat162 l23 = __floats2bfloat162_rn(v.z - __bfloat162float(h23.x),
                                                   v.w - __bfloat162float(h23.y));
        ((uint2*)g_xh)[i] = make_uint2(*(uint32_t*)&h01, *(uint32_t*)&h23);
        ((uint2*)g_xl)[i] = make_uint2(*(uint32_t*)&l01, *(uint32_t*)&l23);
    }
}

// -------- transpose + split: in[R,C] f32 -> outH/outL[C,R] bf16 --------------
__global__ void k_tsplit(const float* __restrict__ in, __nv_bfloat16* __restrict__ outH,
                         __nv_bfloat16* __restrict__ outL, int R, int C) {
    __shared__ float t[32][33];
    const size_t mat = (size_t)R * C;
    in   += (size_t)blockIdx.z * mat;
    outH += (size_t)blockIdx.z * mat;
    outL += (size_t)blockIdx.z * mat;
    int c0 = blockIdx.x * 32, r0 = blockIdx.y * 32;
    int tx = threadIdx.x, ty = threadIdx.y;
    #pragma unroll
    for (int j = 0; j < 32; j += 8)
        t[ty + j][tx] = in[(size_t)(r0 + ty + j) * C + c0 + tx];
    __syncthreads();
    #pragma unroll
    for (int j = 0; j < 32; j += 8) {
        float v = t[tx][ty + j];
        __nv_bfloat16 h = __float2bfloat16_rn(v);
        __nv_bfloat16 l = __float2bfloat16_rn(v - __bfloat162float(h));
        outH[(size_t)(c0 + ty + j) * R + r0 + tx] = h;
        outL[(size_t)(c0 + ty + j) * R + r0 + tx] = l;
    }
}

// ---------------- fused gate+up GEMM + SwiGLU, split-bf16 output -------------
template<int GATHER>
__global__ __launch_bounds__(256, 1)
void k_gu(const __nv_bfloat16* __restrict__ Ah_g, const __nv_bfloat16* __restrict__ Al_g,
          const __nv_bfloat16* __restrict__ Bgh_g, const __nv_bfloat16* __restrict__ Bgl_g,
          const __nv_bfloat16* __restrict__ Buh_g, const __nv_bfloat16* __restrict__ Bul_g,
          __nv_bfloat16* __restrict__ Ch, __nv_bfloat16* __restrict__ Cl,
          int Mtot, int N, int K, size_t wstride)
{
    const int e = blockIdx.z;
    const int M = GATHER ? g_cnt[e] : Mtot;
    const int row0 = blockIdx.y * BM;
    if (row0 >= M) return;
    const int col0 = blockIdx.x * BN;
    const __nv_bfloat16* Bgh = Bgh_g + (size_t)e * wstride;
    const __nv_bfloat16* Bgl = Bgl_g + (size_t)e * wstride;
    const __nv_bfloat16* Buh = Buh_g + (size_t)e * wstride;
    const __nv_bfloat16* Bul = Bul_g + (size_t)e * wstride;

    extern __shared__ char dsm[];
    const uint32_t sb = smem_u32(dsm);

    const int tid = threadIdx.x;
    const int wid = tid >> 5, lane = tid & 31;
    const int wm = wid & 1, wn = wid >> 1;
    const int g = lane >> 2, t4 = lane & 3;

    size_t aoff[2]; size_t boff[2]; uint32_t adst[2];
    #pragma unroll
    for (int j = 0; j < 2; j++) {
        int q = tid + j * 256;
        int r = q >> 2, c16 = q & 3;
        adst[j] = r * (SA * 2) + c16 * 16;
        int gr = row0 + r;
        int grc = (gr < M) ? gr : (M - 1);
        if (GATHER) aoff[j] = (size_t)g_tok[e * TMAX + grc] * K + c16 * 8;
        else        aoff[j] = (size_t)grc * K + c16 * 8;
        boff[j] = (size_t)(col0 + r) * K + c16 * 8;
    }

    const int a_r = (lane & 7) + ((lane >> 3) & 1) * 8;
    const int a_c = ((lane >> 4) & 1) * 8;
    const int b_r = (lane & 7) + ((lane >> 4) & 1) * 8;
    const int b_c = ((lane >> 3) & 1) * 8;
    const uint32_t la = (uint32_t)(a_r * SA + a_c) * 2;
    const uint32_t lb = (uint32_t)(b_r * SA + b_c) * 2;

    float accg[4][4][4], accu[4][4][4];
    #pragma unroll
    for (int mi = 0; mi < 4; mi++)
        #pragma unroll
        for (int ni = 0; ni < 4; ni++)
            #pragma unroll
            for (int q = 0; q < 4; q++) { accg[mi][ni][q] = 0.f; accu[mi][ni][q] = 0.f; }

    const int NC = K / BK;
    // prologue: chunks 0,1 -> stages 0,1
    #pragma unroll
    for (int pc = 0; pc < 2; pc++) {
        uint32_t st = sb + pc * STG_GU;
        size_t ko = (size_t)pc * BK;
        #pragma unroll
        for (int j = 0; j < 2; j++) {
            CP16(st + 0 * TILE_B + adst[j], Ah_g + aoff[j] + ko);
            CP16(st + 1 * TILE_B + adst[j], Al_g + aoff[j] + ko);
            CP16(st + 2 * TILE_B + adst[j], Bgh + boff[j] + ko);
            CP16(st + 3 * TILE_B + adst[j], Bgl + boff[j] + ko);
            CP16(st + 4 * TILE_B + adst[j], Buh + boff[j] + ko);
            CP16(st + 5 * TILE_B + adst[j], Bul + boff[j] + ko);
        }
        CPCOMMIT();
    }

    int s_next = 2;   // stage index for chunk c+2
    for (int c = 0; c < NC; c++) {
        CPWAIT1();          // chunk c complete (c+1 may still be in flight)
        __syncthreads();    // all warps past compute(c-1); stage s_next reusable
        {
            int nc2 = (c + 2 < NC) ? c + 2 : NC - 1;   // clamped tail reload
            uint32_t st = sb + s_next * STG_GU;
            size_t ko = (size_t)nc2 * BK;
            #pragma unroll
            for (int j = 0; j < 2; j++) {
                CP16(st + 0 * TILE_B + adst[j], Ah_g + aoff[j] + ko);
                CP16(st + 1 * TILE_B + adst[j], Al_g + aoff[j] + ko);
                CP16(st + 2 * TILE_B + adst[j], Bgh + boff[j] + ko);
                CP16(st + 3 * TILE_B + adst[j], Bgl + boff[j] + ko);
                CP16(st + 4 * TILE_B + adst[j], Buh + boff[j] + ko);
                CP16(st + 5 * TILE_B + adst[j], Bul + boff[j] + ko);
            }
            CPCOMMIT();
        }
        s_next = (s_next == 2) ? 0 : s_next + 1;
        const uint32_t st = sb + (c % 3) * STG_GU;
        #pragma unroll
        for (int ks = 0; ks < 2; ks++) {
            uint32_t fAh[4][4], fAl[4][4];
            #pragma unroll
            for (int mi = 0; mi < 4; mi++) {
                uint32_t ro = (uint32_t)((wm * 64 + mi * 16) * SA * 2) + ks * 32;
                ldsm4(fAh[mi], st + 0 * TILE_B + ro + la);
                ldsm4(fAl[mi], st + 1 * TILE_B + ro + la);
            }
            {
                uint32_t fBh[2][4], fBl[2][4];
                #pragma unroll
                for (int nb = 0; nb < 2; nb++) {
                    uint32_t ro = (uint32_t)((wn * 32 + nb * 16) * SA * 2) + ks * 32;
                    ldsm4(fBh[nb], st + 2 * TILE_B + ro + lb);
                    ldsm4(fBl[nb], st + 3 * TILE_B + ro + lb);
                }
                #pragma unroll
                for (int mi = 0; mi < 4; mi++)
                    #pragma unroll
                    for (int ni = 0; ni < 4; ni++)
                        mma_bf16(accg[mi][ni], fAh[mi], &fBh[ni >> 1][(ni & 1) * 2]);
                #pragma unroll
                for (int mi = 0; mi < 4; mi++)
                    #pragma unroll
                    for (int ni = 0; ni < 4; ni++)
                        mma_bf16(accg[mi][ni], fAl[mi], &fBh[ni >> 1][(ni & 1) * 2]);
                #pragma unroll
                for (int mi = 0; mi < 4; mi++)
                    #pragma unroll
                    for (int ni = 0; ni < 4; ni++)
                        mma_bf16(accg[mi][ni], fAh[mi], &fBl[ni >> 1][(ni & 1) * 2]);
            }
            {
                uint32_t fBh[2][4], fBl[2][4];
                #pragma unroll
                for (int nb = 0; nb < 2; nb++) {
                    uint32_t ro = (uint32_t)((wn * 32 + nb * 16) * SA * 2) + ks * 32;
                    ldsm4(fBh[nb], st + 4 * TILE_B + ro + lb);
                    ldsm4(fBl[nb], st + 5 * TILE_B + ro + lb);
                }
                #pragma unroll
                for (int mi = 0; mi < 4; mi++)
                    #pragma unroll
                    for (int ni = 0; ni < 4; ni++)
                        mma_bf16(accu[mi][ni], fAh[mi], &fBh[ni >> 1][(ni & 1) * 2]);
                #pragma unroll
                for (int mi = 0; mi < 4; mi++)
                    #pragma unroll
                    for (int ni = 0; ni < 4; ni++)
                        mma_bf16(accu[mi][ni], fAl[mi], &fBh[ni >> 1][(ni & 1) * 2]);
                #pragma unroll
                for (int mi = 0; mi < 4; mi++)
                    #pragma unroll
                    for (int ni = 0; ni < 4; ni++)
                        mma_bf16(accu[mi][ni], fAh[mi], &fBl[ni >> 1][(ni & 1) * 2]);
            }
        }
    }

    // epilogue: swiglu (weighted if GATHER), split bf16 store
    #pragma unroll
    for (int mi = 0; mi < 4; mi++) {
        int p0 = row0 + wm * 64 + mi * 16 + g;
        int p1 = p0 + 8;
        #pragma unroll
        for (int half = 0; half < 2; half++) {
            int p = half ? p1 : p0;
            if (p >= M) continue;
            float w = GATHER ? g_wt[e * TMAX + p] : 1.f;
            size_t rowo = (GATHER ? (size_t)(g_base[e] + p) : (size_t)p) * N;
            #pragma unroll
            for (int ni = 0; ni < 4; ni++) {
                int col = col0 + wn * 32 + ni * 8 + 2 * t4;
                float gv0 = accg[mi][ni][half * 2 + 0];
                float gv1 = accg[mi][ni][half * 2 + 1];
                float uv0 = accu[mi][ni][half * 2 + 0];
                float uv1 = accu[mi][ni][half * 2 + 1];
                float v0 = w * (gv0 / (1.f + expf(-gv0))) * uv0;
                float v1 = w * (gv1 / (1.f + expf(-gv1))) * uv1;
                __nv_bfloat162 h = __floats2bfloat162_rn(v0, v1);
                __nv_bfloat162 l = __floats2bfloat162_rn(v0 - __bfloat162float(h.x),
                                                         v1 - __bfloat162float(h.y));
                *(__nv_bfloat162*)(Ch + rowo + col) = h;
                *(__nv_bfloat162*)(Cl + rowo + col) = l;
            }
        }
    }
}

// ---------------- down GEMM: split-bf16 A @ W^T -> f32 (dense or scatter) ----
template<int SCATTER>
__global__ __launch_bounds__(256, 1)
void k_dn(const __nv_bfloat16* __restrict__ Ah_g, const __nv_bfloat16* __restrict__ Al_g,
          const __nv_bfloat16* __restrict__ Bh_g, const __nv_bfloat16* __restrict__ Bl_g,
          float* __restrict__ C, int Mtot, int N, int K, size_t wstride, int ldc)
{
    const int e = blockIdx.z;
    const int M = SCATTER ? g_cnt[e] : Mtot;
    const int row0 = blockIdx.y * BM;
    if (row0 >= M) return;
    const int col0 = blockIdx.x * BN;
    const __nv_bfloat16* Bh = Bh_g + (size_t)e * wstride;
    const __nv_bfloat16* Bl = Bl_g + (size_t)e * wstride;

    extern __shared__ char dsm[];
    const uint32_t sb = smem_u32(dsm);

    const int tid = threadIdx.x;
    const int wid = tid >> 5, lane = tid & 31;
    const int wm = wid & 1, wn = wid >> 1;
    const int g = lane >> 2, t4 = lane & 3;

    size_t aoff[2]; size_t boff[2]; uint32_t adst[2];
    #pragma unroll
    for (int j = 0; j < 2; j++) {
        int q = tid + j * 256;
        int r = q >> 2, c16 = q & 3;
        adst[j] = r * (SA * 2) + c16 * 16;
        int gr = row0 + r;
        int grc = (gr < M) ? gr : (M - 1);
        if (SCATTER) aoff[j] = (size_t)(g_base[e] + grc) * K + c16 * 8;
        else         aoff[j] = (size_t)grc * K + c16 * 8;
        boff[j] = (size_t)(col0 + r) * K + c16 * 8;
    }
    const int a_r = (lane & 7) + ((lane >> 3) & 1) * 8;
    const int a_c = ((lane >> 4) & 1) * 8;
    const int b_r = (lane & 7) + ((lane >> 4) & 1) * 8;
    const int b_c = ((lane >> 3) & 1) * 8;
    const uint32_t la = (uint32_t)(a_r * SA + a_c) * 2;
    const uint32_t lb = (uint32_t)(b_r * SA + b_c) * 2;

    float acc[4][4][4];
    #pragma unroll
    for (int mi = 0; mi < 4; mi++)
        #pragma unroll
        for (int ni = 0; ni < 4; ni++)
            #pragma unroll
            for (int q = 0; q < 4; q++) acc[mi][ni][q] = 0.f;

    const int NC = K / BK;
    // prologue: chunks 0,1,2 -> stages 0,1,2
    #pragma unroll
    for (int pc = 0; pc < 3; pc++) {
        uint32_t st = sb + pc * STG_DN;
        size_t ko = (size_t)pc * BK;
        #pragma unroll
        for (int j = 0; j < 2; j++) {
            CP16(st + 0 * TILE_B + adst[j], Ah_g + aoff[j] + ko);
            CP16(st + 1 * TILE_B + adst[j], Al_g + aoff[j] + ko);
            CP16(st + 2 * TILE_B + adst[j], Bh + boff[j] + ko);
            CP16(st + 3 * TILE_B + adst[j], Bl + boff[j] + ko);
        }
        CPCOMMIT();
    }

    int s_next = 3;   // stage for chunk c+3
    for (int c = 0; c < NC; c++) {
        CPWAIT2();          // chunk c complete
        __syncthreads();
        {
            int nc3 = (c + 3 < NC) ? c + 3 : NC - 1;
            uint32_t st = sb + s_next * STG_DN;
            size_t ko = (size_t)nc3 * BK;
            #pragma unroll
            for (int j = 0; j < 2; j++) {
                CP16(st + 0 * TILE_B + adst[j], Ah_g + aoff[j] + ko);
                CP16(st + 1 * TILE_B + adst[j], Al_g + aoff[j] + ko);
                CP16(st + 2 * TILE_B + adst[j], Bh + boff[j] + ko);
                CP16(st + 3 * TILE_B + adst[j], Bl + boff[j] + ko);
            }
            CPCOMMIT();
        }
        s_next = (s_next + 1) & 3;
        const uint32_t st = sb + (c & 3) * STG_DN;
        #pragma unroll
        for (int ks = 0; ks < 2; ks++) {
            uint32_t fAh[4][4], fAl[4][4], fBh[2][4], fBl[2][4];
            #pragma unroll
            for (int mi = 0; mi < 4; mi++) {
                uint32_t ro = (uint32_t)((wm * 64 + mi * 16) * SA * 2) + ks * 32;
                ldsm4(fAh[mi], st + 0 * TILE_B + ro + la);
                ldsm4(fAl[mi], st + 1 * TILE_B + ro + la);
            }
            #pragma unroll
            for (int nb = 0; nb < 2; nb++) {
                uint32_t ro = (uint32_t)((wn * 32 + nb * 16) * SA * 2) + ks * 32;
                ldsm4(fBh[nb], st + 2 * TILE_B + ro + lb);
                ldsm4(fBl[nb], st + 3 * TILE_B + ro + lb);
            }
            #pragma unroll
            for (int mi = 0; mi < 4; mi++)
                #pragma unroll
                for (int ni = 0; ni < 4; ni++)
                    mma_bf16(acc[mi][ni], fAh[mi], &fBh[ni >> 1][(ni & 1) * 2]);
            #pragma unroll
            for (int mi = 0; mi < 4; mi++)
                #pragma unroll
                for (int ni = 0; ni < 4; ni++)
                    mma_bf16(acc[mi][ni], fAl[mi], &fBh[ni >> 1][(ni & 1) * 2]);
            #pragma unroll
            for (int mi = 0; mi < 4; mi++)
                #pragma unroll
                for (int ni = 0; ni < 4; ni++)
                    mma_bf16(acc[mi][ni], fAh[mi], &fBl[ni >> 1][(ni & 1) * 2]);
        }
    }

    #pragma unroll
    for (int mi = 0; mi < 4; mi++) {
        int p0 = row0 + wm * 64 + mi * 16 + g;
        int p1 = p0 + 8;
        float* c0 = nullptr; float* c1 = nullptr;
        if (SCATTER) {
            if (p0 < M) c0 = g_routed + (size_t)g_slot[e * TMAX + p0] * HD;
            if (p1 < M) c1 = g_routed + (size_t)g_slot[e * TMAX + p1] * HD;
        } else {
            c0 = C + (size_t)p0 * ldc;
            c1 = C + (size_t)p1 * ldc;
        }
        #pragma unroll
        for (int ni = 0; ni < 4; ni++) {
            int col = col0 + wn * 32 + ni * 8 + 2 * t4;
            if (c0) *(float2*)(c0 + col) = make_float2(acc[mi][ni][0], acc[mi][ni][1]);
            if (c1) *(float2*)(c1 + col) = make_float2(acc[mi][ni][2], acc[mi][ni][3]);
        }
    }
}

// ---------------- final: out += routed_slot0 + routed_slot1 ------------------
__global__ void k_final(float* __restrict__ out, int n4) {
    const float4* r = (const float4*)g_routed;
    float4* o4 = (float4*)out;
    int i = blockIdx.x * blockDim.x + threadIdx.x;
    int stride = gridDim.x * blockDim.x;
    for (; i < n4; i += stride) {
        float4 a = o4[i], b = r[i], c = r[i + n4];
        a.x += b.x + c.x;
        a.y += b.y + c.y;
        a.z += b.z + c.z;
        a.w += b.w + c.w;
        o4[i] = a;
    }
}

// ---------------- launch -----------------------------------------------------
extern "C" void kernel_launch(void* const* d_in, const int* in_sizes, int n_in,
                              void* d_out, int out_size) {
    const float* x   = (const float*)d_in[0];
    const float* Wr  = (const float*)d_in[1];
    const float* Wg  = (const float*)d_in[2];
    const float* Wu  = (const float*)d_in[3];
    const float* Wd  = (const float*)d_in[4];
    const float* Wsg = (const float*)d_in[5];
    const float* Wsu = (const float*)d_in[6];
    const float* Wsd = (const float*)d_in[7];
    float* out = (float*)d_out;
    const int T = in_sizes[0] / HD;   // 8192

    __nv_bfloat16 *xh, *xl, *bufH, *bufL;
    __nv_bfloat16 *WsgTh, *WsgTl, *WsuTh, *WsuTl, *WsdTh, *WsdTl;
    __nv_bfloat16 *WgTh, *WgTl, *WuTh, *WuTl, *WdTh, *WdTl;
    cudaGetSymbolAddress((void**)&xh, g_xh);
    cudaGetSymbolAddress((void**)&xl, g_xl);
    cudaGetSymbolAddress((void**)&bufH, g_bufH);
    cudaGetSymbolAddress((void**)&bufL, g_bufL);
    cudaGetSymbolAddress((void**)&WsgTh, g_WsgTh);
    cudaGetSymbolAddress((void**)&WsgTl, g_WsgTl);
    cudaGetSymbolAddress((void**)&WsuTh, g_WsuTh);
    cudaGetSymbolAddress((void**)&WsuTl, g_WsuTl);
    cudaGetSymbolAddress((void**)&WsdTh, g_WsdTh);
    cudaGetSymbolAddress((void**)&WsdTl, g_WsdTl);
    cudaGetSymbolAddress((void**)&WgTh, g_WgTh);
    cudaGetSymbolAddress((void**)&WgTl, g_WgTl);
    cudaGetSymbolAddress((void**)&WuTh, g_WuTh);
    cudaGetSymbolAddress((void**)&WuTl, g_WuTl);
    cudaGetSymbolAddress((void**)&WdTh, g_WdTh);
    cudaGetSymbolAddress((void**)&WdTl, g_WdTl);

    cudaFuncSetAttribute(k_gu<0>, cudaFuncAttributeMaxDynamicSharedMemorySize, SMEM_GU);
    cudaFuncSetAttribute(k_gu<1>, cudaFuncAttributeMaxDynamicSharedMemorySize, SMEM_GU);
    cudaFuncSetAttribute(k_dn<0>, cudaFuncAttributeMaxDynamicSharedMemorySize, SMEM_DN);
    cudaFuncSetAttribute(k_dn<1>, cudaFuncAttributeMaxDynamicSharedMemorySize, SMEM_DN);

    // operand prep needed by shared expert first, so k_gu<0> lands at launch
    // index 3 (the index ncu captures)
    k_split_x<<<2048, 256>>>(x, T * HD / 4);                               // 0
    dim3 tb(32, 8);
    k_tsplit<<<dim3(DS / 32, HD / 32, 1),  tb>>>(Wsg, WsgTh, WsgTl, HD, DS); // 1
    k_tsplit<<<dim3(DS / 32, HD / 32, 1),  tb>>>(Wsu, WsuTh, WsuTl, HD, DS); // 2
    k_gu<0><<<dim3(DS / BN, T / BM, 1), 256, SMEM_GU>>>(                     // 3 <- profiled
        xh, xl, WsgTh, WsgTl, WsuTh, WsuTl, bufH, bufL, T, DS, HD, 0);

    // routing
    k_init<<<1, 32>>>();
    k_router<<<T / 8, 256>>>(x, Wr, T);
    k_scan<<<1, 1>>>(out, T, out_size);

    // remaining weight prep
    k_tsplit<<<dim3(HD / 32, DS / 32, 1),  tb>>>(Wsd, WsdTh, WsdTl, DS, HD);
    k_tsplit<<<dim3(DD / 32, HD / 32, NE), tb>>>(Wg, WgTh, WgTl, HD, DD);
    k_tsplit<<<dim3(DD / 32, HD / 32, NE), tb>>>(Wu, WuTh, WuTl, HD, DD);
    k_tsplit<<<dim3(HD / 32, DD / 32, NE), tb>>>(Wd, WdTh, WdTl, DD, HD);

    // shared expert down -> out
    k_dn<0><<<dim3(HD / BN, T / BM, 1), 256, SMEM_DN>>>(
        bufH, bufL, WsdTh, WsdTl, out, T, HD, DS, 0, HD);

    // routed experts
    k_gu<1><<<dim3(DD / BN, T / BM, NE), 256, SMEM_GU>>>(
        xh, xl, WgTh, WgTl, WuTh, WuTl, bufH, bufL, 0, DD, HD, (size_t)DD * HD);
    k_dn<1><<<dim3(HD / BN, T / BM, NE), 256, SMEM_DN>>>(
        bufH, bufL, WdTh, WdTl, nullptr, 0, HD, DD, (size_t)HD * DD, HD);

    // combine
    k_final<<<2048, 256>>>(out, (T * HD) / 4);
}

// round 6
// speedup vs baseline: 2.7403x; 1.0929x over previous
#include <cuda_runtime.h>
#include <cuda_bf16.h>
#include <math.h>
#include <stdint.h>

#define NE   8
#define HD   1024
#define DD   512
#define DS   1024
#define TMAX 8192

#define BM 128
#define BN 128
#define BK 32
#define SA 40                 // bf16 elems per smem row (32 + 8 pad)
#define TILE_B (128 * SA * 2) // 10240 bytes per 128x32 bf16 tile
#define STG_GU (6 * TILE_B)
#define STG_DN (4 * TILE_B)
#define SMEM_GU (3 * STG_GU)  // 3-stage, 184320 B
#define SMEM_DN (4 * STG_DN)  // 4-stage, 163840 B

// ---------------- scratch (static device globals; no allocations) ------------
__device__ __align__(16) __nv_bfloat16 g_xh[(size_t)TMAX * HD];
__device__ __align__(16) __nv_bfloat16 g_xl[(size_t)TMAX * HD];
__device__ __align__(16) __nv_bfloat16 g_bufH[(size_t)NE * TMAX * DD];  // routed gu out
__device__ __align__(16) __nv_bfloat16 g_bufL[(size_t)NE * TMAX * DD];
__device__ __align__(16) __nv_bfloat16 g_buf2H[(size_t)TMAX * DS];      // shared gu out
__device__ __align__(16) __nv_bfloat16 g_buf2L[(size_t)TMAX * DS];
__device__ __align__(16) float g_routed[(size_t)2 * TMAX * HD];
__device__ __align__(16) __nv_bfloat16 g_WsgTh[(size_t)DS * HD];
__device__ __align__(16) __nv_bfloat16 g_WsgTl[(size_t)DS * HD];
__device__ __align__(16) __nv_bfloat16 g_WsuTh[(size_t)DS * HD];
__device__ __align__(16) __nv_bfloat16 g_WsuTl[(size_t)DS * HD];
__device__ __align__(16) __nv_bfloat16 g_WsdTh[(size_t)HD * DS];
__device__ __align__(16) __nv_bfloat16 g_WsdTl[(size_t)HD * DS];
__device__ __align__(16) __nv_bfloat16 g_WgTh[(size_t)NE * DD * HD];
__device__ __align__(16) __nv_bfloat16 g_WgTl[(size_t)NE * DD * HD];
__device__ __align__(16) __nv_bfloat16 g_WuTh[(size_t)NE * DD * HD];
__device__ __align__(16) __nv_bfloat16 g_WuTl[(size_t)NE * DD * HD];
__device__ __align__(16) __nv_bfloat16 g_WdTh[(size_t)NE * HD * DD];
__device__ __align__(16) __nv_bfloat16 g_WdTl[(size_t)NE * HD * DD];
__device__ int   g_cnt[NE];
__device__ int   g_tok[NE * TMAX];
__device__ int   g_slot[NE * TMAX];
__device__ float g_wt[NE * TMAX];
__device__ float g_psum[NE];

// ---------------- asm helpers ------------------------------------------------
__device__ __forceinline__ uint32_t smem_u32(const void* p) {
    uint32_t a;
    asm("{ .reg .u64 t; cvta.to.shared.u64 t, %1; cvt.u32.u64 %0, t; }" : "=r"(a) : "l"(p));
    return a;
}
#define CP16(dst, src) \
    asm volatile("cp.async.cg.shared.global [%0], [%1], 16;" :: "r"(dst), "l"(src) : "memory")
#define CPCOMMIT() asm volatile("cp.async.commit_group;" ::: "memory")
#define CPWAIT2()  asm volatile("cp.async.wait_group 2;" ::: "memory")
#define CPWAIT3()  asm volatile("cp.async.wait_group 3;" ::: "memory")

__device__ __forceinline__ void ldsm4(uint32_t* r, uint32_t addr) {
    asm volatile("ldmatrix.sync.aligned.m8n8.x4.shared.b16 {%0,%1,%2,%3}, [%4];"
        : "=r"(r[0]), "=r"(r[1]), "=r"(r[2]), "=r"(r[3]) : "r"(addr));
}
__device__ __forceinline__ void mma_bf16(float* c, const uint32_t* a, const uint32_t* b) {
    asm volatile(
        "mma.sync.aligned.m16n8k16.row.col.f32.bf16.bf16.f32 "
        "{%0,%1,%2,%3}, {%4,%5,%6,%7}, {%8,%9}, {%0,%1,%2,%3};\n"
        : "+f"(c[0]), "+f"(c[1]), "+f"(c[2]), "+f"(c[3])
        : "r"(a[0]), "r"(a[1]), "r"(a[2]), "r"(a[3]), "r"(b[0]), "r"(b[1]));
}

// ---------------- split x (+ zero counters) ----------------------------------
__global__ void k_split_x(const float* __restrict__ x, int n4) {
    if (blockIdx.x == 0 && threadIdx.x < NE) {
        g_cnt[threadIdx.x] = 0; g_psum[threadIdx.x] = 0.f;
    }
    int i = blockIdx.x * blockDim.x + threadIdx.x;
    int stride = gridDim.x * blockDim.x;
    for (; i < n4; i += stride) {
        float4 v = ((const float4*)x)[i];
        __nv_bfloat162 h01 = __floats2bfloat162_rn(v.x, v.y);
        __nv_bfloat162 h23 = __floats2bfloat162_rn(v.z, v.w);
        __nv_bfloat162 l01 = __floats2bfloat162_rn(v.x - __bfloat162float(h01.x),
                                                   v.y - __bfloat162float(h01.y));
        __nv_bfloat162 l23 = __floats2bfloat162_rn(v.z - __bfloat162float(h23.x),
                                                   v.w - __bfloat162float(h23.y));
        ((uint2*)g_xh)[i] = make_uint2(*(uint32_t*)&h01, *(uint32_t*)&h23);
        ((uint2*)g_xl)[i] = make_uint2(*(uint32_t*)&l01, *(uint32_t*)&l23);
    }
}

// -------- one launch: transpose+split all 27 weight matrices -----------------
__global__ void k_tsplit_all(const float* __restrict__ Wsg, const float* __restrict__ Wsu,
                             const float* __restrict__ Wsd, const float* __restrict__ Wg,
                             const float* __restrict__ Wu,  const float* __restrict__ Wd) {
    const int z = blockIdx.z;
    const float* in; __nv_bfloat16 *oh, *ol; int R, C;
    if (z == 0)      { in = Wsg; oh = g_WsgTh; ol = g_WsgTl; R = HD; C = DS; }
    else if (z == 1) { in = Wsu; oh = g_WsuTh; ol = g_WsuTl; R = HD; C = DS; }
    else if (z == 2) { in = Wsd; oh = g_WsdTh; ol = g_WsdTl; R = DS; C = HD; }
    else if (z < 11) { size_t m = (size_t)(z - 3) * HD * DD;
                       in = Wg + m; oh = g_WgTh + m; ol = g_WgTl + m; R = HD; C = DD; }
    else if (z < 19) { size_t m = (size_t)(z - 11) * HD * DD;
                       in = Wu + m; oh = g_WuTh + m; ol = g_WuTl + m; R = HD; C = DD; }
    else             { size_t m = (size_t)(z - 19) * DD * HD;
                       in = Wd + m; oh = g_WdTh + m; ol = g_WdTl + m; R = DD; C = HD; }
    int c0 = blockIdx.x * 32, r0 = blockIdx.y * 32;
    if (c0 >= C || r0 >= R) return;
    __shared__ float t[32][33];
    int tx = threadIdx.x, ty = threadIdx.y;
    #pragma unroll
    for (int j = 0; j < 32; j += 8)
        t[ty + j][tx] = in[(size_t)(r0 + ty + j) * C + c0 + tx];
    __syncthreads();
    #pragma unroll
    for (int j = 0; j < 32; j += 8) {
        float v = t[tx][ty + j];
        __nv_bfloat16 h = __float2bfloat16_rn(v);
        __nv_bfloat16 l = __float2bfloat16_rn(v - __bfloat162float(h));
        oh[(size_t)(c0 + ty + j) * R + r0 + tx] = h;
        ol[(size_t)(c0 + ty + j) * R + r0 + tx] = l;
    }
}

// ---------------- router ----------------------------------------------------
__global__ void k_router(const float* __restrict__ x, const float* __restrict__ Wr, int T) {
    __shared__ float s_p[NE];
    if (threadIdx.x < NE) s_p[threadIdx.x] = 0.f;
    __syncthreads();
    int warp = blockIdx.x * (blockDim.x >> 5) + (threadIdx.x >> 5);
    int lane = threadIdx.x & 31;
    if (warp < T) {
        int t = warp;
        const float* xr = x + (size_t)t * HD;
        float acc[NE];
        #pragma unroll
        for (int e = 0; e < NE; e++) acc[e] = 0.f;
        for (int i = lane; i < HD; i += 32) {
            float xv = xr[i];
            const float* w = Wr + (size_t)i * NE;
            #pragma unroll
            for (int e = 0; e < NE; e++) acc[e] += xv * w[e];
        }
        #pragma unroll
        for (int e = 0; e < NE; e++) {
            #pragma unroll
            for (int o = 16; o > 0; o >>= 1)
                acc[e] += __shfl_xor_sync(0xffffffffu, acc[e], o);
        }
        if (lane == 0) {
            float mx = acc[0];
            #pragma unroll
            for (int e = 1; e < NE; e++) mx = fmaxf(mx, acc[e]);
            float p[NE]; float s = 0.f;
            #pragma unroll
            for (int e = 0; e < NE; e++) { p[e] = expf(acc[e] - mx); s += p[e]; }
            float inv = 1.f / s;
            #pragma unroll
            for (int e = 0; e < NE; e++) p[e] *= inv;
            int i0 = 0;
            #pragma unroll
            for (int e = 1; e < NE; e++) if (p[e] > p[i0]) i0 = e;
            int i1 = (i0 == 0) ? 1 : 0;
            #pragma unroll
            for (int e = 0; e < NE; e++) if (e != i0 && p[e] > p[i1]) i1 = e;
            float w0 = p[i0], w1 = p[i1];
            float rn = 1.f / (w0 + w1);
            w0 *= rn; w1 *= rn;
            int pos0 = atomicAdd(&g_cnt[i0], 1);
            g_tok[i0 * TMAX + pos0]  = t;
            g_slot[i0 * TMAX + pos0] = t;
            g_wt[i0 * TMAX + pos0]   = w0;
            int pos1 = atomicAdd(&g_cnt[i1], 1);
            g_tok[i1 * TMAX + pos1]  = t;
            g_slot[i1 * TMAX + pos1] = T + t;
            g_wt[i1 * TMAX + pos1]   = w1;
            #pragma unroll
            for (int e = 0; e < NE; e++) atomicAdd(&s_p[e], p[e]);
        }
    }
    __syncthreads();
    if (threadIdx.x < NE) atomicAdd(&g_psum[threadIdx.x], s_p[threadIdx.x]);
}

// ------- merged gate+up GEMM + SwiGLU for shared (z=0) and all experts -------
__global__ __launch_bounds__(256, 1)
void k_gu_all(const __nv_bfloat16* __restrict__ Ah_g, const __nv_bfloat16* __restrict__ Al_g,
              int T)
{
    const int z = blockIdx.z;
    int M, N, e = 0;
    bool gather;
    const __nv_bfloat16 *Bgh, *Bgl, *Buh, *Bul;
    __nv_bfloat16 *Ch, *Cl;
    if (z == 0) {
        gather = false; M = T; N = DS;
        Bgh = g_WsgTh; Bgl = g_WsgTl; Buh = g_WsuTh; Bul = g_WsuTl;
        Ch = g_buf2H; Cl = g_buf2L;
    } else {
        gather = true; e = z - 1;
        if (blockIdx.x >= DD / BN) return;
        M = g_cnt[e]; N = DD;
        size_t ws = (size_t)e * DD * HD;
        Bgh = g_WgTh + ws; Bgl = g_WgTl + ws; Buh = g_WuTh + ws; Bul = g_WuTl + ws;
        Ch = g_bufH + (size_t)e * TMAX * DD; Cl = g_bufL + (size_t)e * TMAX * DD;
    }
    const int row0 = blockIdx.y * BM;
    if (row0 >= M) return;
    const int col0 = blockIdx.x * BN;
    const int K = HD;

    extern __shared__ char dsm[];
    const uint32_t sb = smem_u32(dsm);

    const int tid = threadIdx.x;
    const int wid = tid >> 5, lane = tid & 31;
    const int wm = wid & 1, wn = wid >> 1;
    const int g = lane >> 2, t4 = lane & 3;

    size_t aoff[2]; size_t boff[2]; uint32_t adst[2];
    #pragma unroll
    for (int j = 0; j < 2; j++) {
        int q = tid + j * 256;
        int r = q >> 2, c16 = q & 3;
        adst[j] = r * (SA * 2) + c16 * 16;
        int gr = row0 + r;
        int grc = (gr < M) ? gr : (M - 1);
        if (gather) aoff[j] = (size_t)g_tok[e * TMAX + grc] * K + c16 * 8;
        else        aoff[j] = (size_t)grc * K + c16 * 8;
        boff[j] = (size_t)(col0 + r) * K + c16 * 8;
    }

    const int a_r = (lane & 7) + ((lane >> 3) & 1) * 8;
    const int a_c = ((lane >> 4) & 1) * 8;
    const int b_r = (lane & 7) + ((lane >> 4) & 1) * 8;
    const int b_c = ((lane >> 3) & 1) * 8;
    const uint32_t la = (uint32_t)(a_r * SA + a_c) * 2;
    const uint32_t lb = (uint32_t)(b_r * SA + b_c) * 2;

    float accg[4][4][4], accu[4][4][4];
    #pragma unroll
    for (int mi = 0; mi < 4; mi++)
        #pragma unroll
        for (int ni = 0; ni < 4; ni++)
            #pragma unroll
            for (int q = 0; q < 4; q++) { accg[mi][ni][q] = 0.f; accu[mi][ni][q] = 0.f; }

    const int NC = K / BK;   // 32
    #pragma unroll
    for (int pc = 0; pc < 2; pc++) {
        uint32_t st = sb + pc * STG_GU;
        size_t ko = (size_t)pc * BK;
        #pragma unroll
        for (int j = 0; j < 2; j++) {
            CP16(st + 0 * TILE_B + adst[j], Ah_g + aoff[j] + ko);
            CP16(st + 1 * TILE_B + adst[j], Al_g + aoff[j] + ko);
            CP16(st + 2 * TILE_B + adst[j], Bgh + boff[j] + ko);
            CP16(st + 3 * TILE_B + adst[j], Bgl + boff[j] + ko);
            CP16(st + 4 * TILE_B + adst[j], Buh + boff[j] + ko);
            CP16(st + 5 * TILE_B + adst[j], Bul + boff[j] + ko);
        }
        CPCOMMIT();
    }

    int s_next = 2;
    for (int c = 0; c < NC; c++) {
        CPWAIT2();          // chunk c complete; up to 2 younger in flight
        __syncthreads();
        {
            int nc2 = (c + 2 < NC) ? c + 2 : NC - 1;
            uint32_t st = sb + s_next * STG_GU;
            size_t ko = (size_t)nc2 * BK;
            #pragma unroll
            for (int j = 0; j < 2; j++) {
                CP16(st + 0 * TILE_B + adst[j], Ah_g + aoff[j] + ko);
                CP16(st + 1 * TILE_B + adst[j], Al_g + aoff[j] + ko);
                CP16(st + 2 * TILE_B + adst[j], Bgh + boff[j] + ko);
                CP16(st + 3 * TILE_B + adst[j], Bgl + boff[j] + ko);
                CP16(st + 4 * TILE_B + adst[j], Buh + boff[j] + ko);
                CP16(st + 5 * TILE_B + adst[j], Bul + boff[j] + ko);
            }
            CPCOMMIT();
        }
        s_next = (s_next == 2) ? 0 : s_next + 1;
        const uint32_t st = sb + (c % 3) * STG_GU;
        #pragma unroll
        for (int ks = 0; ks < 2; ks++) {
            uint32_t fAh[4][4], fAl[4][4];
            #pragma unroll
            for (int mi = 0; mi < 4; mi++) {
                uint32_t ro = (uint32_t)((wm * 64 + mi * 16) * SA * 2) + ks * 32;
                ldsm4(fAh[mi], st + 0 * TILE_B + ro + la);
                ldsm4(fAl[mi], st + 1 * TILE_B + ro + la);
            }
            {
                uint32_t fBh[2][4], fBl[2][4];
                #pragma unroll
                for (int nb = 0; nb < 2; nb++) {
                    uint32_t ro = (uint32_t)((wn * 32 + nb * 16) * SA * 2) + ks * 32;
                    ldsm4(fBh[nb], st + 2 * TILE_B + ro + lb);
                    ldsm4(fBl[nb], st + 3 * TILE_B + ro + lb);
                }
                #pragma unroll
                for (int mi = 0; mi < 4; mi++)
                    #pragma unroll
                    for (int ni = 0; ni < 4; ni++)
                        mma_bf16(accg[mi][ni], fAh[mi], &fBh[ni >> 1][(ni & 1) * 2]);
                #pragma unroll
                for (int mi = 0; mi < 4; mi++)
                    #pragma unroll
                    for (int ni = 0; ni < 4; ni++)
                        mma_bf16(accg[mi][ni], fAl[mi], &fBh[ni >> 1][(ni & 1) * 2]);
                #pragma unroll
                for (int mi = 0; mi < 4; mi++)
                    #pragma unroll
                    for (int ni = 0; ni < 4; ni++)
                        mma_bf16(accg[mi][ni], fAh[mi], &fBl[ni >> 1][(ni & 1) * 2]);
            }
            {
                uint32_t fBh[2][4], fBl[2][4];
                #pragma unroll
                for (int nb = 0; nb < 2; nb++) {
                    uint32_t ro = (uint32_t)((wn * 32 + nb * 16) * SA * 2) + ks * 32;
                    ldsm4(fBh[nb], st + 4 * TILE_B + ro + lb);
                    ldsm4(fBl[nb], st + 5 * TILE_B + ro + lb);
                }
                #pragma unroll
                for (int mi = 0; mi < 4; mi++)
                    #pragma unroll
                    for (int ni = 0; ni < 4; ni++)
                        mma_bf16(accu[mi][ni], fAh[mi], &fBh[ni >> 1][(ni & 1) * 2]);
                #pragma unroll
                for (int mi = 0; mi < 4; mi++)
                    #pragma unroll
                    for (int ni = 0; ni < 4; ni++)
                        mma_bf16(accu[mi][ni], fAl[mi], &fBh[ni >> 1][(ni & 1) * 2]);
                #pragma unroll
                for (int mi = 0; mi < 4; mi++)
                    #pragma unroll
                    for (int ni = 0; ni < 4; ni++)
                        mma_bf16(accu[mi][ni], fAh[mi], &fBl[ni >> 1][(ni & 1) * 2]);
            }
        }
    }

    #pragma unroll
    for (int mi = 0; mi < 4; mi++) {
        int p0 = row0 + wm * 64 + mi * 16 + g;
        #pragma unroll
        for (int half = 0; half < 2; half++) {
            int p = p0 + half * 8;
            if (p >= M) continue;
            float w = gather ? g_wt[e * TMAX + p] : 1.f;
            size_t rowo = (size_t)p * N;
            #pragma unroll
            for (int ni = 0; ni < 4; ni++) {
                int col = col0 + wn * 32 + ni * 8 + 2 * t4;
                float gv0 = accg[mi][ni][half * 2 + 0];
                float gv1 = accg[mi][ni][half * 2 + 1];
                float uv0 = accu[mi][ni][half * 2 + 0];
                float uv1 = accu[mi][ni][half * 2 + 1];
                float v0 = w * (gv0 / (1.f + expf(-gv0))) * uv0;
                float v1 = w * (gv1 / (1.f + expf(-gv1))) * uv1;
                __nv_bfloat162 h = __floats2bfloat162_rn(v0, v1);
                __nv_bfloat162 l = __floats2bfloat162_rn(v0 - __bfloat162float(h.x),
                                                         v1 - __bfloat162float(h.y));
                *(__nv_bfloat162*)(Ch + rowo + col) = h;
                *(__nv_bfloat162*)(Cl + rowo + col) = l;
            }
        }
    }
}

// ------- merged down GEMM: shared (z=0, dense) and experts (scatter) ---------
__global__ __launch_bounds__(256, 1)
void k_dn_all(float* __restrict__ out, int T)
{
    const int z = blockIdx.z;
    int M, K, e = 0;
    bool scatter;
    const __nv_bfloat16 *Ah_g, *Al_g, *Bh, *Bl;
    if (z == 0) {
        scatter = false; M = T; K = DS;
        Ah_g = g_buf2H; Al_g = g_buf2L;
        Bh = g_WsdTh; Bl = g_WsdTl;
    } else {
        scatter = true; e = z - 1;
        M = g_cnt[e]; K = DD;
        Ah_g = g_bufH + (size_t)e * TMAX * DD;
        Al_g = g_bufL + (size_t)e * TMAX * DD;
        size_t ws = (size_t)e * HD * DD;
        Bh = g_WdTh + ws; Bl = g_WdTl + ws;
    }
    const int row0 = blockIdx.y * BM;
    if (row0 >= M) return;
    const int col0 = blockIdx.x * BN;   // N = HD, x in [0,8)

    extern __shared__ char dsm[];
    const uint32_t sb = smem_u32(dsm);

    const int tid = threadIdx.x;
    const int wid = tid >> 5, lane = tid & 31;
    const int wm = wid & 1, wn = wid >> 1;
    const int g = lane >> 2, t4 = lane & 3;

    size_t aoff[2]; size_t boff[2]; uint32_t adst[2];
    #pragma unroll
    for (int j = 0; j < 2; j++) {
        int q = tid + j * 256;
        int r = q >> 2, c16 = q & 3;
        adst[j] = r * (SA * 2) + c16 * 16;
        int gr = row0 + r;
        int grc = (gr < M) ? gr : (M - 1);
        aoff[j] = (size_t)grc * K + c16 * 8;
        boff[j] = (size_t)(col0 + r) * K + c16 * 8;
    }
    const int a_r = (lane & 7) + ((lane >> 3) & 1) * 8;
    const int a_c = ((lane >> 4) & 1) * 8;
    const int b_r = (lane & 7) + ((lane >> 4) & 1) * 8;
    const int b_c = ((lane >> 3) & 1) * 8;
    const uint32_t la = (uint32_t)(a_r * SA + a_c) * 2;
    const uint32_t lb = (uint32_t)(b_r * SA + b_c) * 2;

    float acc[4][4][4];
    #pragma unroll
    for (int mi = 0; mi < 4; mi++)
        #pragma unroll
        for (int ni = 0; ni < 4; ni++)
            #pragma unroll
            for (int q = 0; q < 4; q++) acc[mi][ni][q] = 0.f;

    const int NC = K / BK;   // 32 or 16
    #pragma unroll
    for (int pc = 0; pc < 3; pc++) {
        uint32_t st = sb + pc * STG_DN;
        size_t ko = (size_t)pc * BK;
        #pragma unroll
        for (int j = 0; j < 2; j++) {
            CP16(st + 0 * TILE_B + adst[j], Ah_g + aoff[j] + ko);
            CP16(st + 1 * TILE_B + adst[j], Al_g + aoff[j] + ko);
            CP16(st + 2 * TILE_B + adst[j], Bh + boff[j] + ko);
            CP16(st + 3 * TILE_B + adst[j], Bl + boff[j] + ko);
        }
        CPCOMMIT();
    }

    int s_next = 3;
    for (int c = 0; c < NC; c++) {
        CPWAIT3();
        __syncthreads();
        {
            int nc3 = (c + 3 < NC) ? c + 3 : NC - 1;
            uint32_t st = sb + s_next * STG_DN;
            size_t ko = (size_t)nc3 * BK;
            #pragma unroll
            for (int j = 0; j < 2; j++) {
                CP16(st + 0 * TILE_B + adst[j], Ah_g + aoff[j] + ko);
                CP16(st + 1 * TILE_B + adst[j], Al_g + aoff[j] + ko);
                CP16(st + 2 * TILE_B + adst[j], Bh + boff[j] + ko);
                CP16(st + 3 * TILE_B + adst[j], Bl + boff[j] + ko);
            }
            CPCOMMIT();
        }
        s_next = (s_next + 1) & 3;
        const uint32_t st = sb + (c & 3) * STG_DN;
        #pragma unroll
        for (int ks = 0; ks < 2; ks++) {
            uint32_t fAh[4][4], fAl[4][4], fBh[2][4], fBl[2][4];
            #pragma unroll
            for (int mi = 0; mi < 4; mi++) {
                uint32_t ro = (uint32_t)((wm * 64 + mi * 16) * SA * 2) + ks * 32;
                ldsm4(fAh[mi], st + 0 * TILE_B + ro + la);
                ldsm4(fAl[mi], st + 1 * TILE_B + ro + la);
            }
            #pragma unroll
            for (int nb = 0; nb < 2; nb++) {
                uint32_t ro = (uint32_t)((wn * 32 + nb * 16) * SA * 2) + ks * 32;
                ldsm4(fBh[nb], st + 2 * TILE_B + ro + lb);
                ldsm4(fBl[nb], st + 3 * TILE_B + ro + lb);
            }
            #pragma unroll
            for (int mi = 0; mi < 4; mi++)
                #pragma unroll
                for (int ni = 0; ni < 4; ni++)
                    mma_bf16(acc[mi][ni], fAh[mi], &fBh[ni >> 1][(ni & 1) * 2]);
            #pragma unroll
            for (int mi = 0; mi < 4; mi++)
                #pragma unroll
                for (int ni = 0; ni < 4; ni++)
                    mma_bf16(acc[mi][ni], fAl[mi], &fBh[ni >> 1][(ni & 1) * 2]);
            #pragma unroll
            for (int mi = 0; mi < 4; mi++)
                #pragma unroll
                for (int ni = 0; ni < 4; ni++)
                    mma_bf16(acc[mi][ni], fAh[mi], &fBl[ni >> 1][(ni & 1) * 2]);
        }
    }

    #pragma unroll
    for (int mi = 0; mi < 4; mi++) {
        int p0 = row0 + wm * 64 + mi * 16 + g;
        int p1 = p0 + 8;
        float* c0 = nullptr; float* c1 = nullptr;
        if (scatter) {
            if (p0 < M) c0 = g_routed + (size_t)g_slot[e * TMAX + p0] * HD;
            if (p1 < M) c1 = g_routed + (size_t)g_slot[e * TMAX + p1] * HD;
        } else {
            c0 = out + (size_t)p0 * HD;
            c1 = out + (size_t)p1 * HD;
        }
        #pragma unroll
        for (int ni = 0; ni < 4; ni++) {
            int col = col0 + wn * 32 + ni * 8 + 2 * t4;
            if (c0) *(float2*)(c0 + col) = make_float2(acc[mi][ni][0], acc[mi][ni][1]);
            if (c1) *(float2*)(c1 + col) = make_float2(acc[mi][ni][2], acc[mi][ni][3]);
        }
    }
}

// ---------------- final: out += routed slots; aux loss tail ------------------
__global__ void k_final(float* __restrict__ out, int n4, int T, int out_size) {
    if (blockIdx.x == 0 && threadIdx.x == 0) {
        float a = 0.f;
        for (int e = 0; e < NE; e++) { float m = g_psum[e] / (float)T; a += m * m; }
        a *= (float)NE;
        for (size_t i = (size_t)T * HD; i < (size_t)out_size; i++) out[i] = a;
    }
    const float4* r = (const float4*)g_routed;
    float4* o4 = (float4*)out;
    int i = blockIdx.x * blockDim.x + threadIdx.x;
    int stride = gridDim.x * blockDim.x;
    for (; i < n4; i += stride) {
        float4 a = o4[i], b = r[i], c = r[i + n4];
        a.x += b.x + c.x;
        a.y += b.y + c.y;
        a.z += b.z + c.z;
        a.w += b.w + c.w;
        o4[i] = a;
    }
}

// ---------------- launch -----------------------------------------------------
extern "C" void kernel_launch(void* const* d_in, const int* in_sizes, int n_in,
                              void* d_out, int out_size) {
    const float* x   = (const float*)d_in[0];
    const float* Wr  = (const float*)d_in[1];
    const float* Wg  = (const float*)d_in[2];
    const float* Wu  = (const float*)d_in[3];
    const float* Wd  = (const float*)d_in[4];
    const float* Wsg = (const float*)d_in[5];
    const float* Wsu = (const float*)d_in[6];
    const float* Wsd = (const float*)d_in[7];
    float* out = (float*)d_out;
    const int T = in_sizes[0] / HD;   // 8192

    __nv_bfloat16 *xh, *xl;
    cudaGetSymbolAddress((void**)&xh, g_xh);
    cudaGetSymbolAddress((void**)&xl, g_xl);

    cudaFuncSetAttribute(k_gu_all, cudaFuncAttributeMaxDynamicSharedMemorySize, SMEM_GU);
    cudaFuncSetAttribute(k_dn_all, cudaFuncAttributeMaxDynamicSharedMemorySize, SMEM_DN);

    // 0: split x (+ zero routing counters)
    k_split_x<<<2048, 256>>>(x, T * HD / 4);
    // 1: all weight transposes+splits
    k_tsplit_all<<<dim3(32, 32, 27), dim3(32, 8)>>>(Wsg, Wsu, Wsd, Wg, Wu, Wd);
    // 2: router
    k_router<<<T / 8, 256>>>(x, Wr, T);
    // 3: merged gate+up (+swiglu) — shared expert + all routed experts
    k_gu_all<<<dim3(DS / BN, T / BM, NE + 1), 256, SMEM_GU>>>(xh, xl, T);
    // 4: merged down — shared (dense to out) + routed (scatter to slots)
    k_dn_all<<<dim3(HD / BN, T / BM, NE + 1), 256, SMEM_DN>>>(out, T);
    // 5: combine + aux loss
    k_final<<<2048, 256>>>(out, (T * HD) / 4, T, out_size);
}

// round 8
// speedup vs baseline: 2.8388x; 1.0360x over previous
#include <cuda_runtime.h>
#include <cuda_bf16.h>
#include <math.h>
#include <stdint.h>

#define NE   8
#define HD   1024
#define DD   512
#define DS   1024
#define TMAX 8192

#define BM 128
#define BN 128
#define BK 32
#define SA 40                 // bf16 elems per smem row (32 + 8 pad)
#define TILE_B (128 * SA * 2) // 10240 bytes per 128x32 bf16 tile
#define STG_GU (6 * TILE_B)
#define STG_DN (4 * TILE_B)
#define SMEM_GU (3 * STG_GU)  // 3-stage, 184320 B
#define SMEM_DN (4 * STG_DN)  // 4-stage, 163840 B

// ---------------- scratch (static device globals; no allocations) ------------
__device__ __align__(16) __nv_bfloat16 g_xh[(size_t)TMAX * HD];
__device__ __align__(16) __nv_bfloat16 g_xl[(size_t)TMAX * HD];
__device__ __align__(16) __nv_bfloat16 g_bufH[(size_t)NE * TMAX * DD];
__device__ __align__(16) __nv_bfloat16 g_bufL[(size_t)NE * TMAX * DD];
__device__ __align__(16) __nv_bfloat16 g_buf2H[(size_t)TMAX * DS];
__device__ __align__(16) __nv_bfloat16 g_buf2L[(size_t)TMAX * DS];
__device__ __align__(16) float g_routed[(size_t)2 * TMAX * HD];
__device__ __align__(16) __nv_bfloat16 g_WsgTh[(size_t)DS * HD];
__device__ __align__(16) __nv_bfloat16 g_WsgTl[(size_t)DS * HD];
__device__ __align__(16) __nv_bfloat16 g_WsuTh[(size_t)DS * HD];
__device__ __align__(16) __nv_bfloat16 g_WsuTl[(size_t)DS * HD];
__device__ __align__(16) __nv_bfloat16 g_WsdTh[(size_t)HD * DS];
__device__ __align__(16) __nv_bfloat16 g_WsdTl[(size_t)HD * DS];
__device__ __align__(16) __nv_bfloat16 g_WgTh[(size_t)NE * DD * HD];
__device__ __align__(16) __nv_bfloat16 g_WgTl[(size_t)NE * DD * HD];
__device__ __align__(16) __nv_bfloat16 g_WuTh[(size_t)NE * DD * HD];
__device__ __align__(16) __nv_bfloat16 g_WuTl[(size_t)NE * DD * HD];
__device__ __align__(16) __nv_bfloat16 g_WdTh[(size_t)NE * HD * DD];
__device__ __align__(16) __nv_bfloat16 g_WdTl[(size_t)NE * HD * DD];
__device__ int   g_cnt[NE];
__device__ int   g_tok[NE * TMAX];
__device__ int   g_slot[NE * TMAX];
__device__ float g_wt[NE * TMAX];
__device__ float g_psum[NE];

// ---------------- asm helpers ------------------------------------------------
__device__ __forceinline__ uint32_t smem_u32(const void* p) {
    uint32_t a;
    asm("{ .reg .u64 t; cvta.to.shared.u64 t, %1; cvt.u32.u64 %0, t; }" : "=r"(a) : "l"(p));
    return a;
}
#define CP16(dst, src) \
    asm volatile("cp.async.cg.shared.global [%0], [%1], 16;" :: "r"(dst), "l"(src) : "memory")
#define CPCOMMIT() asm volatile("cp.async.commit_group;" ::: "memory")
#define CPWAIT1()  asm volatile("cp.async.wait_group 1;" ::: "memory")
#define CPWAIT2()  asm volatile("cp.async.wait_group 2;" ::: "memory")

__device__ __forceinline__ void ldsm4(uint32_t* r, uint32_t addr) {
    asm volatile("ldmatrix.sync.aligned.m8n8.x4.shared.b16 {%0,%1,%2,%3}, [%4];"
        : "=r"(r[0]), "=r"(r[1]), "=r"(r[2]), "=r"(r[3]) : "r"(addr));
}
__device__ __forceinline__ void mma_bf16(float* c, const uint32_t* a, const uint32_t* b) {
    asm volatile(
        "mma.sync.aligned.m16n8k16.row.col.f32.bf16.bf16.f32 "
        "{%0,%1,%2,%3}, {%4,%5,%6,%7}, {%8,%9}, {%0,%1,%2,%3};\n"
        : "+f"(c[0]), "+f"(c[1]), "+f"(c[2]), "+f"(c[3])
        : "r"(a[0]), "r"(a[1]), "r"(a[2]), "r"(a[3]), "r"(b[0]), "r"(b[1]));
}

// ---------------- split x (+ zero counters) ----------------------------------
__global__ void k_split_x(const float* __restrict__ x, int n4) {
    if (blockIdx.x == 0 && threadIdx.x < NE) {
        g_cnt[threadIdx.x] = 0; g_psum[threadIdx.x] = 0.f;
    }
    int i = blockIdx.x * blockDim.x + threadIdx.x;
    int stride = gridDim.x * blockDim.x;
    for (; i < n4; i += stride) {
        float4 v = ((const float4*)x)[i];
        __nv_bfloat162 h01 = __floats2bfloat162_rn(v.x, v.y);
        __nv_bfloat162 h23 = __floats2bfloat162_rn(v.z, v.w);
        __nv_bfloat162 l01 = __floats2bfloat162_rn(v.x - __bfloat162float(h01.x),
                                                   v.y - __bfloat162float(h01.y));
        __nv_bfloat162 l23 = __floats2bfloat162_rn(v.z - __bfloat162float(h23.x),
                                                   v.w - __bfloat162float(h23.y));
        ((uint2*)g_xh)[i] = make_uint2(*(uint32_t*)&h01, *(uint32_t*)&h23);
        ((uint2*)g_xl)[i] = make_uint2(*(uint32_t*)&l01, *(uint32_t*)&l23);
    }
}

// -------- one launch: transpose+split all 27 weight matrices -----------------
__global__ void k_tsplit_all(const float* __restrict__ Wsg, const float* __restrict__ Wsu,
                             const float* __restrict__ Wsd, const float* __restrict__ Wg,
                             const float* __restrict__ Wu,  const float* __restrict__ Wd) {
    const int z = blockIdx.z;
    const float* in; __nv_bfloat16 *oh, *ol; int R, C;
    if (z == 0)      { in = Wsg; oh = g_WsgTh; ol = g_WsgTl; R = HD; C = DS; }
    else if (z == 1) { in = Wsu; oh = g_WsuTh; ol = g_WsuTl; R = HD; C = DS; }
    else if (z == 2) { in = Wsd; oh = g_WsdTh; ol = g_WsdTl; R = DS; C = HD; }
    else if (z < 11) { size_t m = (size_t)(z - 3) * HD * DD;
                       in = Wg + m; oh = g_WgTh + m; ol = g_WgTl + m; R = HD; C = DD; }
    else if (z < 19) { size_t m = (size_t)(z - 11) * HD * DD;
                       in = Wu + m; oh = g_WuTh + m; ol = g_WuTl + m; R = HD; C = DD; }
    else             { size_t m = (size_t)(z - 19) * DD * HD;
                       in = Wd + m; oh = g_WdTh + m; ol = g_WdTl + m; R = DD; C = HD; }
    int c0 = blockIdx.x * 32, r0 = blockIdx.y * 32;
    if (c0 >= C || r0 >= R) return;
    __shared__ float t[32][33];
    int tx = threadIdx.x, ty = threadIdx.y;
    #pragma unroll
    for (int j = 0; j < 32; j += 8)
        t[ty + j][tx] = in[(size_t)(r0 + ty + j) * C + c0 + tx];
    __syncthreads();
    #pragma unroll
    for (int j = 0; j < 32; j += 8) {
        float v = t[tx][ty + j];
        __nv_bfloat16 h = __float2bfloat16_rn(v);
        __nv_bfloat16 l = __float2bfloat16_rn(v - __bfloat162float(h));
        oh[(size_t)(c0 + ty + j) * R + r0 + tx] = h;
        ol[(size_t)(c0 + ty + j) * R + r0 + tx] = l;
    }
}

// ---------------- router ----------------------------------------------------
__global__ void k_router(const float* __restrict__ x, const float* __restrict__ Wr, int T) {
    __shared__ float s_p[NE];
    if (threadIdx.x < NE) s_p[threadIdx.x] = 0.f;
    __syncthreads();
    int warp = blockIdx.x * (blockDim.x >> 5) + (threadIdx.x >> 5);
    int lane = threadIdx.x & 31;
    if (warp < T) {
        int t = warp;
        const float* xr = x + (size_t)t * HD;
        float acc[NE];
        #pragma unroll
        for (int e = 0; e < NE; e++) acc[e] = 0.f;
        for (int i = lane; i < HD; i += 32) {
            float xv = xr[i];
            const float* w = Wr + (size_t)i * NE;
            #pragma unroll
            for (int e = 0; e < NE; e++) acc[e] += xv * w[e];
        }
        #pragma unroll
        for (int e = 0; e < NE; e++) {
            #pragma unroll
            for (int o = 16; o > 0; o >>= 1)
                acc[e] += __shfl_xor_sync(0xffffffffu, acc[e], o);
        }
        if (lane == 0) {
            float mx = acc[0];
            #pragma unroll
            for (int e = 1; e < NE; e++) mx = fmaxf(mx, acc[e]);
            float p[NE]; float s = 0.f;
            #pragma unroll
            for (int e = 0; e < NE; e++) { p[e] = expf(acc[e] - mx); s += p[e]; }
            float inv = 1.f / s;
            #pragma unroll
            for (int e = 0; e < NE; e++) p[e] *= inv;
            int i0 = 0;
            #pragma unroll
            for (int e = 1; e < NE; e++) if (p[e] > p[i0]) i0 = e;
            int i1 = (i0 == 0) ? 1 : 0;
            #pragma unroll
            for (int e = 0; e < NE; e++) if (e != i0 && p[e] > p[i1]) i1 = e;
            float w0 = p[i0], w1 = p[i1];
            float rn = 1.f / (w0 + w1);
            w0 *= rn; w1 *= rn;
            int pos0 = atomicAdd(&g_cnt[i0], 1);
            g_tok[i0 * TMAX + pos0]  = t;
            g_slot[i0 * TMAX + pos0] = t;
            g_wt[i0 * TMAX + pos0]   = w0;
            int pos1 = atomicAdd(&g_cnt[i1], 1);
            g_tok[i1 * TMAX + pos1]  = t;
            g_slot[i1 * TMAX + pos1] = T + t;
            g_wt[i1 * TMAX + pos1]   = w1;
            #pragma unroll
            for (int e = 0; e < NE; e++) atomicAdd(&s_p[e], p[e]);
        }
    }
    __syncthreads();
    if (threadIdx.x < NE) atomicAdd(&g_psum[threadIdx.x], s_p[threadIdx.x]);
}

// ------- merged gate+up GEMM + SwiGLU, 512 threads, warp tile 32x32 ----------
__global__ __launch_bounds__(512, 1)
void k_gu_all(const __nv_bfloat16* __restrict__ Ah_g, const __nv_bfloat16* __restrict__ Al_g,
              int T)
{
    const int z = blockIdx.z;
    int M, N, e = 0;
    bool gather;
    const __nv_bfloat16 *Bgh, *Bgl, *Buh, *Bul;
    __nv_bfloat16 *Ch, *Cl;
    if (z == 0) {
        gather = false; M = T; N = DS;
        Bgh = g_WsgTh; Bgl = g_WsgTl; Buh = g_WsuTh; Bul = g_WsuTl;
        Ch = g_buf2H; Cl = g_buf2L;
    } else {
        gather = true; e = z - 1;
        if (blockIdx.x >= DD / BN) return;
        M = g_cnt[e]; N = DD;
        size_t ws = (size_t)e * DD * HD;
        Bgh = g_WgTh + ws; Bgl = g_WgTl + ws; Buh = g_WuTh + ws; Bul = g_WuTl + ws;
        Ch = g_bufH + (size_t)e * TMAX * DD; Cl = g_bufL + (size_t)e * TMAX * DD;
    }
    const int row0 = blockIdx.y * BM;
    if (row0 >= M) return;
    const int col0 = blockIdx.x * BN;
    const int K = HD;

    extern __shared__ char dsm[];
    const uint32_t sb = smem_u32(dsm);

    const int tid = threadIdx.x;
    const int wid = tid >> 5, lane = tid & 31;
    const int wm = wid & 3, wn = wid >> 2;       // 4x4 warp grid, 32x32 tiles
    const int g = lane >> 2, t4 = lane & 3;

    // cp.async: one 16B chunk per tile per thread (512 threads cover 128x4)
    size_t aoff, boff; uint32_t adst;
    {
        int r = tid >> 2, c16 = tid & 3;
        adst = r * (SA * 2) + c16 * 16;
        int gr = row0 + r;
        int grc = (gr < M) ? gr : (M - 1);
        if (gather) aoff = (size_t)g_tok[e * TMAX + grc] * K + c16 * 8;
        else        aoff = (size_t)grc * K + c16 * 8;
        boff = (size_t)(col0 + r) * K + c16 * 8;
    }

    const int a_r = (lane & 7) + ((lane >> 3) & 1) * 8;
    const int a_c = ((lane >> 4) & 1) * 8;
    const int b_r = (lane & 7) + ((lane >> 4) & 1) * 8;
    const int b_c = ((lane >> 3) & 1) * 8;
    const uint32_t la = (uint32_t)(a_r * SA + a_c) * 2;
    const uint32_t lb = (uint32_t)(b_r * SA + b_c) * 2;

    float accg[2][4][4], accu[2][4][4];
    #pragma unroll
    for (int mi = 0; mi < 2; mi++)
        #pragma unroll
        for (int ni = 0; ni < 4; ni++)
            #pragma unroll
            for (int q = 0; q < 4; q++) { accg[mi][ni][q] = 0.f; accu[mi][ni][q] = 0.f; }

    const int NC = K / BK;   // 32
    #pragma unroll
    for (int pc = 0; pc < 2; pc++) {
        uint32_t st = sb + pc * STG_GU;
        size_t ko = (size_t)pc * BK;
        CP16(st + 0 * TILE_B + adst, Ah_g + aoff + ko);
        CP16(st + 1 * TILE_B + adst, Al_g + aoff + ko);
        CP16(st + 2 * TILE_B + adst, Bgh + boff + ko);
        CP16(st + 3 * TILE_B + adst, Bgl + boff + ko);
        CP16(st + 4 * TILE_B + adst, Buh + boff + ko);
        CP16(st + 5 * TILE_B + adst, Bul + boff + ko);
        CPCOMMIT();
    }

    int s_next = 2;
    for (int c = 0; c < NC; c++) {
        // pending at top: {c, c+1} -> wait_group 1 guarantees chunk c landed
        CPWAIT1();
        __syncthreads();   // all threads have chunk c; stage s_next free
        {
            int nc2 = (c + 2 < NC) ? c + 2 : NC - 1;
            uint32_t st = sb + s_next * STG_GU;
            size_t ko = (size_t)nc2 * BK;
            CP16(st + 0 * TILE_B + adst, Ah_g + aoff + ko);
            CP16(st + 1 * TILE_B + adst, Al_g + aoff + ko);
            CP16(st + 2 * TILE_B + adst, Bgh + boff + ko);
            CP16(st + 3 * TILE_B + adst, Bgl + boff + ko);
            CP16(st + 4 * TILE_B + adst, Buh + boff + ko);
            CP16(st + 5 * TILE_B + adst, Bul + boff + ko);
            CPCOMMIT();
        }
        s_next = (s_next == 2) ? 0 : s_next + 1;
        const uint32_t st = sb + (c % 3) * STG_GU;
        #pragma unroll
        for (int ks = 0; ks < 2; ks++) {
            uint32_t fAh[2][4], fAl[2][4];
            #pragma unroll
            for (int mi = 0; mi < 2; mi++) {
                uint32_t ro = (uint32_t)((wm * 32 + mi * 16) * SA * 2) + ks * 32;
                ldsm4(fAh[mi], st + 0 * TILE_B + ro + la);
                ldsm4(fAl[mi], st + 1 * TILE_B + ro + la);
            }
            {
                uint32_t fBh[2][4], fBl[2][4];
                #pragma unroll
                for (int nb = 0; nb < 2; nb++) {
                    uint32_t ro = (uint32_t)((wn * 32 + nb * 16) * SA * 2) + ks * 32;
                    ldsm4(fBh[nb], st + 2 * TILE_B + ro + lb);
                    ldsm4(fBl[nb], st + 3 * TILE_B + ro + lb);
                }
                #pragma unroll
                for (int mi = 0; mi < 2; mi++)
                    #pragma unroll
                    for (int ni = 0; ni < 4; ni++)
                        mma_bf16(accg[mi][ni], fAh[mi], &fBh[ni >> 1][(ni & 1) * 2]);
                #pragma unroll
                for (int mi = 0; mi < 2; mi++)
                    #pragma unroll
                    for (int ni = 0; ni < 4; ni++)
                        mma_bf16(accg[mi][ni], fAl[mi], &fBh[ni >> 1][(ni & 1) * 2]);
                #pragma unroll
                for (int mi = 0; mi < 2; mi++)
                    #pragma unroll
                    for (int ni = 0; ni < 4; ni++)
                        mma_bf16(accg[mi][ni], fAh[mi], &fBl[ni >> 1][(ni & 1) * 2]);
            }
            {
                uint32_t fBh[2][4], fBl[2][4];
                #pragma unroll
                for (int nb = 0; nb < 2; nb++) {
                    uint32_t ro = (uint32_t)((wn * 32 + nb * 16) * SA * 2) + ks * 32;
                    ldsm4(fBh[nb], st + 4 * TILE_B + ro + lb);
                    ldsm4(fBl[nb], st + 5 * TILE_B + ro + lb);
                }
                #pragma unroll
                for (int mi = 0; mi < 2; mi++)
                    #pragma unroll
                    for (int ni = 0; ni < 4; ni++)
                        mma_bf16(accu[mi][ni], fAh[mi], &fBh[ni >> 1][(ni & 1) * 2]);
                #pragma unroll
                for (int mi = 0; mi < 2; mi++)
                    #pragma unroll
                    for (int ni = 0; ni < 4; ni++)
                        mma_bf16(accu[mi][ni], fAl[mi], &fBh[ni >> 1][(ni & 1) * 2]);
                #pragma unroll
                for (int mi = 0; mi < 2; mi++)
                    #pragma unroll
                    for (int ni = 0; ni < 4; ni++)
                        mma_bf16(accu[mi][ni], fAh[mi], &fBl[ni >> 1][(ni & 1) * 2]);
            }
        }
    }

    #pragma unroll
    for (int mi = 0; mi < 2; mi++) {
        int p0 = row0 + wm * 32 + mi * 16 + g;
        #pragma unroll
        for (int half = 0; half < 2; half++) {
            int p = p0 + half * 8;
            if (p >= M) continue;
            float w = gather ? g_wt[e * TMAX + p] : 1.f;
            size_t rowo = (size_t)p * N;
            #pragma unroll
            for (int ni = 0; ni < 4; ni++) {
                int col = col0 + wn * 32 + ni * 8 + 2 * t4;
                float gv0 = accg[mi][ni][half * 2 + 0];
                float gv1 = accg[mi][ni][half * 2 + 1];
                float uv0 = accu[mi][ni][half * 2 + 0];
                float uv1 = accu[mi][ni][half * 2 + 1];
                float v0 = w * (gv0 / (1.f + expf(-gv0))) * uv0;
                float v1 = w * (gv1 / (1.f + expf(-gv1))) * uv1;
                __nv_bfloat162 h = __floats2bfloat162_rn(v0, v1);
                __nv_bfloat162 l = __floats2bfloat162_rn(v0 - __bfloat162float(h.x),
                                                         v1 - __bfloat162float(h.y));
                *(__nv_bfloat162*)(Ch + rowo + col) = h;
                *(__nv_bfloat162*)(Cl + rowo + col) = l;
            }
        }
    }
}

// ------- merged down GEMM, 512 threads, warp tile 32x32 ----------------------
__global__ __launch_bounds__(512, 1)
void k_dn_all(float* __restrict__ out, int T)
{
    const int z = blockIdx.z;
    int M, K, e = 0;
    bool scatter;
    const __nv_bfloat16 *Ah_g, *Al_g, *Bh, *Bl;
    if (z == 0) {
        scatter = false; M = T; K = DS;
        Ah_g = g_buf2H; Al_g = g_buf2L;
        Bh = g_WsdTh; Bl = g_WsdTl;
    } else {
        scatter = true; e = z - 1;
        M = g_cnt[e]; K = DD;
        Ah_g = g_bufH + (size_t)e * TMAX * DD;
        Al_g = g_bufL + (size_t)e * TMAX * DD;
        size_t ws = (size_t)e * HD * DD;
        Bh = g_WdTh + ws; Bl = g_WdTl + ws;
    }
    const int row0 = blockIdx.y * BM;
    if (row0 >= M) return;
    const int col0 = blockIdx.x * BN;

    extern __shared__ char dsm[];
    const uint32_t sb = smem_u32(dsm);

    const int tid = threadIdx.x;
    const int wid = tid >> 5, lane = tid & 31;
    const int wm = wid & 3, wn = wid >> 2;
    const int g = lane >> 2, t4 = lane & 3;

    size_t aoff, boff; uint32_t adst;
    {
        int r = tid >> 2, c16 = tid & 3;
        adst = r * (SA * 2) + c16 * 16;
        int gr = row0 + r;
        int grc = (gr < M) ? gr : (M - 1);
        aoff = (size_t)grc * K + c16 * 8;
        boff = (size_t)(col0 + r) * K + c16 * 8;
    }
    const int a_r = (lane & 7) + ((lane >> 3) & 1) * 8;
    const int a_c = ((lane >> 4) & 1) * 8;
    const int b_r = (lane & 7) + ((lane >> 4) & 1) * 8;
    const int b_c = ((lane >> 3) & 1) * 8;
    const uint32_t la = (uint32_t)(a_r * SA + a_c) * 2;
    const uint32_t lb = (uint32_t)(b_r * SA + b_c) * 2;

    float acc[2][4][4];
    #pragma unroll
    for (int mi = 0; mi < 2; mi++)
        #pragma unroll
        for (int ni = 0; ni < 4; ni++)
            #pragma unroll
            for (int q = 0; q < 4; q++) acc[mi][ni][q] = 0.f;

    const int NC = K / BK;
    #pragma unroll
    for (int pc = 0; pc < 3; pc++) {
        uint32_t st = sb + pc * STG_DN;
        size_t ko = (size_t)pc * BK;
        CP16(st + 0 * TILE_B + adst, Ah_g + aoff + ko);
        CP16(st + 1 * TILE_B + adst, Al_g + aoff + ko);
        CP16(st + 2 * TILE_B + adst, Bh + boff + ko);
        CP16(st + 3 * TILE_B + adst, Bl + boff + ko);
        CPCOMMIT();
    }

    int s_next = 3;
    for (int c = 0; c < NC; c++) {
        // pending at top: {c, c+1, c+2} -> wait_group 2 guarantees chunk c landed
        CPWAIT2();
        __syncthreads();
        {
            int nc3 = (c + 3 < NC) ? c + 3 : NC - 1;
            uint32_t st = sb + s_next * STG_DN;
            size_t ko = (size_t)nc3 * BK;
            CP16(st + 0 * TILE_B + adst, Ah_g + aoff + ko);
            CP16(st + 1 * TILE_B + adst, Al_g + aoff + ko);
            CP16(st + 2 * TILE_B + adst, Bh + boff + ko);
            CP16(st + 3 * TILE_B + adst, Bl + boff + ko);
            CPCOMMIT();
        }
        s_next = (s_next + 1) & 3;
        const uint32_t st = sb + (c & 3) * STG_DN;
        #pragma unroll
        for (int ks = 0; ks < 2; ks++) {
            uint32_t fAh[2][4], fAl[2][4], fBh[2][4], fBl[2][4];
            #pragma unroll
            for (int mi = 0; mi < 2; mi++) {
                uint32_t ro = (uint32_t)((wm * 32 + mi * 16) * SA * 2) + ks * 32;
                ldsm4(fAh[mi], st + 0 * TILE_B + ro + la);
                ldsm4(fAl[mi], st + 1 * TILE_B + ro + la);
            }
            #pragma unroll
            for (int nb = 0; nb < 2; nb++) {
                uint32_t ro = (uint32_t)((wn * 32 + nb * 16) * SA * 2) + ks * 32;
                ldsm4(fBh[nb], st + 2 * TILE_B + ro + lb);
                ldsm4(fBl[nb], st + 3 * TILE_B + ro + lb);
            }
            #pragma unroll
            for (int mi = 0; mi < 2; mi++)
                #pragma unroll
                for (int ni = 0; ni < 4; ni++)
                    mma_bf16(acc[mi][ni], fAh[mi], &fBh[ni >> 1][(ni & 1) * 2]);
            #pragma unroll
            for (int mi = 0; mi < 2; mi++)
                #pragma unroll
                for (int ni = 0; ni < 4; ni++)
                    mma_bf16(acc[mi][ni], fAl[mi], &fBh[ni >> 1][(ni & 1) * 2]);
            #pragma unroll
            for (int mi = 0; mi < 2; mi++)
                #pragma unroll
                for (int ni = 0; ni < 4; ni++)
                    mma_bf16(acc[mi][ni], fAh[mi], &fBl[ni >> 1][(ni & 1) * 2]);
        }
    }

    #pragma unroll
    for (int mi = 0; mi < 2; mi++) {
        int p0 = row0 + wm * 32 + mi * 16 + g;
        int p1 = p0 + 8;
        float* c0 = nullptr; float* c1 = nullptr;
        if (scatter) {
            if (p0 < M) c0 = g_routed + (size_t)g_slot[e * TMAX + p0] * HD;
            if (p1 < M) c1 = g_routed + (size_t)g_slot[e * TMAX + p1] * HD;
        } else {
            c0 = out + (size_t)p0 * HD;
            c1 = out + (size_t)p1 * HD;
        }
        #pragma unroll
        for (int ni = 0; ni < 4; ni++) {
            int col = col0 + wn * 32 + ni * 8 + 2 * t4;
            if (c0) *(float2*)(c0 + col) = make_float2(acc[mi][ni][0], acc[mi][ni][1]);
            if (c1) *(float2*)(c1 + col) = make_float2(acc[mi][ni][2], acc[mi][ni][3]);
        }
    }
}

// ---------------- final: out += routed slots; aux loss tail ------------------
__global__ void k_final(float* __restrict__ out, int n4, int T, int out_size) {
    if (blockIdx.x == 0 && threadIdx.x == 0) {
        float a = 0.f;
        for (int e = 0; e < NE; e++) { float m = g_psum[e] / (float)T; a += m * m; }
        a *= (float)NE;
        for (size_t i = (size_t)T * HD; i < (size_t)out_size; i++) out[i] = a;
    }
    const float4* r = (const float4*)g_routed;
    float4* o4 = (float4*)out;
    int i = blockIdx.x * blockDim.x + threadIdx.x;
    int stride = gridDim.x * blockDim.x;
    for (; i < n4; i += stride) {
        float4 a = o4[i], b = r[i], c = r[i + n4];
        a.x += b.x + c.x;
        a.y += b.y + c.y;
        a.z += b.z + c.z;
        a.w += b.w + c.w;
        o4[i] = a;
    }
}

// ---------------- launch -----------------------------------------------------
extern "C" void kernel_launch(void* const* d_in, const int* in_sizes, int n_in,
                              void* d_out, int out_size) {
    const float* x   = (const float*)d_in[0];
    const float* Wr  = (const float*)d_in[1];
    const float* Wg  = (const float*)d_in[2];
    const float* Wu  = (const float*)d_in[3];
    const float* Wd  = (const float*)d_in[4];
    const float* Wsg = (const float*)d_in[5];
    const float* Wsu = (const float*)d_in[6];
    const float* Wsd = (const float*)d_in[7];
    float* out = (float*)d_out;
    const int T = in_sizes[0] / HD;   // 8192

    __nv_bfloat16 *xh, *xl;
    cudaGetSymbolAddress((void**)&xh, g_xh);
    cudaGetSymbolAddress((void**)&xl, g_xl);

    cudaFuncSetAttribute(k_gu_all, cudaFuncAttributeMaxDynamicSharedMemorySize, SMEM_GU);
    cudaFuncSetAttribute(k_dn_all, cudaFuncAttributeMaxDynamicSharedMemorySize, SMEM_DN);

    // 0: split x (+ zero routing counters)
    k_split_x<<<2048, 256>>>(x, T * HD / 4);
    // 1: all weight transposes+splits
    k_tsplit_all<<<dim3(32, 32, 27), dim3(32, 8)>>>(Wsg, Wsu, Wsd, Wg, Wu, Wd);
    // 2: router
    k_router<<<T / 8, 256>>>(x, Wr, T);
    // 3: merged gate+up (+swiglu)
    k_gu_all<<<dim3(DS / BN, T / BM, NE + 1), 512, SMEM_GU>>>(xh, xl, T);
    // 4: merged down
    k_dn_all<<<dim3(HD / BN, T / BM, NE + 1), 512, SMEM_DN>>>(out, T);
    // 5: combine + aux loss
    k_final<<<2048, 256>>>(out, (T * HD) / 4, T, out_size);
}

// round 9
// speedup vs baseline: 3.3997x; 1.1976x over previous
#include <cuda_runtime.h>
#include <cuda_bf16.h>
#include <cuda_fp16.h>
#include <math.h>
#include <stdint.h>

#define NE   8
#define HD   1024
#define DD   512
#define DS   1024
#define TMAX 8192

#define BM 128
#define BN 128
#define BK 32
#define SA 40                 // 16-bit elems per smem row (32 + 8 pad)
#define TILE_B (128 * SA * 2) // 10240 bytes per 128x32 16-bit tile
#define STG_GU (4 * TILE_B)   // Ah,Al,Bg,Bu (fp16)
#define STG_DN (4 * TILE_B)   // Ah,Al,Bh,Bl (bf16)
#define SMEM_GU (4 * STG_GU)  // 4-stage, 163840 B
#define SMEM_DN (4 * STG_DN)  // 4-stage, 163840 B

// ---------------- scratch (static device globals; no allocations) ------------
__device__ __align__(16) __half g_xh[(size_t)TMAX * HD];
__device__ __align__(16) __half g_xl[(size_t)TMAX * HD];
__device__ __align__(16) __nv_bfloat16 g_bufH[(size_t)NE * TMAX * DD];
__device__ __align__(16) __nv_bfloat16 g_bufL[(size_t)NE * TMAX * DD];
__device__ __align__(16) __nv_bfloat16 g_buf2H[(size_t)TMAX * DS];
__device__ __align__(16) __nv_bfloat16 g_buf2L[(size_t)TMAX * DS];
__device__ __align__(16) float g_routed[(size_t)2 * TMAX * HD];
__device__ __align__(16) __half g_WsgT[(size_t)DS * HD];          // fp16 single
__device__ __align__(16) __half g_WsuT[(size_t)DS * HD];
__device__ __align__(16) __half g_WgT[(size_t)NE * DD * HD];
__device__ __align__(16) __half g_WuT[(size_t)NE * DD * HD];
__device__ __align__(16) __nv_bfloat16 g_WsdTh[(size_t)HD * DS];  // bf16 hi/lo
__device__ __align__(16) __nv_bfloat16 g_WsdTl[(size_t)HD * DS];
__device__ __align__(16) __nv_bfloat16 g_WdTh[(size_t)NE * HD * DD];
__device__ __align__(16) __nv_bfloat16 g_WdTl[(size_t)NE * HD * DD];
__device__ int   g_cnt[NE];
__device__ int   g_tok[NE * TMAX];
__device__ int   g_slot[NE * TMAX];
__device__ float g_wt[NE * TMAX];
__device__ float g_psum[NE];

// ---------------- asm helpers ------------------------------------------------
__device__ __forceinline__ uint32_t smem_u32(const void* p) {
    uint32_t a;
    asm("{ .reg .u64 t; cvta.to.shared.u64 t, %1; cvt.u32.u64 %0, t; }" : "=r"(a) : "l"(p));
    return a;
}
#define CP16(dst, src) \
    asm volatile("cp.async.cg.shared.global [%0], [%1], 16;" :: "r"(dst), "l"(src) : "memory")
#define CPCOMMIT() asm volatile("cp.async.commit_group;" ::: "memory")
#define CPWAIT2()  asm volatile("cp.async.wait_group 2;" ::: "memory")

__device__ __forceinline__ void ldsm4(uint32_t* r, uint32_t addr) {
    asm volatile("ldmatrix.sync.aligned.m8n8.x4.shared.b16 {%0,%1,%2,%3}, [%4];"
        : "=r"(r[0]), "=r"(r[1]), "=r"(r[2]), "=r"(r[3]) : "r"(addr));
}
__device__ __forceinline__ void mma_bf16(float* c, const uint32_t* a, const uint32_t* b) {
    asm volatile(
        "mma.sync.aligned.m16n8k16.row.col.f32.bf16.bf16.f32 "
        "{%0,%1,%2,%3}, {%4,%5,%6,%7}, {%8,%9}, {%0,%1,%2,%3};\n"
        : "+f"(c[0]), "+f"(c[1]), "+f"(c[2]), "+f"(c[3])
        : "r"(a[0]), "r"(a[1]), "r"(a[2]), "r"(a[3]), "r"(b[0]), "r"(b[1]));
}
__device__ __forceinline__ void mma_f16(float* c, const uint32_t* a, const uint32_t* b) {
    asm volatile(
        "mma.sync.aligned.m16n8k16.row.col.f32.f16.f16.f32 "
        "{%0,%1,%2,%3}, {%4,%5,%6,%7}, {%8,%9}, {%0,%1,%2,%3};\n"
        : "+f"(c[0]), "+f"(c[1]), "+f"(c[2]), "+f"(c[3])
        : "r"(a[0]), "r"(a[1]), "r"(a[2]), "r"(a[3]), "r"(b[0]), "r"(b[1]));
}

// ---------------- split x to fp16 hi/lo (+ zero counters) --------------------
__global__ void k_split_x(const float* __restrict__ x, int n4) {
    if (blockIdx.x == 0 && threadIdx.x < NE) {
        g_cnt[threadIdx.x] = 0; g_psum[threadIdx.x] = 0.f;
    }
    int i = blockIdx.x * blockDim.x + threadIdx.x;
    int stride = gridDim.x * blockDim.x;
    for (; i < n4; i += stride) {
        float4 v = ((const float4*)x)[i];
        __half2 h01 = __floats2half2_rn(v.x, v.y);
        __half2 h23 = __floats2half2_rn(v.z, v.w);
        __half2 l01 = __floats2half2_rn(v.x - __half2float(h01.x),
                                        v.y - __half2float(h01.y));
        __half2 l23 = __floats2half2_rn(v.z - __half2float(h23.x),
                                        v.w - __half2float(h23.y));
        ((uint2*)g_xh)[i] = make_uint2(*(uint32_t*)&h01, *(uint32_t*)&h23);
        ((uint2*)g_xl)[i] = make_uint2(*(uint32_t*)&l01, *(uint32_t*)&l23);
    }
}

// -------- one launch: transpose all weights; gate/up->fp16, down->bf16 hi/lo -
__global__ void k_tsplit_all(const float* __restrict__ Wsg, const float* __restrict__ Wsu,
                             const float* __restrict__ Wsd, const float* __restrict__ Wg,
                             const float* __restrict__ Wu,  const float* __restrict__ Wd) {
    const int z = blockIdx.z;
    const float* in; int R, C;
    __half* of16 = nullptr; __nv_bfloat16 *oh = nullptr, *ol = nullptr;
    if (z == 0)      { in = Wsg; of16 = g_WsgT; R = HD; C = DS; }
    else if (z == 1) { in = Wsu; of16 = g_WsuT; R = HD; C = DS; }
    else if (z == 2) { in = Wsd; oh = g_WsdTh; ol = g_WsdTl; R = DS; C = HD; }
    else if (z < 11) { size_t m = (size_t)(z - 3) * HD * DD;
                       in = Wg + m; of16 = g_WgT + m; R = HD; C = DD; }
    else if (z < 19) { size_t m = (size_t)(z - 11) * HD * DD;
                       in = Wu + m; of16 = g_WuT + m; R = HD; C = DD; }
    else             { size_t m = (size_t)(z - 19) * DD * HD;
                       in = Wd + m; oh = g_WdTh + m; ol = g_WdTl + m; R = DD; C = HD; }
    int c0 = blockIdx.x * 32, r0 = blockIdx.y * 32;
    if (c0 >= C || r0 >= R) return;
    __shared__ float t[32][33];
    int tx = threadIdx.x, ty = threadIdx.y;
    #pragma unroll
    for (int j = 0; j < 32; j += 8)
        t[ty + j][tx] = in[(size_t)(r0 + ty + j) * C + c0 + tx];
    __syncthreads();
    #pragma unroll
    for (int j = 0; j < 32; j += 8) {
        float v = t[tx][ty + j];
        size_t o = (size_t)(c0 + ty + j) * R + r0 + tx;
        if (of16) {
            of16[o] = __float2half_rn(v);
        } else {
            __nv_bfloat16 h = __float2bfloat16_rn(v);
            oh[o] = h;
            ol[o] = __float2bfloat16_rn(v - __bfloat162float(h));
        }
    }
}

// ---------------- router ----------------------------------------------------
__global__ void k_router(const float* __restrict__ x, const float* __restrict__ Wr, int T) {
    __shared__ float s_p[NE];
    if (threadIdx.x < NE) s_p[threadIdx.x] = 0.f;
    __syncthreads();
    int warp = blockIdx.x * (blockDim.x >> 5) + (threadIdx.x >> 5);
    int lane = threadIdx.x & 31;
    if (warp < T) {
        int t = warp;
        const float* xr = x + (size_t)t * HD;
        float acc[NE];
        #pragma unroll
        for (int e = 0; e < NE; e++) acc[e] = 0.f;
        for (int i = lane; i < HD; i += 32) {
            float xv = xr[i];
            const float* w = Wr + (size_t)i * NE;
            #pragma unroll
            for (int e = 0; e < NE; e++) acc[e] += xv * w[e];
        }
        #pragma unroll
        for (int e = 0; e < NE; e++) {
            #pragma unroll
            for (int o = 16; o > 0; o >>= 1)
                acc[e] += __shfl_xor_sync(0xffffffffu, acc[e], o);
        }
        if (lane == 0) {
            float mx = acc[0];
            #pragma unroll
            for (int e = 1; e < NE; e++) mx = fmaxf(mx, acc[e]);
            float p[NE]; float s = 0.f;
            #pragma unroll
            for (int e = 0; e < NE; e++) { p[e] = expf(acc[e] - mx); s += p[e]; }
            float inv = 1.f / s;
            #pragma unroll
            for (int e = 0; e < NE; e++) p[e] *= inv;
            int i0 = 0;
            #pragma unroll
            for (int e = 1; e < NE; e++) if (p[e] > p[i0]) i0 = e;
            int i1 = (i0 == 0) ? 1 : 0;
            #pragma unroll
            for (int e = 0; e < NE; e++) if (e != i0 && p[e] > p[i1]) i1 = e;
            float w0 = p[i0], w1 = p[i1];
            float rn = 1.f / (w0 + w1);
            w0 *= rn; w1 *= rn;
            int pos0 = atomicAdd(&g_cnt[i0], 1);
            g_tok[i0 * TMAX + pos0]  = t;
            g_slot[i0 * TMAX + pos0] = t;
            g_wt[i0 * TMAX + pos0]   = w0;
            int pos1 = atomicAdd(&g_cnt[i1], 1);
            g_tok[i1 * TMAX + pos1]  = t;
            g_slot[i1 * TMAX + pos1] = T + t;
            g_wt[i1 * TMAX + pos1]   = w1;
            #pragma unroll
            for (int e = 0; e < NE; e++) atomicAdd(&s_p[e], p[e]);
        }
    }
    __syncthreads();
    if (threadIdx.x < NE) atomicAdd(&g_psum[threadIdx.x], s_p[threadIdx.x]);
}

// ------- merged gate+up GEMM + SwiGLU, fp16 2-pass, 512 thr, warp 32x32 ------
__global__ __launch_bounds__(512, 1)
void k_gu_all(const __half* __restrict__ Ah_g, const __half* __restrict__ Al_g, int T)
{
    const int z = blockIdx.z;
    int M, N, e = 0;
    bool gather;
    const __half *Bg, *Bu;
    __nv_bfloat16 *Ch, *Cl;
    if (z == 0) {
        gather = false; M = T; N = DS;
        Bg = g_WsgT; Bu = g_WsuT;
        Ch = g_buf2H; Cl = g_buf2L;
    } else {
        gather = true; e = z - 1;
        if (blockIdx.x >= DD / BN) return;
        M = g_cnt[e]; N = DD;
        size_t ws = (size_t)e * DD * HD;
        Bg = g_WgT + ws; Bu = g_WuT + ws;
        Ch = g_bufH + (size_t)e * TMAX * DD; Cl = g_bufL + (size_t)e * TMAX * DD;
    }
    const int row0 = blockIdx.y * BM;
    if (row0 >= M) return;
    const int col0 = blockIdx.x * BN;
    const int K = HD;

    extern __shared__ char dsm[];
    const uint32_t sb = smem_u32(dsm);

    const int tid = threadIdx.x;
    const int wid = tid >> 5, lane = tid & 31;
    const int wm = wid & 3, wn = wid >> 2;
    const int g = lane >> 2, t4 = lane & 3;

    size_t aoff, boff; uint32_t adst;
    {
        int r = tid >> 2, c16 = tid & 3;
        adst = r * (SA * 2) + c16 * 16;
        int gr = row0 + r;
        int grc = (gr < M) ? gr : (M - 1);
        if (gather) aoff = (size_t)g_tok[e * TMAX + grc] * K + c16 * 8;
        else        aoff = (size_t)grc * K + c16 * 8;
        boff = (size_t)(col0 + r) * K + c16 * 8;
    }

    const int a_r = (lane & 7) + ((lane >> 3) & 1) * 8;
    const int a_c = ((lane >> 4) & 1) * 8;
    const int b_r = (lane & 7) + ((lane >> 4) & 1) * 8;
    const int b_c = ((lane >> 3) & 1) * 8;
    const uint32_t la = (uint32_t)(a_r * SA + a_c) * 2;
    const uint32_t lb = (uint32_t)(b_r * SA + b_c) * 2;

    float accg[2][4][4], accu[2][4][4];
    #pragma unroll
    for (int mi = 0; mi < 2; mi++)
        #pragma unroll
        for (int ni = 0; ni < 4; ni++)
            #pragma unroll
            for (int q = 0; q < 4; q++) { accg[mi][ni][q] = 0.f; accu[mi][ni][q] = 0.f; }

    const int NC = K / BK;   // 32
    #pragma unroll
    for (int pc = 0; pc < 3; pc++) {
        uint32_t st = sb + pc * STG_GU;
        size_t ko = (size_t)pc * BK;
        CP16(st + 0 * TILE_B + adst, Ah_g + aoff + ko);
        CP16(st + 1 * TILE_B + adst, Al_g + aoff + ko);
        CP16(st + 2 * TILE_B + adst, Bg + boff + ko);
        CP16(st + 3 * TILE_B + adst, Bu + boff + ko);
        CPCOMMIT();
    }

    int s_next = 3;
    for (int c = 0; c < NC; c++) {
        // pending at top: {c, c+1, c+2} -> wait_group 2 guarantees chunk c landed
        CPWAIT2();
        __syncthreads();
        {
            int nc3 = (c + 3 < NC) ? c + 3 : NC - 1;
            uint32_t st = sb + s_next * STG_GU;
            size_t ko = (size_t)nc3 * BK;
            CP16(st + 0 * TILE_B + adst, Ah_g + aoff + ko);
            CP16(st + 1 * TILE_B + adst, Al_g + aoff + ko);
            CP16(st + 2 * TILE_B + adst, Bg + boff + ko);
            CP16(st + 3 * TILE_B + adst, Bu + boff + ko);
            CPCOMMIT();
        }
        s_next = (s_next + 1) & 3;
        const uint32_t st = sb + (c & 3) * STG_GU;
        #pragma unroll
        for (int ks = 0; ks < 2; ks++) {
            uint32_t fAh[2][4], fAl[2][4], fBg[2][4], fBu[2][4];
            #pragma unroll
            for (int mi = 0; mi < 2; mi++) {
                uint32_t ro = (uint32_t)((wm * 32 + mi * 16) * SA * 2) + ks * 32;
                ldsm4(fAh[mi], st + 0 * TILE_B + ro + la);
                ldsm4(fAl[mi], st + 1 * TILE_B + ro + la);
            }
            #pragma unroll
            for (int nb = 0; nb < 2; nb++) {
                uint32_t ro = (uint32_t)((wn * 32 + nb * 16) * SA * 2) + ks * 32;
                ldsm4(fBg[nb], st + 2 * TILE_B + ro + lb);
                ldsm4(fBu[nb], st + 3 * TILE_B + ro + lb);
            }
            // 2-pass: (Ah + Al) x Bg / Bu
            #pragma unroll
            for (int mi = 0; mi < 2; mi++)
                #pragma unroll
                for (int ni = 0; ni < 4; ni++)
                    mma_f16(accg[mi][ni], fAh[mi], &fBg[ni >> 1][(ni & 1) * 2]);
            #pragma unroll
            for (int mi = 0; mi < 2; mi++)
                #pragma unroll
                for (int ni = 0; ni < 4; ni++)
                    mma_f16(accg[mi][ni], fAl[mi], &fBg[ni >> 1][(ni & 1) * 2]);
            #pragma unroll
            for (int mi = 0; mi < 2; mi++)
                #pragma unroll
                for (int ni = 0; ni < 4; ni++)
                    mma_f16(accu[mi][ni], fAh[mi], &fBu[ni >> 1][(ni & 1) * 2]);
            #pragma unroll
            for (int mi = 0; mi < 2; mi++)
                #pragma unroll
                for (int ni = 0; ni < 4; ni++)
                    mma_f16(accu[mi][ni], fAl[mi], &fBu[ni >> 1][(ni & 1) * 2]);
        }
    }

    #pragma unroll
    for (int mi = 0; mi < 2; mi++) {
        int p0 = row0 + wm * 32 + mi * 16 + g;
        #pragma unroll
        for (int half = 0; half < 2; half++) {
            int p = p0 + half * 8;
            if (p >= M) continue;
            float w = gather ? g_wt[e * TMAX + p] : 1.f;
            size_t rowo = (size_t)p * N;
            #pragma unroll
            for (int ni = 0; ni < 4; ni++) {
                int col = col0 + wn * 32 + ni * 8 + 2 * t4;
                float gv0 = accg[mi][ni][half * 2 + 0];
                float gv1 = accg[mi][ni][half * 2 + 1];
                float uv0 = accu[mi][ni][half * 2 + 0];
                float uv1 = accu[mi][ni][half * 2 + 1];
                float v0 = w * (gv0 / (1.f + expf(-gv0))) * uv0;
                float v1 = w * (gv1 / (1.f + expf(-gv1))) * uv1;
                __nv_bfloat162 h = __floats2bfloat162_rn(v0, v1);
                __nv_bfloat162 l = __floats2bfloat162_rn(v0 - __bfloat162float(h.x),
                                                         v1 - __bfloat162float(h.y));
                *(__nv_bfloat162*)(Ch + rowo + col) = h;
                *(__nv_bfloat162*)(Cl + rowo + col) = l;
            }
        }
    }
}

// ------- merged down GEMM, bf16 3-pass (unchanged), 512 thr ------------------
__global__ __launch_bounds__(512, 1)
void k_dn_all(float* __restrict__ out, int T)
{
    const int z = blockIdx.z;
    int M, K, e = 0;
    bool scatter;
    const __nv_bfloat16 *Ah_g, *Al_g, *Bh, *Bl;
    if (z == 0) {
        scatter = false; M = T; K = DS;
        Ah_g = g_buf2H; Al_g = g_buf2L;
        Bh = g_WsdTh; Bl = g_WsdTl;
    } else {
        scatter = true; e = z - 1;
        M = g_cnt[e]; K = DD;
        Ah_g = g_bufH + (size_t)e * TMAX * DD;
        Al_g = g_bufL + (size_t)e * TMAX * DD;
        size_t ws = (size_t)e * HD * DD;
        Bh = g_WdTh + ws; Bl = g_WdTl + ws;
    }
    const int row0 = blockIdx.y * BM;
    if (row0 >= M) return;
    const int col0 = blockIdx.x * BN;

    extern __shared__ char dsm[];
    const uint32_t sb = smem_u32(dsm);

    const int tid = threadIdx.x;
    const int wid = tid >> 5, lane = tid & 31;
    const int wm = wid & 3, wn = wid >> 2;
    const int g = lane >> 2, t4 = lane & 3;

    size_t aoff, boff; uint32_t adst;
    {
        int r = tid >> 2, c16 = tid & 3;
        adst = r * (SA * 2) + c16 * 16;
        int gr = row0 + r;
        int grc = (gr < M) ? gr : (M - 1);
        aoff = (size_t)grc * K + c16 * 8;
        boff = (size_t)(col0 + r) * K + c16 * 8;
    }
    const int a_r = (lane & 7) + ((lane >> 3) & 1) * 8;
    const int a_c = ((lane >> 4) & 1) * 8;
    const int b_r = (lane & 7) + ((lane >> 4) & 1) * 8;
    const int b_c = ((lane >> 3) & 1) * 8;
    const uint32_t la = (uint32_t)(a_r * SA + a_c) * 2;
    const uint32_t lb = (uint32_t)(b_r * SA + b_c) * 2;

    float acc[2][4][4];
    #pragma unroll
    for (int mi = 0; mi < 2; mi++)
        #pragma unroll
        for (int ni = 0; ni < 4; ni++)
            #pragma unroll
            for (int q = 0; q < 4; q++) acc[mi][ni][q] = 0.f;

    const int NC = K / BK;
    #pragma unroll
    for (int pc = 0; pc < 3; pc++) {
        uint32_t st = sb + pc * STG_DN;
        size_t ko = (size_t)pc * BK;
        CP16(st + 0 * TILE_B + adst, Ah_g + aoff + ko);
        CP16(st + 1 * TILE_B + adst, Al_g + aoff + ko);
        CP16(st + 2 * TILE_B + adst, Bh + boff + ko);
        CP16(st + 3 * TILE_B + adst, Bl + boff + ko);
        CPCOMMIT();
    }

    int s_next = 3;
    for (int c = 0; c < NC; c++) {
        CPWAIT2();
        __syncthreads();
        {
            int nc3 = (c + 3 < NC) ? c + 3 : NC - 1;
            uint32_t st = sb + s_next * STG_DN;
            size_t ko = (size_t)nc3 * BK;
            CP16(st + 0 * TILE_B + adst, Ah_g + aoff + ko);
            CP16(st + 1 * TILE_B + adst, Al_g + aoff + ko);
            CP16(st + 2 * TILE_B + adst, Bh + boff + ko);
            CP16(st + 3 * TILE_B + adst, Bl + boff + ko);
            CPCOMMIT();
        }
        s_next = (s_next + 1) & 3;
        const uint32_t st = sb + (c & 3) * STG_DN;
        #pragma unroll
        for (int ks = 0; ks < 2; ks++) {
            uint32_t fAh[2][4], fAl[2][4], fBh[2][4], fBl[2][4];
            #pragma unroll
            for (int mi = 0; mi < 2; mi++) {
                uint32_t ro = (uint32_t)((wm * 32 + mi * 16) * SA * 2) + ks * 32;
                ldsm4(fAh[mi], st + 0 * TILE_B + ro + la);
                ldsm4(fAl[mi], st + 1 * TILE_B + ro + la);
            }
            #pragma unroll
            for (int nb = 0; nb < 2; nb++) {
                uint32_t ro = (uint32_t)((wn * 32 + nb * 16) * SA * 2) + ks * 32;
                ldsm4(fBh[nb], st + 2 * TILE_B + ro + lb);
                ldsm4(fBl[nb], st + 3 * TILE_B + ro + lb);
            }
            #pragma unroll
            for (int mi = 0; mi < 2; mi++)
                #pragma unroll
                for (int ni = 0; ni < 4; ni++)
                    mma_bf16(acc[mi][ni], fAh[mi], &fBh[ni >> 1][(ni & 1) * 2]);
            #pragma unroll
            for (int mi = 0; mi < 2; mi++)
                #pragma unroll
                for (int ni = 0; ni < 4; ni++)
                    mma_bf16(acc[mi][ni], fAl[mi], &fBh[ni >> 1][(ni & 1) * 2]);
            #pragma unroll
            for (int mi = 0; mi < 2; mi++)
                #pragma unroll
                for (int ni = 0; ni < 4; ni++)
                    mma_bf16(acc[mi][ni], fAh[mi], &fBl[ni >> 1][(ni & 1) * 2]);
        }
    }

    #pragma unroll
    for (int mi = 0; mi < 2; mi++) {
        int p0 = row0 + wm * 32 + mi * 16 + g;
        int p1 = p0 + 8;
        float* c0 = nullptr; float* c1 = nullptr;
        if (scatter) {
            if (p0 < M) c0 = g_routed + (size_t)g_slot[e * TMAX + p0] * HD;
            if (p1 < M) c1 = g_routed + (size_t)g_slot[e * TMAX + p1] * HD;
        } else {
            c0 = out + (size_t)p0 * HD;
            c1 = out + (size_t)p1 * HD;
        }
        #pragma unroll
        for (int ni = 0; ni < 4; ni++) {
            int col = col0 + wn * 32 + ni * 8 + 2 * t4;
            if (c0) *(float2*)(c0 + col) = make_float2(acc[mi][ni][0], acc[mi][ni][1]);
            if (c1) *(float2*)(c1 + col) = make_float2(acc[mi][ni][2], acc[mi][ni][3]);
        }
    }
}

// ---------------- final: out += routed slots; aux loss tail ------------------
__global__ void k_final(float* __restrict__ out, int n4, int T, int out_size) {
    if (blockIdx.x == 0 && threadIdx.x == 0) {
        float a = 0.f;
        for (int e = 0; e < NE; e++) { float m = g_psum[e] / (float)T; a += m * m; }
        a *= (float)NE;
        for (size_t i = (size_t)T * HD; i < (size_t)out_size; i++) out[i] = a;
    }
    const float4* r = (const float4*)g_routed;
    float4* o4 = (float4*)out;
    int i = blockIdx.x * blockDim.x + threadIdx.x;
    int stride = gridDim.x * blockDim.x;
    for (; i < n4; i += stride) {
        float4 a = o4[i], b = r[i], c = r[i + n4];
        a.x += b.x + c.x;
        a.y += b.y + c.y;
        a.z += b.z + c.z;
        a.w += b.w + c.w;
        o4[i] = a;
    }
}

// ---------------- launch -----------------------------------------------------
extern "C" void kernel_launch(void* const* d_in, const int* in_sizes, int n_in,
                              void* d_out, int out_size) {
    const float* x   = (const float*)d_in[0];
    const float* Wr  = (const float*)d_in[1];
    const float* Wg  = (const float*)d_in[2];
    const float* Wu  = (const float*)d_in[3];
    const float* Wd  = (const float*)d_in[4];
    const float* Wsg = (const float*)d_in[5];
    const float* Wsu = (const float*)d_in[6];
    const float* Wsd = (const float*)d_in[7];
    float* out = (float*)d_out;
    const int T = in_sizes[0] / HD;   // 8192

    __half *xh, *xl;
    cudaGetSymbolAddress((void**)&xh, g_xh);
    cudaGetSymbolAddress((void**)&xl, g_xl);

    cudaFuncSetAttribute(k_gu_all, cudaFuncAttributeMaxDynamicSharedMemorySize, SMEM_GU);
    cudaFuncSetAttribute(k_dn_all, cudaFuncAttributeMaxDynamicSharedMemorySize, SMEM_DN);

    // 0: split x (+ zero routing counters)
    k_split_x<<<2048, 256>>>(x, T * HD / 4);
    // 1: all weight transposes (+fp16/bf16 split)
    k_tsplit_all<<<dim3(32, 32, 27), dim3(32, 8)>>>(Wsg, Wsu, Wsd, Wg, Wu, Wd);
    // 2: router
    k_router<<<T / 8, 256>>>(x, Wr, T);
    // 3: merged gate+up (+swiglu), fp16 2-pass
    k_gu_all<<<dim3(DS / BN, T / BM, NE + 1), 512, SMEM_GU>>>(xh, xl, T);
    // 4: merged down, bf16 3-pass
    k_dn_all<<<dim3(HD / BN, T / BM, NE + 1), 512, SMEM_DN>>>(out, T);
    // 5: combine + aux loss
    k_final<<<2048, 256>>>(out, (T * HD) / 4, T, out_size);
}

// round 10
// speedup vs baseline: 3.8656x; 1.1371x over previous
#include <cuda_runtime.h>
#include <cuda_bf16.h>
#include <cuda_fp16.h>
#include <math.h>
#include <stdint.h>

#define NE   8
#define HD   1024
#define DD   512
#define DS   1024
#define TMAX 8192

#define BM 128
#define BN 128
#define BK 32
#define SA 40                 // 16-bit elems per smem row (32 + 8 pad)
#define TILE_B (128 * SA * 2) // 10240 bytes per 128x32 16-bit tile
#define STG_GU (4 * TILE_B)   // Ah,Al,Bg,Bu
#define STG_DN (3 * TILE_B)   // Ah,Al,B
#define SMEM_GU (4 * STG_GU)  // 4-stage, 163840 B
#define SMEM_DN (4 * STG_DN)  // 4-stage, 122880 B

// ---------------- scratch (static device globals; no allocations) ------------
__device__ __align__(16) __half g_xh[(size_t)TMAX * HD];
__device__ __align__(16) __half g_xl[(size_t)TMAX * HD];
__device__ __align__(16) __half g_bufH[(size_t)NE * TMAX * DD];   // routed gu out (fp16 hi)
__device__ __align__(16) __half g_bufL[(size_t)NE * TMAX * DD];   // (fp16 lo)
__device__ __align__(16) __half g_buf2H[(size_t)TMAX * DS];       // shared gu out
__device__ __align__(16) __half g_buf2L[(size_t)TMAX * DS];
__device__ __align__(16) float g_routed[(size_t)2 * TMAX * HD];
__device__ __align__(16) __half g_WsgT[(size_t)DS * HD];
__device__ __align__(16) __half g_WsuT[(size_t)DS * HD];
__device__ __align__(16) __half g_WsdT[(size_t)HD * DS];
__device__ __align__(16) __half g_WgT[(size_t)NE * DD * HD];
__device__ __align__(16) __half g_WuT[(size_t)NE * DD * HD];
__device__ __align__(16) __half g_WdT[(size_t)NE * HD * DD];
__device__ int   g_cnt[NE];
__device__ int   g_tok[NE * TMAX];
__device__ int   g_slot[NE * TMAX];
__device__ float g_wt[NE * TMAX];
__device__ float g_psum[NE];

// ---------------- asm helpers ------------------------------------------------
__device__ __forceinline__ uint32_t smem_u32(const void* p) {
    uint32_t a;
    asm("{ .reg .u64 t; cvta.to.shared.u64 t, %1; cvt.u32.u64 %0, t; }" : "=r"(a) : "l"(p));
    return a;
}
#define CP16(dst, src) \
    asm volatile("cp.async.cg.shared.global [%0], [%1], 16;" :: "r"(dst), "l"(src) : "memory")
#define CPCOMMIT() asm volatile("cp.async.commit_group;" ::: "memory")
#define CPWAIT2()  asm volatile("cp.async.wait_group 2;" ::: "memory")

__device__ __forceinline__ void ldsm4(uint32_t* r, uint32_t addr) {
    asm volatile("ldmatrix.sync.aligned.m8n8.x4.shared.b16 {%0,%1,%2,%3}, [%4];"
        : "=r"(r[0]), "=r"(r[1]), "=r"(r[2]), "=r"(r[3]) : "r"(addr));
}
__device__ __forceinline__ void mma_f16(float* c, const uint32_t* a, const uint32_t* b) {
    asm volatile(
        "mma.sync.aligned.m16n8k16.row.col.f32.f16.f16.f32 "
        "{%0,%1,%2,%3}, {%4,%5,%6,%7}, {%8,%9}, {%0,%1,%2,%3};\n"
        : "+f"(c[0]), "+f"(c[1]), "+f"(c[2]), "+f"(c[3])
        : "r"(a[0]), "r"(a[1]), "r"(a[2]), "r"(a[3]), "r"(b[0]), "r"(b[1]));
}

// ---------------- split x to fp16 hi/lo (+ zero counters) --------------------
__global__ void k_split_x(const float* __restrict__ x, int n4) {
    if (blockIdx.x == 0 && threadIdx.x < NE) {
        g_cnt[threadIdx.x] = 0; g_psum[threadIdx.x] = 0.f;
    }
    int i = blockIdx.x * blockDim.x + threadIdx.x;
    int stride = gridDim.x * blockDim.x;
    for (; i < n4; i += stride) {
        float4 v = ((const float4*)x)[i];
        __half2 h01 = __floats2half2_rn(v.x, v.y);
        __half2 h23 = __floats2half2_rn(v.z, v.w);
        __half2 l01 = __floats2half2_rn(v.x - __half2float(h01.x),
                                        v.y - __half2float(h01.y));
        __half2 l23 = __floats2half2_rn(v.z - __half2float(h23.x),
                                        v.w - __half2float(h23.y));
        ((uint2*)g_xh)[i] = make_uint2(*(uint32_t*)&h01, *(uint32_t*)&h23);
        ((uint2*)g_xl)[i] = make_uint2(*(uint32_t*)&l01, *(uint32_t*)&l23);
    }
}

// -------- one launch: transpose all 27 weight matrices to fp16 ---------------
__global__ void k_tsplit_all(const float* __restrict__ Wsg, const float* __restrict__ Wsu,
                             const float* __restrict__ Wsd, const float* __restrict__ Wg,
                             const float* __restrict__ Wu,  const float* __restrict__ Wd) {
    const int z = blockIdx.z;
    const float* in; __half* of16; int R, C;
    if (z == 0)      { in = Wsg; of16 = g_WsgT; R = HD; C = DS; }
    else if (z == 1) { in = Wsu; of16 = g_WsuT; R = HD; C = DS; }
    else if (z == 2) { in = Wsd; of16 = g_WsdT; R = DS; C = HD; }
    else if (z < 11) { size_t m = (size_t)(z - 3) * HD * DD;
                       in = Wg + m; of16 = g_WgT + m; R = HD; C = DD; }
    else if (z < 19) { size_t m = (size_t)(z - 11) * HD * DD;
                       in = Wu + m; of16 = g_WuT + m; R = HD; C = DD; }
    else             { size_t m = (size_t)(z - 19) * DD * HD;
                       in = Wd + m; of16 = g_WdT + m; R = DD; C = HD; }
    int c0 = blockIdx.x * 32, r0 = blockIdx.y * 32;
    if (c0 >= C || r0 >= R) return;
    __shared__ float t[32][33];
    int tx = threadIdx.x, ty = threadIdx.y;
    #pragma unroll
    for (int j = 0; j < 32; j += 8)
        t[ty + j][tx] = in[(size_t)(r0 + ty + j) * C + c0 + tx];
    __syncthreads();
    #pragma unroll
    for (int j = 0; j < 32; j += 8)
        of16[(size_t)(c0 + ty + j) * R + r0 + tx] = __float2half_rn(t[tx][ty + j]);
}

// ---------------- router ----------------------------------------------------
__global__ void k_router(const float* __restrict__ x, const float* __restrict__ Wr, int T) {
    __shared__ float s_p[NE];
    if (threadIdx.x < NE) s_p[threadIdx.x] = 0.f;
    __syncthreads();
    int warp = blockIdx.x * (blockDim.x >> 5) + (threadIdx.x >> 5);
    int lane = threadIdx.x & 31;
    if (warp < T) {
        int t = warp;
        const float* xr = x + (size_t)t * HD;
        float acc[NE];
        #pragma unroll
        for (int e = 0; e < NE; e++) acc[e] = 0.f;
        for (int i = lane; i < HD; i += 32) {
            float xv = xr[i];
            const float* w = Wr + (size_t)i * NE;
            #pragma unroll
            for (int e = 0; e < NE; e++) acc[e] += xv * w[e];
        }
        #pragma unroll
        for (int e = 0; e < NE; e++) {
            #pragma unroll
            for (int o = 16; o > 0; o >>= 1)
                acc[e] += __shfl_xor_sync(0xffffffffu, acc[e], o);
        }
        if (lane == 0) {
            float mx = acc[0];
            #pragma unroll
            for (int e = 1; e < NE; e++) mx = fmaxf(mx, acc[e]);
            float p[NE]; float s = 0.f;
            #pragma unroll
            for (int e = 0; e < NE; e++) { p[e] = expf(acc[e] - mx); s += p[e]; }
            float inv = 1.f / s;
            #pragma unroll
            for (int e = 0; e < NE; e++) p[e] *= inv;
            int i0 = 0;
            #pragma unroll
            for (int e = 1; e < NE; e++) if (p[e] > p[i0]) i0 = e;
            int i1 = (i0 == 0) ? 1 : 0;
            #pragma unroll
            for (int e = 0; e < NE; e++) if (e != i0 && p[e] > p[i1]) i1 = e;
            float w0 = p[i0], w1 = p[i1];
            float rn = 1.f / (w0 + w1);
            w0 *= rn; w1 *= rn;
            int pos0 = atomicAdd(&g_cnt[i0], 1);
            g_tok[i0 * TMAX + pos0]  = t;
            g_slot[i0 * TMAX + pos0] = t;
            g_wt[i0 * TMAX + pos0]   = w0;
            int pos1 = atomicAdd(&g_cnt[i1], 1);
            g_tok[i1 * TMAX + pos1]  = t;
            g_slot[i1 * TMAX + pos1] = T + t;
            g_wt[i1 * TMAX + pos1]   = w1;
            #pragma unroll
            for (int e = 0; e < NE; e++) atomicAdd(&s_p[e], p[e]);
        }
    }
    __syncthreads();
    if (threadIdx.x < NE) atomicAdd(&g_psum[threadIdx.x], s_p[threadIdx.x]);
}

// ------- merged gate+up GEMM + SwiGLU, fp16 2-pass, 512 thr, warp 32x32 ------
__global__ __launch_bounds__(512, 1)
void k_gu_all(const __half* __restrict__ Ah_g, const __half* __restrict__ Al_g, int T)
{
    const int z = blockIdx.z;
    int M, N, e = 0;
    bool gather;
    const __half *Bg, *Bu;
    __half *Ch, *Cl;
    if (z == 0) {
        gather = false; M = T; N = DS;
        Bg = g_WsgT; Bu = g_WsuT;
        Ch = g_buf2H; Cl = g_buf2L;
    } else {
        gather = true; e = z - 1;
        if (blockIdx.x >= DD / BN) return;
        M = g_cnt[e]; N = DD;
        size_t ws = (size_t)e * DD * HD;
        Bg = g_WgT + ws; Bu = g_WuT + ws;
        Ch = g_bufH + (size_t)e * TMAX * DD; Cl = g_bufL + (size_t)e * TMAX * DD;
    }
    const int row0 = blockIdx.y * BM;
    if (row0 >= M) return;
    const int col0 = blockIdx.x * BN;
    const int K = HD;

    extern __shared__ char dsm[];
    const uint32_t sb = smem_u32(dsm);

    const int tid = threadIdx.x;
    const int wid = tid >> 5, lane = tid & 31;
    const int wm = wid & 3, wn = wid >> 2;
    const int g = lane >> 2, t4 = lane & 3;

    size_t aoff, boff; uint32_t adst;
    {
        int r = tid >> 2, c16 = tid & 3;
        adst = r * (SA * 2) + c16 * 16;
        int gr = row0 + r;
        int grc = (gr < M) ? gr : (M - 1);
        if (gather) aoff = (size_t)g_tok[e * TMAX + grc] * K + c16 * 8;
        else        aoff = (size_t)grc * K + c16 * 8;
        boff = (size_t)(col0 + r) * K + c16 * 8;
    }

    const int a_r = (lane & 7) + ((lane >> 3) & 1) * 8;
    const int a_c = ((lane >> 4) & 1) * 8;
    const int b_r = (lane & 7) + ((lane >> 4) & 1) * 8;
    const int b_c = ((lane >> 3) & 1) * 8;
    const uint32_t la = (uint32_t)(a_r * SA + a_c) * 2;
    const uint32_t lb = (uint32_t)(b_r * SA + b_c) * 2;

    float accg[2][4][4], accu[2][4][4];
    #pragma unroll
    for (int mi = 0; mi < 2; mi++)
        #pragma unroll
        for (int ni = 0; ni < 4; ni++)
            #pragma unroll
            for (int q = 0; q < 4; q++) { accg[mi][ni][q] = 0.f; accu[mi][ni][q] = 0.f; }

    const int NC = K / BK;   // 32
    #pragma unroll
    for (int pc = 0; pc < 3; pc++) {
        uint32_t st = sb + pc * STG_GU;
        size_t ko = (size_t)pc * BK;
        CP16(st + 0 * TILE_B + adst, Ah_g + aoff + ko);
        CP16(st + 1 * TILE_B + adst, Al_g + aoff + ko);
        CP16(st + 2 * TILE_B + adst, Bg + boff + ko);
        CP16(st + 3 * TILE_B + adst, Bu + boff + ko);
        CPCOMMIT();
    }

    int s_next = 3;
    for (int c = 0; c < NC; c++) {
        CPWAIT2();
        __syncthreads();
        {
            int nc3 = (c + 3 < NC) ? c + 3 : NC - 1;
            uint32_t st = sb + s_next * STG_GU;
            size_t ko = (size_t)nc3 * BK;
            CP16(st + 0 * TILE_B + adst, Ah_g + aoff + ko);
            CP16(st + 1 * TILE_B + adst, Al_g + aoff + ko);
            CP16(st + 2 * TILE_B + adst, Bg + boff + ko);
            CP16(st + 3 * TILE_B + adst, Bu + boff + ko);
            CPCOMMIT();
        }
        s_next = (s_next + 1) & 3;
        const uint32_t st = sb + (c & 3) * STG_GU;
        #pragma unroll
        for (int ks = 0; ks < 2; ks++) {
            uint32_t fAh[2][4], fAl[2][4], fBg[2][4], fBu[2][4];
            #pragma unroll
            for (int mi = 0; mi < 2; mi++) {
                uint32_t ro = (uint32_t)((wm * 32 + mi * 16) * SA * 2) + ks * 32;
                ldsm4(fAh[mi], st + 0 * TILE_B + ro + la);
                ldsm4(fAl[mi], st + 1 * TILE_B + ro + la);
            }
            #pragma unroll
            for (int nb = 0; nb < 2; nb++) {
                uint32_t ro = (uint32_t)((wn * 32 + nb * 16) * SA * 2) + ks * 32;
                ldsm4(fBg[nb], st + 2 * TILE_B + ro + lb);
                ldsm4(fBu[nb], st + 3 * TILE_B + ro + lb);
            }
            #pragma unroll
            for (int mi = 0; mi < 2; mi++)
                #pragma unroll
                for (int ni = 0; ni < 4; ni++)
                    mma_f16(accg[mi][ni], fAh[mi], &fBg[ni >> 1][(ni & 1) * 2]);
            #pragma unroll
            for (int mi = 0; mi < 2; mi++)
                #pragma unroll
                for (int ni = 0; ni < 4; ni++)
                    mma_f16(accg[mi][ni], fAl[mi], &fBg[ni >> 1][(ni & 1) * 2]);
            #pragma unroll
            for (int mi = 0; mi < 2; mi++)
                #pragma unroll
                for (int ni = 0; ni < 4; ni++)
                    mma_f16(accu[mi][ni], fAh[mi], &fBu[ni >> 1][(ni & 1) * 2]);
            #pragma unroll
            for (int mi = 0; mi < 2; mi++)
                #pragma unroll
                for (int ni = 0; ni < 4; ni++)
                    mma_f16(accu[mi][ni], fAl[mi], &fBu[ni >> 1][(ni & 1) * 2]);
        }
    }

    // epilogue: swiglu (weighted if gather), fp16 hi/lo split store
    #pragma unroll
    for (int mi = 0; mi < 2; mi++) {
        int p0 = row0 + wm * 32 + mi * 16 + g;
        #pragma unroll
        for (int half = 0; half < 2; half++) {
            int p = p0 + half * 8;
            if (p >= M) continue;
            float w = gather ? g_wt[e * TMAX + p] : 1.f;
            size_t rowo = (size_t)p * N;
            #pragma unroll
            for (int ni = 0; ni < 4; ni++) {
                int col = col0 + wn * 32 + ni * 8 + 2 * t4;
                float gv0 = accg[mi][ni][half * 2 + 0];
                float gv1 = accg[mi][ni][half * 2 + 1];
                float uv0 = accu[mi][ni][half * 2 + 0];
                float uv1 = accu[mi][ni][half * 2 + 1];
                float v0 = w * (gv0 / (1.f + expf(-gv0))) * uv0;
                float v1 = w * (gv1 / (1.f + expf(-gv1))) * uv1;
                __half2 h = __floats2half2_rn(v0, v1);
                __half2 l = __floats2half2_rn(v0 - __half2float(h.x),
                                              v1 - __half2float(h.y));
                *(__half2*)(Ch + rowo + col) = h;
                *(__half2*)(Cl + rowo + col) = l;
            }
        }
    }
}

// ------- merged down GEMM, fp16 2-pass, 512 thr, warp 32x32 ------------------
__global__ __launch_bounds__(512, 1)
void k_dn_all(float* __restrict__ out, int T)
{
    const int z = blockIdx.z;
    int M, K, e = 0;
    bool scatter;
    const __half *Ah_g, *Al_g, *B;
    if (z == 0) {
        scatter = false; M = T; K = DS;
        Ah_g = g_buf2H; Al_g = g_buf2L;
        B = g_WsdT;
    } else {
        scatter = true; e = z - 1;
        M = g_cnt[e]; K = DD;
        Ah_g = g_bufH + (size_t)e * TMAX * DD;
        Al_g = g_bufL + (size_t)e * TMAX * DD;
        B = g_WdT + (size_t)e * HD * DD;
    }
    const int row0 = blockIdx.y * BM;
    if (row0 >= M) return;
    const int col0 = blockIdx.x * BN;

    extern __shared__ char dsm[];
    const uint32_t sb = smem_u32(dsm);

    const int tid = threadIdx.x;
    const int wid = tid >> 5, lane = tid & 31;
    const int wm = wid & 3, wn = wid >> 2;
    const int g = lane >> 2, t4 = lane & 3;

    size_t aoff, boff; uint32_t adst;
    {
        int r = tid >> 2, c16 = tid & 3;
        adst = r * (SA * 2) + c16 * 16;
        int gr = row0 + r;
        int grc = (gr < M) ? gr : (M - 1);
        aoff = (size_t)grc * K + c16 * 8;
        boff = (size_t)(col0 + r) * K + c16 * 8;
    }
    const int a_r = (lane & 7) + ((lane >> 3) & 1) * 8;
    const int a_c = ((lane >> 4) & 1) * 8;
    const int b_r = (lane & 7) + ((lane >> 4) & 1) * 8;
    const int b_c = ((lane >> 3) & 1) * 8;
    const uint32_t la = (uint32_t)(a_r * SA + a_c) * 2;
    const uint32_t lb = (uint32_t)(b_r * SA + b_c) * 2;

    float acc[2][4][4];
    #pragma unroll
    for (int mi = 0; mi < 2; mi++)
        #pragma unroll
        for (int ni = 0; ni < 4; ni++)
            #pragma unroll
            for (int q = 0; q < 4; q++) acc[mi][ni][q] = 0.f;

    const int NC = K / BK;
    #pragma unroll
    for (int pc = 0; pc < 3; pc++) {
        uint32_t st = sb + pc * STG_DN;
        size_t ko = (size_t)pc * BK;
        CP16(st + 0 * TILE_B + adst, Ah_g + aoff + ko);
        CP16(st + 1 * TILE_B + adst, Al_g + aoff + ko);
        CP16(st + 2 * TILE_B + adst, B + boff + ko);
        CPCOMMIT();
    }

    int s_next = 3;
    for (int c = 0; c < NC; c++) {
        CPWAIT2();
        __syncthreads();
        {
            int nc3 = (c + 3 < NC) ? c + 3 : NC - 1;
            uint32_t st = sb + s_next * STG_DN;
            size_t ko = (size_t)nc3 * BK;
            CP16(st + 0 * TILE_B + adst, Ah_g + aoff + ko);
            CP16(st + 1 * TILE_B + adst, Al_g + aoff + ko);
            CP16(st + 2 * TILE_B + adst, B + boff + ko);
            CPCOMMIT();
        }
        s_next = (s_next + 1) & 3;
        const uint32_t st = sb + (c & 3) * STG_DN;
        #pragma unroll
        for (int ks = 0; ks < 2; ks++) {
            uint32_t fAh[2][4], fAl[2][4], fB[2][4];
            #pragma unroll
            for (int mi = 0; mi < 2; mi++) {
                uint32_t ro = (uint32_t)((wm * 32 + mi * 16) * SA * 2) + ks * 32;
                ldsm4(fAh[mi], st + 0 * TILE_B + ro + la);
                ldsm4(fAl[mi], st + 1 * TILE_B + ro + la);
            }
            #pragma unroll
            for (int nb = 0; nb < 2; nb++) {
                uint32_t ro = (uint32_t)((wn * 32 + nb * 16) * SA * 2) + ks * 32;
                ldsm4(fB[nb], st + 2 * TILE_B + ro + lb);
            }
            #pragma unroll
            for (int mi = 0; mi < 2; mi++)
                #pragma unroll
                for (int ni = 0; ni < 4; ni++)
                    mma_f16(acc[mi][ni], fAh[mi], &fB[ni >> 1][(ni & 1) * 2]);
            #pragma unroll
            for (int mi = 0; mi < 2; mi++)
                #pragma unroll
                for (int ni = 0; ni < 4; ni++)
                    mma_f16(acc[mi][ni], fAl[mi], &fB[ni >> 1][(ni & 1) * 2]);
        }
    }

    #pragma unroll
    for (int mi = 0; mi < 2; mi++) {
        int p0 = row0 + wm * 32 + mi * 16 + g;
        int p1 = p0 + 8;
        float* c0 = nullptr; float* c1 = nullptr;
        if (scatter) {
            if (p0 < M) c0 = g_routed + (size_t)g_slot[e * TMAX + p0] * HD;
            if (p1 < M) c1 = g_routed + (size_t)g_slot[e * TMAX + p1] * HD;
        } else {
            c0 = out + (size_t)p0 * HD;
            c1 = out + (size_t)p1 * HD;
        }
        #pragma unroll
        for (int ni = 0; ni < 4; ni++) {
            int col = col0 + wn * 32 + ni * 8 + 2 * t4;
            if (c0) *(float2*)(c0 + col) = make_float2(acc[mi][ni][0], acc[mi][ni][1]);
            if (c1) *(float2*)(c1 + col) = make_float2(acc[mi][ni][2], acc[mi][ni][3]);
        }
    }
}

// ---------------- final: out += routed slots; aux loss tail ------------------
__global__ void k_final(float* __restrict__ out, int n4, int T, int out_size) {
    if (blockIdx.x == 0 && threadIdx.x == 0) {
        float a = 0.f;
        for (int e = 0; e < NE; e++) { float m = g_psum[e] / (float)T; a += m * m; }
        a *= (float)NE;
        for (size_t i = (size_t)T * HD; i < (size_t)out_size; i++) out[i] = a;
    }
    const float4* r = (const float4*)g_routed;
    float4* o4 = (float4*)out;
    int i = blockIdx.x * blockDim.x + threadIdx.x;
    int stride = gridDim.x * blockDim.x;
    for (; i < n4; i += stride) {
        float4 a = o4[i], b = r[i], c = r[i + n4];
        a.x += b.x + c.x;
        a.y += b.y + c.y;
        a.z += b.z + c.z;
        a.w += b.w + c.w;
        o4[i] = a;
    }
}

// ---------------- launch -----------------------------------------------------
extern "C" void kernel_launch(void* const* d_in, const int* in_sizes, int n_in,
                              void* d_out, int out_size) {
    const float* x   = (const float*)d_in[0];
    const float* Wr  = (const float*)d_in[1];
    const float* Wg  = (const float*)d_in[2];
    const float* Wu  = (const float*)d_in[3];
    const float* Wd  = (const float*)d_in[4];
    const float* Wsg = (const float*)d_in[5];
    const float* Wsu = (const float*)d_in[6];
    const float* Wsd = (const float*)d_in[7];
    float* out = (float*)d_out;
    const int T = in_sizes[0] / HD;   // 8192

    __half *xh, *xl;
    cudaGetSymbolAddress((void**)&xh, g_xh);
    cudaGetSymbolAddress((void**)&xl, g_xl);

    cudaFuncSetAttribute(k_gu_all, cudaFuncAttributeMaxDynamicSharedMemorySize, SMEM_GU);
    cudaFuncSetAttribute(k_dn_all, cudaFuncAttributeMaxDynamicSharedMemorySize, SMEM_DN);

    // 0: split x (+ zero routing counters)
    k_split_x<<<2048, 256>>>(x, T * HD / 4);
    // 1: all weight transposes -> fp16
    k_tsplit_all<<<dim3(32, 32, 27), dim3(32, 8)>>>(Wsg, Wsu, Wsd, Wg, Wu, Wd);
    // 2: router
    k_router<<<T / 8, 256>>>(x, Wr, T);
    // 3: merged gate+up (+swiglu), fp16 2-pass
    k_gu_all<<<dim3(DS / BN, T / BM, NE + 1), 512, SMEM_GU>>>(xh, xl, T);
    // 4: merged down, fp16 2-pass
    k_dn_all<<<dim3(HD / BN, T / BM, NE + 1), 512, SMEM_DN>>>(out, T);
    // 5: combine + aux loss
    k_final<<<2048, 256>>>(out, (T * HD) / 4, T, out_size);
}

// round 11
// speedup vs baseline: 4.9512x; 1.2808x over previous
#include <cuda_runtime.h>
#include <cuda_fp16.h>
#include <math.h>
#include <stdint.h>

#define NE   8
#define HD   1024
#define DD   512
#define DS   1024
#define TMAX 8192

#define BM 128
#define BN 128
#define BK 32
#define SA 40                    // A: 16-bit elems per row (32 + 8 pad)
#define SB 136                   // B: 16-bit elems per row (128 + 8 pad)
#define TILE_A (128 * SA * 2)    // 10240 B : 128 rows x 32 k
#define TILE_BB (32 * SB * 2)    // 8704 B  : 32 k-rows x 128 n
#define STG_GU (TILE_A + 2 * TILE_BB)      // A, Bg, Bu = 27648
#define STG_DN (2 * TILE_A + TILE_BB)      // Ah, Al, B = 29184
#define SMEM_GU (4 * STG_GU)     // 110592
#define SMEM_DN (4 * STG_DN)     // 116736

// ---------------- scratch (static device globals; no allocations) ------------
__device__ __align__(16) __half g_xh[(size_t)TMAX * HD];
__device__ __align__(16) __half g_bufH[(size_t)NE * TMAX * DD];   // routed gu out hi
__device__ __align__(16) __half g_bufL[(size_t)NE * TMAX * DD];   // lo
__device__ __align__(16) __half g_buf2H[(size_t)TMAX * DS];       // shared gu out
__device__ __align__(16) __half g_buf2L[(size_t)TMAX * DS];
__device__ __align__(16) float g_routed[(size_t)2 * TMAX * HD];
// fp16 weights in NATURAL [K][N] layout (no transpose)
__device__ __align__(16) __half g_Wsg16[(size_t)HD * DS];
__device__ __align__(16) __half g_Wsu16[(size_t)HD * DS];
__device__ __align__(16) __half g_Wsd16[(size_t)DS * HD];
__device__ __align__(16) __half g_Wg16[(size_t)NE * HD * DD];
__device__ __align__(16) __half g_Wu16[(size_t)NE * HD * DD];
__device__ __align__(16) __half g_Wd16[(size_t)NE * DD * HD];
__device__ int   g_cnt[NE];
__device__ int   g_tok[NE * TMAX];
__device__ int   g_slot[NE * TMAX];
__device__ float g_wt[NE * TMAX];
__device__ float g_psum[NE];

// ---------------- asm helpers ------------------------------------------------
__device__ __forceinline__ uint32_t smem_u32(const void* p) {
    uint32_t a;
    asm("{ .reg .u64 t; cvta.to.shared.u64 t, %1; cvt.u32.u64 %0, t; }" : "=r"(a) : "l"(p));
    return a;
}
#define CP16(dst, src) \
    asm volatile("cp.async.cg.shared.global [%0], [%1], 16;" :: "r"(dst), "l"(src) : "memory")
#define CPCOMMIT() asm volatile("cp.async.commit_group;" ::: "memory")
#define CPWAIT2()  asm volatile("cp.async.wait_group 2;" ::: "memory")

__device__ __forceinline__ void ldsm4(uint32_t* r, uint32_t addr) {
    asm volatile("ldmatrix.sync.aligned.m8n8.x4.shared.b16 {%0,%1,%2,%3}, [%4];"
        : "=r"(r[0]), "=r"(r[1]), "=r"(r[2]), "=r"(r[3]) : "r"(addr));
}
__device__ __forceinline__ void ldsm4t(uint32_t* r, uint32_t addr) {
    asm volatile("ldmatrix.sync.aligned.m8n8.x4.trans.shared.b16 {%0,%1,%2,%3}, [%4];"
        : "=r"(r[0]), "=r"(r[1]), "=r"(r[2]), "=r"(r[3]) : "r"(addr));
}
__device__ __forceinline__ void mma_f16(float* c, const uint32_t* a, const uint32_t* b) {
    asm volatile(
        "mma.sync.aligned.m16n8k16.row.col.f32.f16.f16.f32 "
        "{%0,%1,%2,%3}, {%4,%5,%6,%7}, {%8,%9}, {%0,%1,%2,%3};\n"
        : "+f"(c[0]), "+f"(c[1]), "+f"(c[2]), "+f"(c[3])
        : "r"(a[0]), "r"(a[1]), "r"(a[2]), "r"(a[3]), "r"(b[0]), "r"(b[1]));
}

// ---------------- x -> fp16 (single), + zero counters ------------------------
__global__ void k_split_x(const float* __restrict__ x, int n4) {
    if (blockIdx.x == 0 && threadIdx.x < NE) {
        g_cnt[threadIdx.x] = 0; g_psum[threadIdx.x] = 0.f;
    }
    int i = blockIdx.x * blockDim.x + threadIdx.x;
    int stride = gridDim.x * blockDim.x;
    for (; i < n4; i += stride) {
        float4 v = ((const float4*)x)[i];
        __half2 h01 = __floats2half2_rn(v.x, v.y);
        __half2 h23 = __floats2half2_rn(v.z, v.w);
        ((uint2*)g_xh)[i] = make_uint2(*(uint32_t*)&h01, *(uint32_t*)&h23);
    }
}

// -------- pure streaming convert f32 -> fp16 for all 6 weight tensors --------
__global__ void k_wconv(const float* __restrict__ Wsg, const float* __restrict__ Wsu,
                        const float* __restrict__ Wsd, const float* __restrict__ Wg,
                        const float* __restrict__ Wu,  const float* __restrict__ Wd) {
    const int z = blockIdx.z;
    const float* in; __half* o; size_t n4;
    if (z == 0)      { in = Wsg; o = g_Wsg16; n4 = (size_t)HD * DS / 4; }
    else if (z == 1) { in = Wsu; o = g_Wsu16; n4 = (size_t)HD * DS / 4; }
    else if (z == 2) { in = Wsd; o = g_Wsd16; n4 = (size_t)DS * HD / 4; }
    else if (z == 3) { in = Wg;  o = g_Wg16;  n4 = (size_t)NE * HD * DD / 4; }
    else if (z == 4) { in = Wu;  o = g_Wu16;  n4 = (size_t)NE * HD * DD / 4; }
    else             { in = Wd;  o = g_Wd16;  n4 = (size_t)NE * DD * HD / 4; }
    size_t i = (size_t)blockIdx.x * blockDim.x + threadIdx.x;
    size_t stride = (size_t)gridDim.x * blockDim.x;
    for (; i < n4; i += stride) {
        float4 v = ((const float4*)in)[i];
        __half2 h01 = __floats2half2_rn(v.x, v.y);
        __half2 h23 = __floats2half2_rn(v.z, v.w);
        ((uint2*)o)[i] = make_uint2(*(uint32_t*)&h01, *(uint32_t*)&h23);
    }
}

// ---------------- router ----------------------------------------------------
__global__ void k_router(const float* __restrict__ x, const float* __restrict__ Wr, int T) {
    __shared__ float s_p[NE];
    if (threadIdx.x < NE) s_p[threadIdx.x] = 0.f;
    __syncthreads();
    int warp = blockIdx.x * (blockDim.x >> 5) + (threadIdx.x >> 5);
    int lane = threadIdx.x & 31;
    if (warp < T) {
        int t = warp;
        const float* xr = x + (size_t)t * HD;
        float acc[NE];
        #pragma unroll
        for (int e = 0; e < NE; e++) acc[e] = 0.f;
        for (int i = lane; i < HD; i += 32) {
            float xv = xr[i];
            const float* w = Wr + (size_t)i * NE;
            #pragma unroll
            for (int e = 0; e < NE; e++) acc[e] += xv * w[e];
        }
        #pragma unroll
        for (int e = 0; e < NE; e++) {
            #pragma unroll
            for (int o = 16; o > 0; o >>= 1)
                acc[e] += __shfl_xor_sync(0xffffffffu, acc[e], o);
        }
        if (lane == 0) {
            float mx = acc[0];
            #pragma unroll
            for (int e = 1; e < NE; e++) mx = fmaxf(mx, acc[e]);
            float p[NE]; float s = 0.f;
            #pragma unroll
            for (int e = 0; e < NE; e++) { p[e] = expf(acc[e] - mx); s += p[e]; }
            float inv = 1.f / s;
            #pragma unroll
            for (int e = 0; e < NE; e++) p[e] *= inv;
            int i0 = 0;
            #pragma unroll
            for (int e = 1; e < NE; e++) if (p[e] > p[i0]) i0 = e;
            int i1 = (i0 == 0) ? 1 : 0;
            #pragma unroll
            for (int e = 0; e < NE; e++) if (e != i0 && p[e] > p[i1]) i1 = e;
            float w0 = p[i0], w1 = p[i1];
            float rn = 1.f / (w0 + w1);
            w0 *= rn; w1 *= rn;
            int pos0 = atomicAdd(&g_cnt[i0], 1);
            g_tok[i0 * TMAX + pos0]  = t;
            g_slot[i0 * TMAX + pos0] = t;
            g_wt[i0 * TMAX + pos0]   = w0;
            int pos1 = atomicAdd(&g_cnt[i1], 1);
            g_tok[i1 * TMAX + pos1]  = t;
            g_slot[i1 * TMAX + pos1] = T + t;
            g_wt[i1 * TMAX + pos1]   = w1;
            #pragma unroll
            for (int e = 0; e < NE; e++) atomicAdd(&s_p[e], p[e]);
        }
    }
    __syncthreads();
    if (threadIdx.x < NE) atomicAdd(&g_psum[threadIdx.x], s_p[threadIdx.x]);
}

// ------- merged gate+up GEMM + SwiGLU, single-fp16 A, trans-B ----------------
__global__ __launch_bounds__(512, 1)
void k_gu_all(const __half* __restrict__ A_g, int T)
{
    const int z = blockIdx.z;
    int M, N, e = 0;
    bool gather;
    const __half *Bg, *Bu;
    __half *Ch, *Cl;
    if (z == 0) {
        gather = false; M = T; N = DS;
        Bg = g_Wsg16; Bu = g_Wsu16;
        Ch = g_buf2H; Cl = g_buf2L;
    } else {
        gather = true; e = z - 1;
        if (blockIdx.x >= DD / BN) return;
        M = g_cnt[e]; N = DD;
        size_t ws = (size_t)e * HD * DD;
        Bg = g_Wg16 + ws; Bu = g_Wu16 + ws;
        Ch = g_bufH + (size_t)e * TMAX * DD; Cl = g_bufL + (size_t)e * TMAX * DD;
    }
    const int row0 = blockIdx.y * BM;
    if (row0 >= M) return;
    const int col0 = blockIdx.x * BN;
    const int K = HD;

    extern __shared__ char dsm[];
    const uint32_t sb = smem_u32(dsm);

    const int tid = threadIdx.x;
    const int wid = tid >> 5, lane = tid & 31;
    const int wm = wid & 3, wn = wid >> 2;
    const int g = lane >> 2, t4 = lane & 3;

    // A cp.async: 1 chunk/thread (128 rows x 4 chunks of 16B)
    size_t aoff; uint32_t adst;
    {
        int r = tid >> 2, c16 = tid & 3;
        adst = r * (SA * 2) + c16 * 16;
        int gr = row0 + r;
        int grc = (gr < M) ? gr : (M - 1);
        if (gather) aoff = (size_t)g_tok[e * TMAX + grc] * K + c16 * 8;
        else        aoff = (size_t)grc * K + c16 * 8;
    }
    // B cp.async: 1 chunk/thread per B tile (32 k-rows x 16 chunks of 16B)
    size_t boff; uint32_t bdst;
    {
        int br = tid >> 4, bc = tid & 15;
        bdst = br * (SB * 2) + bc * 16;
        boff = (size_t)br * N + col0 + bc * 8;
    }
    const size_t bstep = (size_t)BK * N;

    // A ldsm (non-trans)
    const int a_r = (lane & 7) + ((lane >> 3) & 1) * 8;
    const int a_c = ((lane >> 4) & 1) * 8;
    const uint32_t la = (uint32_t)(a_r * SA + a_c) * 2;
    // B ldsm (trans): k_row along rows, n_col along cols
    const int b_k = (lane & 7) + ((lane >> 3) & 1) * 8;
    const int b_n = ((lane >> 4) & 1) * 8;
    const uint32_t lbT = (uint32_t)(b_k * SB + b_n) * 2;

    float accg[2][4][4], accu[2][4][4];
    #pragma unroll
    for (int mi = 0; mi < 2; mi++)
        #pragma unroll
        for (int ni = 0; ni < 4; ni++)
            #pragma unroll
            for (int q = 0; q < 4; q++) { accg[mi][ni][q] = 0.f; accu[mi][ni][q] = 0.f; }

    const int NC = K / BK;   // 32
    #pragma unroll
    for (int pc = 0; pc < 3; pc++) {
        uint32_t st = sb + pc * STG_GU;
        CP16(st + adst, A_g + aoff + (size_t)pc * BK);
        CP16(st + TILE_A + bdst, Bg + boff + (size_t)pc * bstep);
        CP16(st + TILE_A + TILE_BB + bdst, Bu + boff + (size_t)pc * bstep);
        CPCOMMIT();
    }

    int s_next = 3;
    for (int c = 0; c < NC; c++) {
        CPWAIT2();
        __syncthreads();
        {
            int nc3 = (c + 3 < NC) ? c + 3 : NC - 1;
            uint32_t st = sb + s_next * STG_GU;
            CP16(st + adst, A_g + aoff + (size_t)nc3 * BK);
            CP16(st + TILE_A + bdst, Bg + boff + (size_t)nc3 * bstep);
            CP16(st + TILE_A + TILE_BB + bdst, Bu + boff + (size_t)nc3 * bstep);
            CPCOMMIT();
        }
        s_next = (s_next + 1) & 3;
        const uint32_t st = sb + (c & 3) * STG_GU;
        #pragma unroll
        for (int ks = 0; ks < 2; ks++) {
            uint32_t fA[2][4], fBg[2][4], fBu[2][4];
            #pragma unroll
            for (int mi = 0; mi < 2; mi++) {
                uint32_t ro = (uint32_t)((wm * 32 + mi * 16) * SA * 2) + ks * 32;
                ldsm4(fA[mi], st + ro + la);
            }
            #pragma unroll
            for (int nb = 0; nb < 2; nb++) {
                uint32_t bo = (uint32_t)(ks * 16 * SB * 2) + (uint32_t)((wn * 32 + nb * 16) * 2);
                ldsm4t(fBg[nb], st + TILE_A + bo + lbT);
                ldsm4t(fBu[nb], st + TILE_A + TILE_BB + bo + lbT);
            }
            #pragma unroll
            for (int mi = 0; mi < 2; mi++)
                #pragma unroll
                for (int ni = 0; ni < 4; ni++)
                    mma_f16(accg[mi][ni], fA[mi], &fBg[ni >> 1][(ni & 1) * 2]);
            #pragma unroll
            for (int mi = 0; mi < 2; mi++)
                #pragma unroll
                for (int ni = 0; ni < 4; ni++)
                    mma_f16(accu[mi][ni], fA[mi], &fBu[ni >> 1][(ni & 1) * 2]);
        }
    }

    // epilogue: swiglu (weighted if gather), fp16 hi/lo split store
    #pragma unroll
    for (int mi = 0; mi < 2; mi++) {
        int p0 = row0 + wm * 32 + mi * 16 + g;
        #pragma unroll
        for (int half = 0; half < 2; half++) {
            int p = p0 + half * 8;
            if (p >= M) continue;
            float w = gather ? g_wt[e * TMAX + p] : 1.f;
            size_t rowo = (size_t)p * N;
            #pragma unroll
            for (int ni = 0; ni < 4; ni++) {
                int col = col0 + wn * 32 + ni * 8 + 2 * t4;
                float gv0 = accg[mi][ni][half * 2 + 0];
                float gv1 = accg[mi][ni][half * 2 + 1];
                float uv0 = accu[mi][ni][half * 2 + 0];
                float uv1 = accu[mi][ni][half * 2 + 1];
                float v0 = w * (gv0 / (1.f + expf(-gv0))) * uv0;
                float v1 = w * (gv1 / (1.f + expf(-gv1))) * uv1;
                __half2 h = __floats2half2_rn(v0, v1);
                __half2 l = __floats2half2_rn(v0 - __half2float(h.x),
                                              v1 - __half2float(h.y));
                *(__half2*)(Ch + rowo + col) = h;
                *(__half2*)(Cl + rowo + col) = l;
            }
        }
    }
}

// ------- merged down GEMM, hi/lo A (2-pass), trans-B -------------------------
__global__ __launch_bounds__(512, 1)
void k_dn_all(float* __restrict__ out, int T)
{
    const int z = blockIdx.z;
    int M, K, e = 0;
    bool scatter;
    const __half *Ah_g, *Al_g, *B;
    if (z == 0) {
        scatter = false; M = T; K = DS;
        Ah_g = g_buf2H; Al_g = g_buf2L;
        B = g_Wsd16;
    } else {
        scatter = true; e = z - 1;
        M = g_cnt[e]; K = DD;
        Ah_g = g_bufH + (size_t)e * TMAX * DD;
        Al_g = g_bufL + (size_t)e * TMAX * DD;
        B = g_Wd16 + (size_t)e * DD * HD;
    }
    const int row0 = blockIdx.y * BM;
    if (row0 >= M) return;
    const int col0 = blockIdx.x * BN;   // N = HD
    const int N = HD;

    extern __shared__ char dsm[];
    const uint32_t sb = smem_u32(dsm);

    const int tid = threadIdx.x;
    const int wid = tid >> 5, lane = tid & 31;
    const int wm = wid & 3, wn = wid >> 2;
    const int g = lane >> 2, t4 = lane & 3;

    size_t aoff; uint32_t adst;
    {
        int r = tid >> 2, c16 = tid & 3;
        adst = r * (SA * 2) + c16 * 16;
        int gr = row0 + r;
        int grc = (gr < M) ? gr : (M - 1);
        aoff = (size_t)grc * K + c16 * 8;
    }
    size_t boff; uint32_t bdst;
    {
        int br = tid >> 4, bc = tid & 15;
        bdst = br * (SB * 2) + bc * 16;
        boff = (size_t)br * N + col0 + bc * 8;
    }
    const size_t bstep = (size_t)BK * N;

    const int a_r = (lane & 7) + ((lane >> 3) & 1) * 8;
    const int a_c = ((lane >> 4) & 1) * 8;
    const uint32_t la = (uint32_t)(a_r * SA + a_c) * 2;
    const int b_k = (lane & 7) + ((lane >> 3) & 1) * 8;
    const int b_n = ((lane >> 4) & 1) * 8;
    const uint32_t lbT = (uint32_t)(b_k * SB + b_n) * 2;

    float acc[2][4][4];
    #pragma unroll
    for (int mi = 0; mi < 2; mi++)
        #pragma unroll
        for (int ni = 0; ni < 4; ni++)
            #pragma unroll
            for (int q = 0; q < 4; q++) acc[mi][ni][q] = 0.f;

    const int NC = K / BK;
    #pragma unroll
    for (int pc = 0; pc < 3; pc++) {
        uint32_t st = sb + pc * STG_DN;
        CP16(st + adst, Ah_g + aoff + (size_t)pc * BK);
        CP16(st + TILE_A + adst, Al_g + aoff + (size_t)pc * BK);
        CP16(st + 2 * TILE_A + bdst, B + boff + (size_t)pc * bstep);
        CPCOMMIT();
    }

    int s_next = 3;
    for (int c = 0; c < NC; c++) {
        CPWAIT2();
        __syncthreads();
        {
            int nc3 = (c + 3 < NC) ? c + 3 : NC - 1;
            uint32_t st = sb + s_next * STG_DN;
            CP16(st + adst, Ah_g + aoff + (size_t)nc3 * BK);
            CP16(st + TILE_A + adst, Al_g + aoff + (size_t)nc3 * BK);
            CP16(st + 2 * TILE_A + bdst, B + boff + (size_t)nc3 * bstep);
            CPCOMMIT();
        }
        s_next = (s_next + 1) & 3;
        const uint32_t st = sb + (c & 3) * STG_DN;
        #pragma unroll
        for (int ks = 0; ks < 2; ks++) {
            uint32_t fAh[2][4], fAl[2][4], fB[2][4];
            #pragma unroll
            for (int mi = 0; mi < 2; mi++) {
                uint32_t ro = (uint32_t)((wm * 32 + mi * 16) * SA * 2) + ks * 32;
                ldsm4(fAh[mi], st + ro + la);
                ldsm4(fAl[mi], st + TILE_A + ro + la);
            }
            #pragma unroll
            for (int nb = 0; nb < 2; nb++) {
                uint32_t bo = (uint32_t)(ks * 16 * SB * 2) + (uint32_t)((wn * 32 + nb * 16) * 2);
                ldsm4t(fB[nb], st + 2 * TILE_A + bo + lbT);
            }
            #pragma unroll
            for (int mi = 0; mi < 2; mi++)
                #pragma unroll
                for (int ni = 0; ni < 4; ni++)
                    mma_f16(acc[mi][ni], fAh[mi], &fB[ni >> 1][(ni & 1) * 2]);
            #pragma unroll
            for (int mi = 0; mi < 2; mi++)
                #pragma unroll
                for (int ni = 0; ni < 4; ni++)
                    mma_f16(acc[mi][ni], fAl[mi], &fB[ni >> 1][(ni & 1) * 2]);
        }
    }

    #pragma unroll
    for (int mi = 0; mi < 2; mi++) {
        int p0 = row0 + wm * 32 + mi * 16 + g;
        int p1 = p0 + 8;
        float* c0 = nullptr; float* c1 = nullptr;
        if (scatter) {
            if (p0 < M) c0 = g_routed + (size_t)g_slot[e * TMAX + p0] * HD;
            if (p1 < M) c1 = g_routed + (size_t)g_slot[e * TMAX + p1] * HD;
        } else {
            c0 = out + (size_t)p0 * HD;
            c1 = out + (size_t)p1 * HD;
        }
        #pragma unroll
        for (int ni = 0; ni < 4; ni++) {
            int col = col0 + wn * 32 + ni * 8 + 2 * t4;
            if (c0) *(float2*)(c0 + col) = make_float2(acc[mi][ni][0], acc[mi][ni][1]);
            if (c1) *(float2*)(c1 + col) = make_float2(acc[mi][ni][2], acc[mi][ni][3]);
        }
    }
}

// ---------------- final: out += routed slots; aux loss tail ------------------
__global__ void k_final(float* __restrict__ out, int n4, int T, int out_size) {
    if (blockIdx.x == 0 && threadIdx.x == 0) {
        float a = 0.f;
        for (int e = 0; e < NE; e++) { float m = g_psum[e] / (float)T; a += m * m; }
        a *= (float)NE;
        for (size_t i = (size_t)T * HD; i < (size_t)out_size; i++) out[i] = a;
    }
    const float4* r = (const float4*)g_routed;
    float4* o4 = (float4*)out;
    int i = blockIdx.x * blockDim.x + threadIdx.x;
    int stride = gridDim.x * blockDim.x;
    for (; i < n4; i += stride) {
        float4 a = o4[i], b = r[i], c = r[i + n4];
        a.x += b.x + c.x;
        a.y += b.y + c.y;
        a.z += b.z + c.z;
        a.w += b.w + c.w;
        o4[i] = a;
    }
}

// ---------------- launch -----------------------------------------------------
extern "C" void kernel_launch(void* const* d_in, const int* in_sizes, int n_in,
                              void* d_out, int out_size) {
    const float* x   = (const float*)d_in[0];
    const float* Wr  = (const float*)d_in[1];
    const float* Wg  = (const float*)d_in[2];
    const float* Wu  = (const float*)d_in[3];
    const float* Wd  = (const float*)d_in[4];
    const float* Wsg = (const float*)d_in[5];
    const float* Wsu = (const float*)d_in[6];
    const float* Wsd = (const float*)d_in[7];
    float* out = (float*)d_out;
    const int T = in_sizes[0] / HD;   // 8192

    __half* xh;
    cudaGetSymbolAddress((void**)&xh, g_xh);

    cudaFuncSetAttribute(k_gu_all, cudaFuncAttributeMaxDynamicSharedMemorySize, SMEM_GU);
    cudaFuncSetAttribute(k_dn_all, cudaFuncAttributeMaxDynamicSharedMemorySize, SMEM_DN);

    // 0: x -> fp16 (+ zero routing counters)
    k_split_x<<<2048, 256>>>(x, T * HD / 4);
    // 1: streaming weight convert f32 -> fp16 (natural layout, no transpose)
    k_wconv<<<dim3(512, 1, 6), 256>>>(Wsg, Wsu, Wsd, Wg, Wu, Wd);
    // 2: router
    k_router<<<T / 8, 256>>>(x, Wr, T);
    // 3: merged gate+up (+swiglu), single-fp16 A, trans-B
    k_gu_all<<<dim3(DS / BN, T / BM, NE + 1), 512, SMEM_GU>>>(xh, T);
    // 4: merged down, hi/lo A, trans-B
    k_dn_all<<<dim3(HD / BN, T / BM, NE + 1), 512, SMEM_DN>>>(out, T);
    // 5: combine + aux loss
    k_final<<<2048, 256>>>(out, (T * HD) / 4, T, out_size);
}

// round 12
// speedup vs baseline: 5.8764x; 1.1869x over previous
#include <cuda_runtime.h>
#include <cuda_fp16.h>
#include <math.h>
#include <stdint.h>

#define NE   8
#define HD   1024
#define DD   512
#define DS   1024
#define TMAX 8192

#define BM 128
#define BN 128
#define BK 32
#define SA 40                    // A: 16-bit elems per row (32 + 8 pad)
#define SB 136                   // B: 16-bit elems per row (128 + 8 pad)
#define TILE_A (128 * SA * 2)    // 10240 B
#define TILE_BB (32 * SB * 2)    // 8704 B
#define STG_GU (TILE_A + 2 * TILE_BB)   // A, Bg, Bu = 27648
#define STG_DN (TILE_A + TILE_BB)       // A, B = 18944
#define SMEM_GU (4 * STG_GU)     // 110592
#define SMEM_DN (4 * STG_DN)     // 75776

// ---------------- scratch (static device globals; no allocations) ------------
__device__ __align__(16) __half g_xh[(size_t)TMAX * HD];
__device__ __align__(16) __half g_bufH[(size_t)NE * TMAX * DD];   // routed gu out
__device__ __align__(16) __half g_buf2H[(size_t)TMAX * DS];       // shared gu out
__device__ __align__(16) float g_routed[(size_t)2 * TMAX * HD];
// fp16 weights in NATURAL [K][N] layout
__device__ __align__(16) __half g_Wsg16[(size_t)HD * DS];
__device__ __align__(16) __half g_Wsu16[(size_t)HD * DS];
__device__ __align__(16) __half g_Wsd16[(size_t)DS * HD];
__device__ __align__(16) __half g_Wg16[(size_t)NE * HD * DD];
__device__ __align__(16) __half g_Wu16[(size_t)NE * HD * DD];
__device__ __align__(16) __half g_Wd16[(size_t)NE * DD * HD];
__device__ int   g_cnt[NE];
__device__ int   g_tok[NE * TMAX];
__device__ int   g_slot[NE * TMAX];
__device__ float g_wt[NE * TMAX];
__device__ float g_psum[NE];

// ---------------- asm helpers ------------------------------------------------
__device__ __forceinline__ uint32_t smem_u32(const void* p) {
    uint32_t a;
    asm("{ .reg .u64 t; cvta.to.shared.u64 t, %1; cvt.u32.u64 %0, t; }" : "=r"(a) : "l"(p));
    return a;
}
#define CP16(dst, src) \
    asm volatile("cp.async.cg.shared.global [%0], [%1], 16;" :: "r"(dst), "l"(src) : "memory")
#define CPCOMMIT() asm volatile("cp.async.commit_group;" ::: "memory")
#define CPWAIT2()  asm volatile("cp.async.wait_group 2;" ::: "memory")

__device__ __forceinline__ void ldsm4(uint32_t* r, uint32_t addr) {
    asm volatile("ldmatrix.sync.aligned.m8n8.x4.shared.b16 {%0,%1,%2,%3}, [%4];"
        : "=r"(r[0]), "=r"(r[1]), "=r"(r[2]), "=r"(r[3]) : "r"(addr));
}
__device__ __forceinline__ void ldsm4t(uint32_t* r, uint32_t addr) {
    asm volatile("ldmatrix.sync.aligned.m8n8.x4.trans.shared.b16 {%0,%1,%2,%3}, [%4];"
        : "=r"(r[0]), "=r"(r[1]), "=r"(r[2]), "=r"(r[3]) : "r"(addr));
}
__device__ __forceinline__ void mma_f16(float* c, const uint32_t* a, const uint32_t* b) {
    asm volatile(
        "mma.sync.aligned.m16n8k16.row.col.f32.f16.f16.f32 "
        "{%0,%1,%2,%3}, {%4,%5,%6,%7}, {%8,%9}, {%0,%1,%2,%3};\n"
        : "+f"(c[0]), "+f"(c[1]), "+f"(c[2]), "+f"(c[3])
        : "r"(a[0]), "r"(a[1]), "r"(a[2]), "r"(a[3]), "r"(b[0]), "r"(b[1]));
}

// ---------------- x -> fp16, + zero counters ---------------------------------
__global__ void k_split_x(const float* __restrict__ x, int n4) {
    if (blockIdx.x == 0 && threadIdx.x < NE) {
        g_cnt[threadIdx.x] = 0; g_psum[threadIdx.x] = 0.f;
    }
    int i = blockIdx.x * blockDim.x + threadIdx.x;
    int stride = gridDim.x * blockDim.x;
    for (; i < n4; i += stride) {
        float4 v = ((const float4*)x)[i];
        __half2 h01 = __floats2half2_rn(v.x, v.y);
        __half2 h23 = __floats2half2_rn(v.z, v.w);
        ((uint2*)g_xh)[i] = make_uint2(*(uint32_t*)&h01, *(uint32_t*)&h23);
    }
}

// -------- streaming convert f32 -> fp16 for all 6 weight tensors -------------
__global__ void k_wconv(const float* __restrict__ Wsg, const float* __restrict__ Wsu,
                        const float* __restrict__ Wsd, const float* __restrict__ Wg,
                        const float* __restrict__ Wu,  const float* __restrict__ Wd) {
    const int z = blockIdx.z;
    const float* in; __half* o; size_t n4;
    if (z == 0)      { in = Wsg; o = g_Wsg16; n4 = (size_t)HD * DS / 4; }
    else if (z == 1) { in = Wsu; o = g_Wsu16; n4 = (size_t)HD * DS / 4; }
    else if (z == 2) { in = Wsd; o = g_Wsd16; n4 = (size_t)DS * HD / 4; }
    else if (z == 3) { in = Wg;  o = g_Wg16;  n4 = (size_t)NE * HD * DD / 4; }
    else if (z == 4) { in = Wu;  o = g_Wu16;  n4 = (size_t)NE * HD * DD / 4; }
    else             { in = Wd;  o = g_Wd16;  n4 = (size_t)NE * DD * HD / 4; }
    size_t i = (size_t)blockIdx.x * blockDim.x + threadIdx.x;
    size_t stride = (size_t)gridDim.x * blockDim.x;
    for (; i < n4; i += stride) {
        float4 v = ((const float4*)in)[i];
        __half2 h01 = __floats2half2_rn(v.x, v.y);
        __half2 h23 = __floats2half2_rn(v.z, v.w);
        ((uint2*)o)[i] = make_uint2(*(uint32_t*)&h01, *(uint32_t*)&h23);
    }
}

// ---------------- router ----------------------------------------------------
__global__ void k_router(const float* __restrict__ x, const float* __restrict__ Wr, int T) {
    __shared__ float s_p[NE];
    if (threadIdx.x < NE) s_p[threadIdx.x] = 0.f;
    __syncthreads();
    int warp = blockIdx.x * (blockDim.x >> 5) + (threadIdx.x >> 5);
    int lane = threadIdx.x & 31;
    if (warp < T) {
        int t = warp;
        const float* xr = x + (size_t)t * HD;
        float acc[NE];
        #pragma unroll
        for (int e = 0; e < NE; e++) acc[e] = 0.f;
        for (int i = lane; i < HD; i += 32) {
            float xv = xr[i];
            const float* w = Wr + (size_t)i * NE;
            #pragma unroll
            for (int e = 0; e < NE; e++) acc[e] += xv * w[e];
        }
        #pragma unroll
        for (int e = 0; e < NE; e++) {
            #pragma unroll
            for (int o = 16; o > 0; o >>= 1)
                acc[e] += __shfl_xor_sync(0xffffffffu, acc[e], o);
        }
        if (lane == 0) {
            float mx = acc[0];
            #pragma unroll
            for (int e = 1; e < NE; e++) mx = fmaxf(mx, acc[e]);
            float p[NE]; float s = 0.f;
            #pragma unroll
            for (int e = 0; e < NE; e++) { p[e] = expf(acc[e] - mx); s += p[e]; }
            float inv = 1.f / s;
            #pragma unroll
            for (int e = 0; e < NE; e++) p[e] *= inv;
            int i0 = 0;
            #pragma unroll
            for (int e = 1; e < NE; e++) if (p[e] > p[i0]) i0 = e;
            int i1 = (i0 == 0) ? 1 : 0;
            #pragma unroll
            for (int e = 0; e < NE; e++) if (e != i0 && p[e] > p[i1]) i1 = e;
            float w0 = p[i0], w1 = p[i1];
            float rn = 1.f / (w0 + w1);
            w0 *= rn; w1 *= rn;
            int pos0 = atomicAdd(&g_cnt[i0], 1);
            g_tok[i0 * TMAX + pos0]  = t;
            g_slot[i0 * TMAX + pos0] = t;
            g_wt[i0 * TMAX + pos0]   = w0;
            int pos1 = atomicAdd(&g_cnt[i1], 1);
            g_tok[i1 * TMAX + pos1]  = t;
            g_slot[i1 * TMAX + pos1] = T + t;
            g_wt[i1 * TMAX + pos1]   = w1;
            #pragma unroll
            for (int e = 0; e < NE; e++) atomicAdd(&s_p[e], p[e]);
        }
    }
    __syncthreads();
    if (threadIdx.x < NE) atomicAdd(&g_psum[threadIdx.x], s_p[threadIdx.x]);
}

// ------- merged gate+up GEMM + SwiGLU, single-fp16 A, trans-B ----------------
__global__ __launch_bounds__(512, 1)
void k_gu_all(const __half* __restrict__ A_g, int T)
{
    const int z = blockIdx.z;
    int M, N, e = 0;
    bool gather;
    const __half *Bg, *Bu;
    __half* Ch;
    if (z == 0) {
        gather = false; M = T; N = DS;
        Bg = g_Wsg16; Bu = g_Wsu16;
        Ch = g_buf2H;
    } else {
        gather = true; e = z - 1;
        if (blockIdx.x >= DD / BN) return;
        M = g_cnt[e]; N = DD;
        size_t ws = (size_t)e * HD * DD;
        Bg = g_Wg16 + ws; Bu = g_Wu16 + ws;
        Ch = g_bufH + (size_t)e * TMAX * DD;
    }
    const int row0 = blockIdx.y * BM;
    if (row0 >= M) return;
    const int col0 = blockIdx.x * BN;
    const int K = HD;

    extern __shared__ char dsm[];
    const uint32_t sb = smem_u32(dsm);

    const int tid = threadIdx.x;
    const int wid = tid >> 5, lane = tid & 31;
    const int wm = wid & 3, wn = wid >> 2;
    const int g = lane >> 2, t4 = lane & 3;

    size_t aoff; uint32_t adst;
    {
        int r = tid >> 2, c16 = tid & 3;
        adst = r * (SA * 2) + c16 * 16;
        int gr = row0 + r;
        int grc = (gr < M) ? gr : (M - 1);
        if (gather) aoff = (size_t)g_tok[e * TMAX + grc] * K + c16 * 8;
        else        aoff = (size_t)grc * K + c16 * 8;
    }
    size_t boff; uint32_t bdst;
    {
        int br = tid >> 4, bc = tid & 15;
        bdst = br * (SB * 2) + bc * 16;
        boff = (size_t)br * N + col0 + bc * 8;
    }
    const size_t bstep = (size_t)BK * N;

    const int a_r = (lane & 7) + ((lane >> 3) & 1) * 8;
    const int a_c = ((lane >> 4) & 1) * 8;
    const uint32_t la = (uint32_t)(a_r * SA + a_c) * 2;
    const int b_k = (lane & 7) + ((lane >> 3) & 1) * 8;
    const int b_n = ((lane >> 4) & 1) * 8;
    const uint32_t lbT = (uint32_t)(b_k * SB + b_n) * 2;

    float accg[2][4][4], accu[2][4][4];
    #pragma unroll
    for (int mi = 0; mi < 2; mi++)
        #pragma unroll
        for (int ni = 0; ni < 4; ni++)
            #pragma unroll
            for (int q = 0; q < 4; q++) { accg[mi][ni][q] = 0.f; accu[mi][ni][q] = 0.f; }

    const int NC = K / BK;   // 32
    #pragma unroll
    for (int pc = 0; pc < 3; pc++) {
        uint32_t st = sb + pc * STG_GU;
        CP16(st + adst, A_g + aoff + (size_t)pc * BK);
        CP16(st + TILE_A + bdst, Bg + boff + (size_t)pc * bstep);
        CP16(st + TILE_A + TILE_BB + bdst, Bu + boff + (size_t)pc * bstep);
        CPCOMMIT();
    }

    int s_next = 3;
    for (int c = 0; c < NC; c++) {
        CPWAIT2();
        __syncthreads();
        {
            int nc3 = (c + 3 < NC) ? c + 3 : NC - 1;
            uint32_t st = sb + s_next * STG_GU;
            CP16(st + adst, A_g + aoff + (size_t)nc3 * BK);
            CP16(st + TILE_A + bdst, Bg + boff + (size_t)nc3 * bstep);
            CP16(st + TILE_A + TILE_BB + bdst, Bu + boff + (size_t)nc3 * bstep);
            CPCOMMIT();
        }
        s_next = (s_next + 1) & 3;
        const uint32_t st = sb + (c & 3) * STG_GU;
        #pragma unroll
        for (int ks = 0; ks < 2; ks++) {
            uint32_t fA[2][4], fBg[2][4], fBu[2][4];
            #pragma unroll
            for (int mi = 0; mi < 2; mi++) {
                uint32_t ro = (uint32_t)((wm * 32 + mi * 16) * SA * 2) + ks * 32;
                ldsm4(fA[mi], st + ro + la);
            }
            #pragma unroll
            for (int nb = 0; nb < 2; nb++) {
                uint32_t bo = (uint32_t)(ks * 16 * SB * 2) + (uint32_t)((wn * 32 + nb * 16) * 2);
                ldsm4t(fBg[nb], st + TILE_A + bo + lbT);
                ldsm4t(fBu[nb], st + TILE_A + TILE_BB + bo + lbT);
            }
            #pragma unroll
            for (int mi = 0; mi < 2; mi++)
                #pragma unroll
                for (int ni = 0; ni < 4; ni++)
                    mma_f16(accg[mi][ni], fA[mi], &fBg[ni >> 1][(ni & 1) * 2]);
            #pragma unroll
            for (int mi = 0; mi < 2; mi++)
                #pragma unroll
                for (int ni = 0; ni < 4; ni++)
                    mma_f16(accu[mi][ni], fA[mi], &fBu[ni >> 1][(ni & 1) * 2]);
        }
    }

    // epilogue: swiglu (weighted if gather), single-fp16 store
    #pragma unroll
    for (int mi = 0; mi < 2; mi++) {
        int p0 = row0 + wm * 32 + mi * 16 + g;
        #pragma unroll
        for (int half = 0; half < 2; half++) {
            int p = p0 + half * 8;
            if (p >= M) continue;
            float w = gather ? g_wt[e * TMAX + p] : 1.f;
            size_t rowo = (size_t)p * N;
            #pragma unroll
            for (int ni = 0; ni < 4; ni++) {
                int col = col0 + wn * 32 + ni * 8 + 2 * t4;
                float gv0 = accg[mi][ni][half * 2 + 0];
                float gv1 = accg[mi][ni][half * 2 + 1];
                float uv0 = accu[mi][ni][half * 2 + 0];
                float uv1 = accu[mi][ni][half * 2 + 1];
                float v0 = w * (gv0 / (1.f + expf(-gv0))) * uv0;
                float v1 = w * (gv1 / (1.f + expf(-gv1))) * uv1;
                *(__half2*)(Ch + rowo + col) = __floats2half2_rn(v0, v1);
            }
        }
    }
}

// ------- merged down GEMM, single-fp16 A, trans-B ----------------------------
__global__ __launch_bounds__(512, 1)
void k_dn_all(float* __restrict__ out, int T)
{
    const int z = blockIdx.z;
    int M, K, e = 0;
    bool scatter;
    const __half *A_g, *B;
    if (z == 0) {
        scatter = false; M = T; K = DS;
        A_g = g_buf2H;
        B = g_Wsd16;
    } else {
        scatter = true; e = z - 1;
        M = g_cnt[e]; K = DD;
        A_g = g_bufH + (size_t)e * TMAX * DD;
        B = g_Wd16 + (size_t)e * DD * HD;
    }
    const int row0 = blockIdx.y * BM;
    if (row0 >= M) return;
    const int col0 = blockIdx.x * BN;
    const int N = HD;

    extern __shared__ char dsm[];
    const uint32_t sb = smem_u32(dsm);

    const int tid = threadIdx.x;
    const int wid = tid >> 5, lane = tid & 31;
    const int wm = wid & 3, wn = wid >> 2;
    const int g = lane >> 2, t4 = lane & 3;

    size_t aoff; uint32_t adst;
    {
        int r = tid >> 2, c16 = tid & 3;
        adst = r * (SA * 2) + c16 * 16;
        int gr = row0 + r;
        int grc = (gr < M) ? gr : (M - 1);
        aoff = (size_t)grc * K + c16 * 8;
    }
    size_t boff; uint32_t bdst;
    {
        int br = tid >> 4, bc = tid & 15;
        bdst = br * (SB * 2) + bc * 16;
        boff = (size_t)br * N + col0 + bc * 8;
    }
    const size_t bstep = (size_t)BK * N;

    const int a_r = (lane & 7) + ((lane >> 3) & 1) * 8;
    const int a_c = ((lane >> 4) & 1) * 8;
    const uint32_t la = (uint32_t)(a_r * SA + a_c) * 2;
    const int b_k = (lane & 7) + ((lane >> 3) & 1) * 8;
    const int b_n = ((lane >> 4) & 1) * 8;
    const uint32_t lbT = (uint32_t)(b_k * SB + b_n) * 2;

    float acc[2][4][4];
    #pragma unroll
    for (int mi = 0; mi < 2; mi++)
        #pragma unroll
        for (int ni = 0; ni < 4; ni++)
            #pragma unroll
            for (int q = 0; q < 4; q++) acc[mi][ni][q] = 0.f;

    const int NC = K / BK;
    #pragma unroll
    for (int pc = 0; pc < 3; pc++) {
        uint32_t st = sb + pc * STG_DN;
        CP16(st + adst, A_g + aoff + (size_t)pc * BK);
        CP16(st + TILE_A + bdst, B + boff + (size_t)pc * bstep);
        CPCOMMIT();
    }

    int s_next = 3;
    for (int c = 0; c < NC; c++) {
        CPWAIT2();
        __syncthreads();
        {
            int nc3 = (c + 3 < NC) ? c + 3 : NC - 1;
            uint32_t st = sb + s_next * STG_DN;
            CP16(st + adst, A_g + aoff + (size_t)nc3 * BK);
            CP16(st + TILE_A + bdst, B + boff + (size_t)nc3 * bstep);
            CPCOMMIT();
        }
        s_next = (s_next + 1) & 3;
        const uint32_t st = sb + (c & 3) * STG_DN;
        #pragma unroll
        for (int ks = 0; ks < 2; ks++) {
            uint32_t fA[2][4], fB[2][4];
            #pragma unroll
            for (int mi = 0; mi < 2; mi++) {
                uint32_t ro = (uint32_t)((wm * 32 + mi * 16) * SA * 2) + ks * 32;
                ldsm4(fA[mi], st + ro + la);
            }
            #pragma unroll
            for (int nb = 0; nb < 2; nb++) {
                uint32_t bo = (uint32_t)(ks * 16 * SB * 2) + (uint32_t)((wn * 32 + nb * 16) * 2);
                ldsm4t(fB[nb], st + TILE_A + bo + lbT);
            }
            #pragma unroll
            for (int mi = 0; mi < 2; mi++)
                #pragma unroll
                for (int ni = 0; ni < 4; ni++)
                    mma_f16(acc[mi][ni], fA[mi], &fB[ni >> 1][(ni & 1) * 2]);
        }
    }

    #pragma unroll
    for (int mi = 0; mi < 2; mi++) {
        int p0 = row0 + wm * 32 + mi * 16 + g;
        int p1 = p0 + 8;
        float* c0 = nullptr; float* c1 = nullptr;
        if (scatter) {
            if (p0 < M) c0 = g_routed + (size_t)g_slot[e * TMAX + p0] * HD;
            if (p1 < M) c1 = g_routed + (size_t)g_slot[e * TMAX + p1] * HD;
        } else {
            c0 = out + (size_t)p0 * HD;
            c1 = out + (size_t)p1 * HD;
        }
        #pragma unroll
        for (int ni = 0; ni < 4; ni++) {
            int col = col0 + wn * 32 + ni * 8 + 2 * t4;
            if (c0) *(float2*)(c0 + col) = make_float2(acc[mi][ni][0], acc[mi][ni][1]);
            if (c1) *(float2*)(c1 + col) = make_float2(acc[mi][ni][2], acc[mi][ni][3]);
        }
    }
}

// ---------------- final: out += routed slots; aux loss tail ------------------
__global__ void k_final(float* __restrict__ out, int n4, int T, int out_size) {
    if (blockIdx.x == 0 && threadIdx.x == 0) {
        float a = 0.f;
        for (int e = 0; e < NE; e++) { float m = g_psum[e] / (float)T; a += m * m; }
        a *= (float)NE;
        for (size_t i = (size_t)T * HD; i < (size_t)out_size; i++) out[i] = a;
    }
    const float4* r = (const float4*)g_routed;
    float4* o4 = (float4*)out;
    int i = blockIdx.x * blockDim.x + threadIdx.x;
    int stride = gridDim.x * blockDim.x;
    for (; i < n4; i += stride) {
        float4 a = o4[i], b = r[i], c = r[i + n4];
        a.x += b.x + c.x;
        a.y += b.y + c.y;
        a.z += b.z + c.z;
        a.w += b.w + c.w;
        o4[i] = a;
    }
}

// ---------------- launch -----------------------------------------------------
extern "C" void kernel_launch(void* const* d_in, const int* in_sizes, int n_in,
                              void* d_out, int out_size) {
    const float* x   = (const float*)d_in[0];
    const float* Wr  = (const float*)d_in[1];
    const float* Wg  = (const float*)d_in[2];
    const float* Wu  = (const float*)d_in[3];
    const float* Wd  = (const float*)d_in[4];
    const float* Wsg = (const float*)d_in[5];
    const float* Wsu = (const float*)d_in[6];
    const float* Wsd = (const float*)d_in[7];
    float* out = (float*)d_out;
    const int T = in_sizes[0] / HD;   // 8192

    __half* xh;
    cudaGetSymbolAddress((void**)&xh, g_xh);

    cudaFuncSetAttribute(k_gu_all, cudaFuncAttributeMaxDynamicSharedMemorySize, SMEM_GU);
    cudaFuncSetAttribute(k_dn_all, cudaFuncAttributeMaxDynamicSharedMemorySize, SMEM_DN);

    // 0: x -> fp16 (+ zero routing counters)
    k_split_x<<<2048, 256>>>(x, T * HD / 4);
    // 1: streaming weight convert f32 -> fp16
    k_wconv<<<dim3(512, 1, 6), 256>>>(Wsg, Wsu, Wsd, Wg, Wu, Wd);
    // 2: router
    k_router<<<T / 8, 256>>>(x, Wr, T);
    // 3: merged gate+up (+swiglu), single-fp16 A, trans-B
    k_gu_all<<<dim3(DS / BN, T / BM, NE + 1), 512, SMEM_GU>>>(xh, T);
    // 4: merged down, single-fp16 A, trans-B
    k_dn_all<<<dim3(HD / BN, T / BM, NE + 1), 512, SMEM_DN>>>(out, T);
    // 5: combine + aux loss
    k_final<<<2048, 256>>>(out, (T * HD) / 4, T, out_size);
}

// round 13
// speedup vs baseline: 6.0262x; 1.0255x over previous
#include <cuda_runtime.h>
#include <cuda_fp16.h>
#include <math.h>
#include <stdint.h>

#define NE   8
#define HD   1024
#define DD   512
#define DS   1024
#define TMAX 8192

#define BM 128
#define BN 128
#define BK 32
#define SA 40                    // A: 16-bit elems per row (32 + 8 pad)
#define SB 136                   // B: 16-bit elems per row (128 + 8 pad)
#define TILE_A (128 * SA * 2)    // 10240 B
#define TILE_BB (32 * SB * 2)    // 8704 B
#define STG_GU (TILE_A + 2 * TILE_BB)   // A, Bg, Bu = 27648
#define STG_DN (TILE_A + TILE_BB)       // A, B = 18944
#define SMEM_GU (4 * STG_GU)     // 110592
#define SMEM_DN (4 * STG_DN)     // 75776

// ---------------- scratch (static device globals; no allocations) ------------
__device__ __align__(16) __half g_xh[(size_t)TMAX * HD];
__device__ __align__(16) __half g_bufH[(size_t)NE * TMAX * DD];   // routed gu out
__device__ __align__(16) __half g_buf2H[(size_t)TMAX * DS];       // shared gu out
__device__ __align__(16) __half g_routed[(size_t)2 * TMAX * HD];  // fp16 slots
// fp16 weights in NATURAL [K][N] layout
__device__ __align__(16) __half g_Wsg16[(size_t)HD * DS];
__device__ __align__(16) __half g_Wsu16[(size_t)HD * DS];
__device__ __align__(16) __half g_Wsd16[(size_t)DS * HD];
__device__ __align__(16) __half g_Wg16[(size_t)NE * HD * DD];
__device__ __align__(16) __half g_Wu16[(size_t)NE * HD * DD];
__device__ __align__(16) __half g_Wd16[(size_t)NE * DD * HD];
__device__ int   g_cnt[NE];
__device__ int   g_tok[NE * TMAX];
__device__ int   g_slot[NE * TMAX];
__device__ float g_wt[NE * TMAX];
__device__ float g_psum[NE];

// ---------------- asm helpers ------------------------------------------------
__device__ __forceinline__ uint32_t smem_u32(const void* p) {
    uint32_t a;
    asm("{ .reg .u64 t; cvta.to.shared.u64 t, %1; cvt.u32.u64 %0, t; }" : "=r"(a) : "l"(p));
    return a;
}
#define CP16(dst, src) \
    asm volatile("cp.async.cg.shared.global [%0], [%1], 16;" :: "r"(dst), "l"(src) : "memory")
#define CPCOMMIT() asm volatile("cp.async.commit_group;" ::: "memory")
#define CPWAIT2()  asm volatile("cp.async.wait_group 2;" ::: "memory")

__device__ __forceinline__ void ldsm4(uint32_t* r, uint32_t addr) {
    asm volatile("ldmatrix.sync.aligned.m8n8.x4.shared.b16 {%0,%1,%2,%3}, [%4];"
        : "=r"(r[0]), "=r"(r[1]), "=r"(r[2]), "=r"(r[3]) : "r"(addr));
}
__device__ __forceinline__ void ldsm4t(uint32_t* r, uint32_t addr) {
    asm volatile("ldmatrix.sync.aligned.m8n8.x4.trans.shared.b16 {%0,%1,%2,%3}, [%4];"
        : "=r"(r[0]), "=r"(r[1]), "=r"(r[2]), "=r"(r[3]) : "r"(addr));
}
__device__ __forceinline__ void mma_f16(float* c, const uint32_t* a, const uint32_t* b) {
    asm volatile(
        "mma.sync.aligned.m16n8k16.row.col.f32.f16.f16.f32 "
        "{%0,%1,%2,%3}, {%4,%5,%6,%7}, {%8,%9}, {%0,%1,%2,%3};\n"
        : "+f"(c[0]), "+f"(c[1]), "+f"(c[2]), "+f"(c[3])
        : "r"(a[0]), "r"(a[1]), "r"(a[2]), "r"(a[3]), "r"(b[0]), "r"(b[1]));
}

// ---- fused prep: z=0 split x -> fp16 (+zero counters); z=1..6 weight conv ---
__global__ void k_prep(const float* __restrict__ x, int xn4,
                       const float* __restrict__ Wsg, const float* __restrict__ Wsu,
                       const float* __restrict__ Wsd, const float* __restrict__ Wg,
                       const float* __restrict__ Wu,  const float* __restrict__ Wd) {
    const int z = blockIdx.z;
    const float* in; __half* o; size_t n4;
    if (z == 0) {
        if (blockIdx.x == 0 && threadIdx.x < NE) {
            g_cnt[threadIdx.x] = 0; g_psum[threadIdx.x] = 0.f;
        }
        in = x; o = g_xh; n4 = (size_t)xn4;
    }
    else if (z == 1) { in = Wsg; o = g_Wsg16; n4 = (size_t)HD * DS / 4; }
    else if (z == 2) { in = Wsu; o = g_Wsu16; n4 = (size_t)HD * DS / 4; }
    else if (z == 3) { in = Wsd; o = g_Wsd16; n4 = (size_t)DS * HD / 4; }
    else if (z == 4) { in = Wg;  o = g_Wg16;  n4 = (size_t)NE * HD * DD / 4; }
    else if (z == 5) { in = Wu;  o = g_Wu16;  n4 = (size_t)NE * HD * DD / 4; }
    else             { in = Wd;  o = g_Wd16;  n4 = (size_t)NE * DD * HD / 4; }
    size_t i = (size_t)blockIdx.x * blockDim.x + threadIdx.x;
    size_t stride = (size_t)gridDim.x * blockDim.x;
    for (; i < n4; i += stride) {
        float4 v = ((const float4*)in)[i];
        __half2 h01 = __floats2half2_rn(v.x, v.y);
        __half2 h23 = __floats2half2_rn(v.z, v.w);
        ((uint2*)o)[i] = make_uint2(*(uint32_t*)&h01, *(uint32_t*)&h23);
    }
}

// ---------------- router ----------------------------------------------------
__global__ void k_router(const float* __restrict__ x, const float* __restrict__ Wr, int T) {
    __shared__ float s_p[NE];
    if (threadIdx.x < NE) s_p[threadIdx.x] = 0.f;
    __syncthreads();
    int warp = blockIdx.x * (blockDim.x >> 5) + (threadIdx.x >> 5);
    int lane = threadIdx.x & 31;
    if (warp < T) {
        int t = warp;
        const float* xr = x + (size_t)t * HD;
        float acc[NE];
        #pragma unroll
        for (int e = 0; e < NE; e++) acc[e] = 0.f;
        for (int i = lane; i < HD; i += 32) {
            float xv = xr[i];
            const float* w = Wr + (size_t)i * NE;
            #pragma unroll
            for (int e = 0; e < NE; e++) acc[e] += xv * w[e];
        }
        #pragma unroll
        for (int e = 0; e < NE; e++) {
            #pragma unroll
            for (int o = 16; o > 0; o >>= 1)
                acc[e] += __shfl_xor_sync(0xffffffffu, acc[e], o);
        }
        if (lane == 0) {
            float mx = acc[0];
            #pragma unroll
            for (int e = 1; e < NE; e++) mx = fmaxf(mx, acc[e]);
            float p[NE]; float s = 0.f;
            #pragma unroll
            for (int e = 0; e < NE; e++) { p[e] = expf(acc[e] - mx); s += p[e]; }
            float inv = 1.f / s;
            #pragma unroll
            for (int e = 0; e < NE; e++) p[e] *= inv;
            int i0 = 0;
            #pragma unroll
            for (int e = 1; e < NE; e++) if (p[e] > p[i0]) i0 = e;
            int i1 = (i0 == 0) ? 1 : 0;
            #pragma unroll
            for (int e = 0; e < NE; e++) if (e != i0 && p[e] > p[i1]) i1 = e;
            float w0 = p[i0], w1 = p[i1];
            float rn = 1.f / (w0 + w1);
            w0 *= rn; w1 *= rn;
            int pos0 = atomicAdd(&g_cnt[i0], 1);
            g_tok[i0 * TMAX + pos0]  = t;
            g_slot[i0 * TMAX + pos0] = t;
            g_wt[i0 * TMAX + pos0]   = w0;
            int pos1 = atomicAdd(&g_cnt[i1], 1);
            g_tok[i1 * TMAX + pos1]  = t;
            g_slot[i1 * TMAX + pos1] = T + t;
            g_wt[i1 * TMAX + pos1]   = w1;
            #pragma unroll
            for (int e = 0; e < NE; e++) atomicAdd(&s_p[e], p[e]);
        }
    }
    __syncthreads();
    if (threadIdx.x < NE) atomicAdd(&g_psum[threadIdx.x], s_p[threadIdx.x]);
}

// ------- merged gate+up GEMM + SwiGLU, single-fp16 A, trans-B, ks skew -------
__global__ __launch_bounds__(512, 1)
void k_gu_all(const __half* __restrict__ A_g, int T)
{
    const int z = blockIdx.z;
    int M, N, e = 0;
    bool gather;
    const __half *Bg, *Bu;
    __half* Ch;
    if (z == 0) {
        gather = false; M = T; N = DS;
        Bg = g_Wsg16; Bu = g_Wsu16;
        Ch = g_buf2H;
    } else {
        gather = true; e = z - 1;
        if (blockIdx.x >= DD / BN) return;
        M = g_cnt[e]; N = DD;
        size_t ws = (size_t)e * HD * DD;
        Bg = g_Wg16 + ws; Bu = g_Wu16 + ws;
        Ch = g_bufH + (size_t)e * TMAX * DD;
    }
    const int row0 = blockIdx.y * BM;
    if (row0 >= M) return;
    const int col0 = blockIdx.x * BN;
    const int K = HD;

    extern __shared__ char dsm[];
    const uint32_t sb = smem_u32(dsm);

    const int tid = threadIdx.x;
    const int wid = tid >> 5, lane = tid & 31;
    const int wm = wid & 3, wn = wid >> 2;
    const int g = lane >> 2, t4 = lane & 3;
    const int kswap = wid & 1;          // phase-skew parity

    size_t aoff; uint32_t adst;
    {
        int r = tid >> 2, c16 = tid & 3;
        adst = r * (SA * 2) + c16 * 16;
        int gr = row0 + r;
        int grc = (gr < M) ? gr : (M - 1);
        if (gather) aoff = (size_t)g_tok[e * TMAX + grc] * K + c16 * 8;
        else        aoff = (size_t)grc * K + c16 * 8;
    }
    size_t boff; uint32_t bdst;
    {
        int br = tid >> 4, bc = tid & 15;
        bdst = br * (SB * 2) + bc * 16;
        boff = (size_t)br * N + col0 + bc * 8;
    }
    const size_t bstep = (size_t)BK * N;

    const int a_r = (lane & 7) + ((lane >> 3) & 1) * 8;
    const int a_c = ((lane >> 4) & 1) * 8;
    const uint32_t la = (uint32_t)(a_r * SA + a_c) * 2;
    const int b_k = (lane & 7) + ((lane >> 3) & 1) * 8;
    const int b_n = ((lane >> 4) & 1) * 8;
    const uint32_t lbT = (uint32_t)(b_k * SB + b_n) * 2;

    float accg[2][4][4], accu[2][4][4];
    #pragma unroll
    for (int mi = 0; mi < 2; mi++)
        #pragma unroll
        for (int ni = 0; ni < 4; ni++)
            #pragma unroll
            for (int q = 0; q < 4; q++) { accg[mi][ni][q] = 0.f; accu[mi][ni][q] = 0.f; }

    const int NC = K / BK;   // 32
    #pragma unroll
    for (int pc = 0; pc < 3; pc++) {
        uint32_t st = sb + pc * STG_GU;
        CP16(st + adst, A_g + aoff + (size_t)pc * BK);
        CP16(st + TILE_A + bdst, Bg + boff + (size_t)pc * bstep);
        CP16(st + TILE_A + TILE_BB + bdst, Bu + boff + (size_t)pc * bstep);
        CPCOMMIT();
    }

    int s_next = 3;
    for (int c = 0; c < NC; c++) {
        CPWAIT2();
        __syncthreads();
        {
            int nc3 = (c + 3 < NC) ? c + 3 : NC - 1;
            uint32_t st = sb + s_next * STG_GU;
            CP16(st + adst, A_g + aoff + (size_t)nc3 * BK);
            CP16(st + TILE_A + bdst, Bg + boff + (size_t)nc3 * bstep);
            CP16(st + TILE_A + TILE_BB + bdst, Bu + boff + (size_t)nc3 * bstep);
            CPCOMMIT();
        }
        s_next = (s_next + 1) & 3;
        const uint32_t st = sb + (c & 3) * STG_GU;
        #pragma unroll
        for (int kss = 0; kss < 2; kss++) {
            const int ks = kswap ? (1 - kss) : kss;   // odd warps reverse order
            uint32_t fA[2][4], fBg[2][4], fBu[2][4];
            #pragma unroll
            for (int mi = 0; mi < 2; mi++) {
                uint32_t ro = (uint32_t)((wm * 32 + mi * 16) * SA * 2) + ks * 32;
                ldsm4(fA[mi], st + ro + la);
            }
            #pragma unroll
            for (int nb = 0; nb < 2; nb++) {
                uint32_t bo = (uint32_t)(ks * 16 * SB * 2) + (uint32_t)((wn * 32 + nb * 16) * 2);
                ldsm4t(fBg[nb], st + TILE_A + bo + lbT);
                ldsm4t(fBu[nb], st + TILE_A + TILE_BB + bo + lbT);
            }
            #pragma unroll
            for (int mi = 0; mi < 2; mi++)
                #pragma unroll
                for (int ni = 0; ni < 4; ni++)
                    mma_f16(accg[mi][ni], fA[mi], &fBg[ni >> 1][(ni & 1) * 2]);
            #pragma unroll
            for (int mi = 0; mi < 2; mi++)
                #pragma unroll
                for (int ni = 0; ni < 4; ni++)
                    mma_f16(accu[mi][ni], fA[mi], &fBu[ni >> 1][(ni & 1) * 2]);
        }
    }

    // epilogue: swiglu (weighted if gather), single-fp16 store
    #pragma unroll
    for (int mi = 0; mi < 2; mi++) {
        int p0 = row0 + wm * 32 + mi * 16 + g;
        #pragma unroll
        for (int half = 0; half < 2; half++) {
            int p = p0 + half * 8;
            if (p >= M) continue;
            float w = gather ? g_wt[e * TMAX + p] : 1.f;
            size_t rowo = (size_t)p * N;
            #pragma unroll
            for (int ni = 0; ni < 4; ni++) {
                int col = col0 + wn * 32 + ni * 8 + 2 * t4;
                float gv0 = accg[mi][ni][half * 2 + 0];
                float gv1 = accg[mi][ni][half * 2 + 1];
                float uv0 = accu[mi][ni][half * 2 + 0];
                float uv1 = accu[mi][ni][half * 2 + 1];
                float v0 = w * (gv0 / (1.f + expf(-gv0))) * uv0;
                float v1 = w * (gv1 / (1.f + expf(-gv1))) * uv1;
                *(__half2*)(Ch + rowo + col) = __floats2half2_rn(v0, v1);
            }
        }
    }
}

// ------- merged down GEMM, single-fp16 A, trans-B, ks skew -------------------
__global__ __launch_bounds__(512, 1)
void k_dn_all(float* __restrict__ out, int T)
{
    const int z = blockIdx.z;
    int M, K, e = 0;
    bool scatter;
    const __half *A_g, *B;
    if (z == 0) {
        scatter = false; M = T; K = DS;
        A_g = g_buf2H;
        B = g_Wsd16;
    } else {
        scatter = true; e = z - 1;
        M = g_cnt[e]; K = DD;
        A_g = g_bufH + (size_t)e * TMAX * DD;
        B = g_Wd16 + (size_t)e * DD * HD;
    }
    const int row0 = blockIdx.y * BM;
    if (row0 >= M) return;
    const int col0 = blockIdx.x * BN;
    const int N = HD;

    extern __shared__ char dsm[];
    const uint32_t sb = smem_u32(dsm);

    const int tid = threadIdx.x;
    const int wid = tid >> 5, lane = tid & 31;
    const int wm = wid & 3, wn = wid >> 2;
    const int g = lane >> 2, t4 = lane & 3;
    const int kswap = wid & 1;

    size_t aoff; uint32_t adst;
    {
        int r = tid >> 2, c16 = tid & 3;
        adst = r * (SA * 2) + c16 * 16;
        int gr = row0 + r;
        int grc = (gr < M) ? gr : (M - 1);
        aoff = (size_t)grc * K + c16 * 8;
    }
    size_t boff; uint32_t bdst;
    {
        int br = tid >> 4, bc = tid & 15;
        bdst = br * (SB * 2) + bc * 16;
        boff = (size_t)br * N + col0 + bc * 8;
    }
    const size_t bstep = (size_t)BK * N;

    const int a_r = (lane & 7) + ((lane >> 3) & 1) * 8;
    const int a_c = ((lane >> 4) & 1) * 8;
    const uint32_t la = (uint32_t)(a_r * SA + a_c) * 2;
    const int b_k = (lane & 7) + ((lane >> 3) & 1) * 8;
    const int b_n = ((lane >> 4) & 1) * 8;
    const uint32_t lbT = (uint32_t)(b_k * SB + b_n) * 2;

    float acc[2][4][4];
    #pragma unroll
    for (int mi = 0; mi < 2; mi++)
        #pragma unroll
        for (int ni = 0; ni < 4; ni++)
            #pragma unroll
            for (int q = 0; q < 4; q++) acc[mi][ni][q] = 0.f;

    const int NC = K / BK;
    #pragma unroll
    for (int pc = 0; pc < 3; pc++) {
        uint32_t st = sb + pc * STG_DN;
        CP16(st + adst, A_g + aoff + (size_t)pc * BK);
        CP16(st + TILE_A + bdst, B + boff + (size_t)pc * bstep);
        CPCOMMIT();
    }

    int s_next = 3;
    for (int c = 0; c < NC; c++) {
        CPWAIT2();
        __syncthreads();
        {
            int nc3 = (c + 3 < NC) ? c + 3 : NC - 1;
            uint32_t st = sb + s_next * STG_DN;
            CP16(st + adst, A_g + aoff + (size_t)nc3 * BK);
            CP16(st + TILE_A + bdst, B + boff + (size_t)nc3 * bstep);
            CPCOMMIT();
        }
        s_next = (s_next + 1) & 3;
        const uint32_t st = sb + (c & 3) * STG_DN;
        #pragma unroll
        for (int kss = 0; kss < 2; kss++) {
            const int ks = kswap ? (1 - kss) : kss;
            uint32_t fA[2][4], fB[2][4];
            #pragma unroll
            for (int mi = 0; mi < 2; mi++) {
                uint32_t ro = (uint32_t)((wm * 32 + mi * 16) * SA * 2) + ks * 32;
                ldsm4(fA[mi], st + ro + la);
            }
            #pragma unroll
            for (int nb = 0; nb < 2; nb++) {
                uint32_t bo = (uint32_t)(ks * 16 * SB * 2) + (uint32_t)((wn * 32 + nb * 16) * 2);
                ldsm4t(fB[nb], st + TILE_A + bo + lbT);
            }
            #pragma unroll
            for (int mi = 0; mi < 2; mi++)
                #pragma unroll
                for (int ni = 0; ni < 4; ni++)
                    mma_f16(acc[mi][ni], fA[mi], &fB[ni >> 1][(ni & 1) * 2]);
        }
    }

    #pragma unroll
    for (int mi = 0; mi < 2; mi++) {
        int p0 = row0 + wm * 32 + mi * 16 + g;
        int p1 = p0 + 8;
        if (scatter) {
            __half* c0 = (p0 < M) ? g_routed + (size_t)g_slot[e * TMAX + p0] * HD : nullptr;
            __half* c1 = (p1 < M) ? g_routed + (size_t)g_slot[e * TMAX + p1] * HD : nullptr;
            #pragma unroll
            for (int ni = 0; ni < 4; ni++) {
                int col = col0 + wn * 32 + ni * 8 + 2 * t4;
                if (c0) *(__half2*)(c0 + col) = __floats2half2_rn(acc[mi][ni][0], acc[mi][ni][1]);
                if (c1) *(__half2*)(c1 + col) = __floats2half2_rn(acc[mi][ni][2], acc[mi][ni][3]);
            }
        } else {
            float* c0 = out + (size_t)p0 * HD;
            float* c1 = out + (size_t)p1 * HD;
            #pragma unroll
            for (int ni = 0; ni < 4; ni++) {
                int col = col0 + wn * 32 + ni * 8 + 2 * t4;
                *(float2*)(c0 + col) = make_float2(acc[mi][ni][0], acc[mi][ni][1]);
                *(float2*)(c1 + col) = make_float2(acc[mi][ni][2], acc[mi][ni][3]);
            }
        }
    }
}

// ---------------- final: out += routed slots (fp16); aux loss tail -----------
__global__ void k_final(float* __restrict__ out, int n4, int T, int out_size) {
    if (blockIdx.x == 0 && threadIdx.x == 0) {
        float a = 0.f;
        for (int e = 0; e < NE; e++) { float m = g_psum[e] / (float)T; a += m * m; }
        a *= (float)NE;
        for (size_t i = (size_t)T * HD; i < (size_t)out_size; i++) out[i] = a;
    }
    const uint2* r = (const uint2*)g_routed;   // 4 halves per uint2
    float4* o4 = (float4*)out;
    int i = blockIdx.x * blockDim.x + threadIdx.x;
    int stride = gridDim.x * blockDim.x;
    for (; i < n4; i += stride) {
        float4 a = o4[i];
        uint2 b2 = r[i], c2 = r[i + n4];
        __half2 b01 = *(__half2*)&b2.x, b23 = *(__half2*)&b2.y;
        __half2 c01 = *(__half2*)&c2.x, c23 = *(__half2*)&c2.y;
        float2 fb01 = __half22float2(b01), fb23 = __half22float2(b23);
        float2 fc01 = __half22float2(c01), fc23 = __half22float2(c23);
        a.x += fb01.x + fc01.x;
        a.y += fb01.y + fc01.y;
        a.z += fb23.x + fc23.x;
        a.w += fb23.y + fc23.y;
        o4[i] = a;
    }
}

// ---------------- launch -----------------------------------------------------
extern "C" void kernel_launch(void* const* d_in, const int* in_sizes, int n_in,
                              void* d_out, int out_size) {
    const float* x   = (const float*)d_in[0];
    const float* Wr  = (const float*)d_in[1];
    const float* Wg  = (const float*)d_in[2];
    const float* Wu  = (const float*)d_in[3];
    const float* Wd  = (const float*)d_in[4];
    const float* Wsg = (const float*)d_in[5];
    const float* Wsu = (const float*)d_in[6];
    const float* Wsd = (const float*)d_in[7];
    float* out = (float*)d_out;
    const int T = in_sizes[0] / HD;   // 8192

    __half* xh;
    cudaGetSymbolAddress((void**)&xh, g_xh);

    cudaFuncSetAttribute(k_gu_all, cudaFuncAttributeMaxDynamicSharedMemorySize, SMEM_GU);
    cudaFuncSetAttribute(k_dn_all, cudaFuncAttributeMaxDynamicSharedMemorySize, SMEM_DN);

    // 0: fused prep — x->fp16 (+zero counters) and all weight converts
    k_prep<<<dim3(512, 1, 7), 256>>>(x, T * HD / 4, Wsg, Wsu, Wsd, Wg, Wu, Wd);
    // 1: router
    k_router<<<T / 8, 256>>>(x, Wr, T);
    // 2: merged gate+up (+swiglu)
    k_gu_all<<<dim3(DS / BN, T / BM, NE + 1), 512, SMEM_GU>>>(xh, T);
    // 3: merged down
    k_dn_all<<<dim3(HD / BN, T / BM, NE + 1), 512, SMEM_DN>>>(out, T);
    // 4: combine + aux loss
    k_final<<<2048, 256>>>(out, (T * HD) / 4, T, out_size);
}